// round 2
// baseline (speedup 1.0000x reference)
#include <cuda_runtime.h>
#include <math.h>

#define NB 512
#define NS 65536
#define DD 256
#define SPLITS 64
#define KCH (NS / SPLITS)   // 1024

// ---------------- scratch (device globals; no allocations allowed) ----------
__device__ float g_sim[(size_t)NB * NS];          // 128 MB
__device__ float g_ww [(size_t)NB * NS];          // 128 MB (unnormalized write softmax)
__device__ float g_qn [NB * DD];
__device__ float g_minv[NS];
__device__ float g_rowmax[NB];
__device__ float g_rowZ[NB];
__device__ int   g_argmax[NB];
__device__ float g_S1[NB];
__device__ float g_M1[NB];
__device__ float g_wZinv[NB];
__device__ float g_erase[NS];
__device__ float g_partial[(size_t)SPLITS * NB * DD];  // 32 MB

// ---------------- norms: memory row inv-norms + normalized query ------------
__global__ void k_norms(const float* __restrict__ mem, const float* __restrict__ q) {
    int lane = threadIdx.x;
    int row  = blockIdx.x * 8 + threadIdx.y;
    if (row < NS) {
        const float4* p = reinterpret_cast<const float4*>(mem + (size_t)row * DD);
        float4 v0 = p[lane];
        float4 v1 = p[lane + 32];
        float s = v0.x*v0.x + v0.y*v0.y + v0.z*v0.z + v0.w*v0.w
                + v1.x*v1.x + v1.y*v1.y + v1.z*v1.z + v1.w*v1.w;
        #pragma unroll
        for (int o = 16; o; o >>= 1) s += __shfl_xor_sync(0xffffffffu, s, o);
        if (lane == 0) g_minv[row] = 1.0f / fmaxf(sqrtf(s), 1e-12f);
    } else {
        int qr = row - NS;
        if (qr < NB) {
            const float4* p = reinterpret_cast<const float4*>(q + (size_t)qr * DD);
            float4 v0 = p[lane];
            float4 v1 = p[lane + 32];
            float s = v0.x*v0.x + v0.y*v0.y + v0.z*v0.z + v0.w*v0.w
                    + v1.x*v1.x + v1.y*v1.y + v1.z*v1.z + v1.w*v1.w;
            #pragma unroll
            for (int o = 16; o; o >>= 1) s += __shfl_xor_sync(0xffffffffu, s, o);
            float inv = 1.0f / fmaxf(sqrtf(s), 1e-12f);
            v0.x *= inv; v0.y *= inv; v0.z *= inv; v0.w *= inv;
            v1.x *= inv; v1.y *= inv; v1.z *= inv; v1.w *= inv;
            float4* o4 = reinterpret_cast<float4*>(g_qn + (size_t)qr * DD);
            o4[lane] = v0; o4[lane + 32] = v1;
        }
    }
}

// ---------------- sim GEMM: g_sim[b][n] = (qn[b] . mem[n]) * minv[n] --------
// M=512(b) N=65536(n) K=256.  128x128x16 tile, 8x8 microtile, 256 threads.
__global__ void __launch_bounds__(256) k_sim(const float* __restrict__ mem) {
    __shared__ float As[16][128];   // [k][b]
    __shared__ float Bs[16][128];   // [k][n]
    int bn = blockIdx.x * 128;
    int bm = blockIdx.y * 128;
    int tid = threadIdx.x;
    int tx = tid & 15, ty = tid >> 4;
    float acc[8][8];
    #pragma unroll
    for (int i = 0; i < 8; i++)
        #pragma unroll
        for (int j = 0; j < 8; j++) acc[i][j] = 0.f;

    for (int k0 = 0; k0 < DD; k0 += 16) {
        #pragma unroll
        for (int l = 0; l < 2; l++) {
            int v = tid + l * 256;
            int m  = v >> 2;
            int kq = (v & 3) << 2;
            float4 a = *reinterpret_cast<const float4*>(g_qn + (size_t)(bm + m) * DD + k0 + kq);
            As[kq+0][m] = a.x; As[kq+1][m] = a.y; As[kq+2][m] = a.z; As[kq+3][m] = a.w;
            float4 b = *reinterpret_cast<const float4*>(mem + (size_t)(bn + m) * DD + k0 + kq);
            Bs[kq+0][m] = b.x; Bs[kq+1][m] = b.y; Bs[kq+2][m] = b.z; Bs[kq+3][m] = b.w;
        }
        __syncthreads();
        #pragma unroll
        for (int kk = 0; kk < 16; kk++) {
            float a[8], b[8];
            *(float4*)(a)   = *(const float4*)&As[kk][ty*4];
            *(float4*)(a+4) = *(const float4*)&As[kk][64 + ty*4];
            *(float4*)(b)   = *(const float4*)&Bs[kk][tx*4];
            *(float4*)(b+4) = *(const float4*)&Bs[kk][64 + tx*4];
            #pragma unroll
            for (int i = 0; i < 8; i++)
                #pragma unroll
                for (int j = 0; j < 8; j++) acc[i][j] += a[i]*b[j];
        }
        __syncthreads();
    }
    float mv[8];
    *(float4*)(mv)   = *reinterpret_cast<const float4*>(g_minv + bn + tx*4);
    *(float4*)(mv+4) = *reinterpret_cast<const float4*>(g_minv + bn + 64 + tx*4);
    #pragma unroll
    for (int i = 0; i < 8; i++) {
        int r = bm + ((i < 4) ? (ty*4 + i) : (64 + ty*4 + (i-4)));
        float* dst = g_sim + (size_t)r * NS + bn;
        float4 o0 = make_float4(acc[i][0]*mv[0], acc[i][1]*mv[1], acc[i][2]*mv[2], acc[i][3]*mv[3]);
        float4 o1 = make_float4(acc[i][4]*mv[4], acc[i][5]*mv[5], acc[i][6]*mv[6], acc[i][7]*mv[7]);
        *reinterpret_cast<float4*>(dst + tx*4)      = o0;
        *reinterpret_cast<float4*>(dst + 64 + tx*4) = o1;
    }
}

// ---------------- content softmax stats + argmax per batch row --------------
__global__ void __launch_bounds__(256) k_cstats() {
    int b = blockIdx.x, t = threadIdx.x;
    const float4* r4 = reinterpret_cast<const float4*>(g_sim + (size_t)b * NS);
    float m = -1e30f; int am = 0;
    for (int i = t; i < NS/4; i += 256) {
        float4 v = r4[i];
        int base = i * 4;
        if (v.x > m) { m = v.x; am = base; }
        if (v.y > m) { m = v.y; am = base+1; }
        if (v.z > m) { m = v.z; am = base+2; }
        if (v.w > m) { m = v.w; am = base+3; }
    }
    __shared__ float sm[256]; __shared__ int sa[256];
    sm[t] = m; sa[t] = am; __syncthreads();
    for (int o = 128; o; o >>= 1) {
        if (t < o) {
            if (sm[t+o] > sm[t] || (sm[t+o] == sm[t] && sa[t+o] < sa[t])) {
                sm[t] = sm[t+o]; sa[t] = sa[t+o];
            }
        }
        __syncthreads();
    }
    m = sm[0];
    float s = 0.f;
    for (int i = t; i < NS/4; i += 256) {
        float4 v = r4[i];
        s += expf(v.x - m) + expf(v.y - m) + expf(v.z - m) + expf(v.w - m);
    }
    __shared__ float ss[256];
    ss[t] = s; __syncthreads();
    for (int o = 128; o; o >>= 1) { if (t < o) ss[t] += ss[t+o]; __syncthreads(); }
    if (t == 0) { g_rowmax[b] = m; g_rowZ[b] = ss[0]; g_argmax[b] = sa[0]; }
}

// ---------------- write-weight stats: S1 = sum sharp, M1 = max sharp --------
__global__ void __launch_bounds__(256) k_wstats(const float* __restrict__ prev,
                                                const float* __restrict__ sw) {
    int b = blockIdx.x, t = threadIdx.x;
    const float* row = prev + (size_t)b * NS;
    float w0 = sw[0], w1 = sw[1], w2 = sw[2];
    float sum = 0.f, mx = 0.f;
    for (int i = t; i < NS; i += 256) {
        float l = (i > 0)      ? row[i-1] : 0.f;
        float c = row[i];
        float r = (i < NS-1)   ? row[i+1] : 0.f;
        float sh = l*w0 + c*w1 + r*w2;
        float sp = sh * sqrtf(sh);
        sum += sp; mx = fmaxf(mx, sp);
    }
    __shared__ float ssum[256]; __shared__ float smax[256];
    ssum[t] = sum; smax[t] = mx; __syncthreads();
    for (int o = 128; o; o >>= 1) {
        if (t < o) { ssum[t] += ssum[t+o]; smax[t] = fmaxf(smax[t], smax[t+o]); }
        __syncthreads();
    }
    if (t == 0) { g_S1[b] = ssum[0]; g_M1[b] = smax[0]; }
}

// ---------------- write-weight exp + partition Z ----------------------------
__global__ void __launch_bounds__(256) k_wexp(const float* __restrict__ prev,
                                              const float* __restrict__ sw) {
    int b = blockIdx.x, t = threadIdx.x;
    const float* row = prev + (size_t)b * NS;
    float* wr = g_ww + (size_t)b * NS;
    float w0 = sw[0], w1 = sw[1], w2 = sw[2];
    float sinv = 1.0f / (g_S1[b] + 1e-8f);
    float m = g_M1[b] * sinv;
    float z = 0.f;
    for (int i = t; i < NS; i += 256) {
        float l = (i > 0)    ? row[i-1] : 0.f;
        float c = row[i];
        float r = (i < NS-1) ? row[i+1] : 0.f;
        float sh = l*w0 + c*w1 + r*w2;
        float sp = sh * sqrtf(sh);
        float e = expf(sp * sinv - m);
        wr[i] = e;
        z += e;
    }
    __shared__ float ss[256];
    ss[t] = z; __syncthreads();
    for (int o = 128; o; o >>= 1) { if (t < o) ss[t] += ss[t+o]; __syncthreads(); }
    if (t == 0) g_wZinv[b] = 1.0f / ss[0];
}

// ---------------- erase factor: prod over batch ------------------------------
__global__ void __launch_bounds__(256) k_erase() {
    __shared__ float zin[NB];
    int t = threadIdx.x;
    for (int i = t; i < NB; i += 256) zin[i] = g_wZinv[i];
    __syncthreads();
    int n = blockIdx.x * 256 + t;
    float p = 1.f;
    #pragma unroll 8
    for (int b = 0; b < NB; b++) {
        p *= (1.0f - 0.5f * g_ww[(size_t)b * NS + n] * zin[b]);
    }
    g_erase[n] = p;
}

// ---------------- read_topk: one-hot gather of argmax row --------------------
__global__ void k_topk(const float* __restrict__ mem, float* __restrict__ out2) {
    int b = blockIdx.x;
    int t = threadIdx.x;
    out2[(size_t)b * DD + t] = mem[(size_t)g_argmax[b] * DD + t];
}

// ---------------- content GEMM (split-K): partial = exp(sim-max) @ memory ----
__global__ void __launch_bounds__(256) k_content(const float* __restrict__ mem) {
    __shared__ float As[16][128];   // [k][b]  = exp(sim - rowmax)
    __shared__ float Bs[16][128];   // [k][d]
    __shared__ float rmax[128];
    int bd = blockIdx.x * 128;
    int bm = blockIdx.y * 128;
    int z  = blockIdx.z;
    int tid = threadIdx.x, tx = tid & 15, ty = tid >> 4;
    if (tid < 128) rmax[tid] = g_rowmax[bm + tid];
    __syncthreads();
    float acc[8][8];
    #pragma unroll
    for (int i = 0; i < 8; i++)
        #pragma unroll
        for (int j = 0; j < 8; j++) acc[i][j] = 0.f;

    int kbase = z * KCH;
    for (int k0 = kbase; k0 < kbase + KCH; k0 += 16) {
        #pragma unroll
        for (int l = 0; l < 2; l++) {
            int v = tid + l * 256;
            int m  = v >> 2;
            int kq = (v & 3) << 2;
            float4 a = *reinterpret_cast<const float4*>(g_sim + (size_t)(bm + m) * NS + k0 + kq);
            float rm = rmax[m];
            As[kq+0][m] = expf(a.x - rm);
            As[kq+1][m] = expf(a.y - rm);
            As[kq+2][m] = expf(a.z - rm);
            As[kq+3][m] = expf(a.w - rm);
            int kr = v >> 5;
            int dc = (v & 31) << 2;
            *(float4*)&Bs[kr][dc] =
                *reinterpret_cast<const float4*>(mem + (size_t)(k0 + kr) * DD + bd + dc);
        }
        __syncthreads();
        #pragma unroll
        for (int kk = 0; kk < 16; kk++) {
            float a[8], b[8];
            *(float4*)(a)   = *(const float4*)&As[kk][ty*4];
            *(float4*)(a+4) = *(const float4*)&As[kk][64 + ty*4];
            *(float4*)(b)   = *(const float4*)&Bs[kk][tx*4];
            *(float4*)(b+4) = *(const float4*)&Bs[kk][64 + tx*4];
            #pragma unroll
            for (int i = 0; i < 8; i++)
                #pragma unroll
                for (int j = 0; j < 8; j++) acc[i][j] += a[i]*b[j];
        }
        __syncthreads();
    }
    #pragma unroll
    for (int i = 0; i < 8; i++) {
        int r = bm + ((i < 4) ? (ty*4 + i) : (64 + ty*4 + (i-4)));
        float* dst = g_partial + ((size_t)z * NB + r) * DD + bd;
        *(float4*)(dst + tx*4)      = make_float4(acc[i][0], acc[i][1], acc[i][2], acc[i][3]);
        *(float4*)(dst + 64 + tx*4) = make_float4(acc[i][4], acc[i][5], acc[i][6], acc[i][7]);
    }
}

// ---------------- reduce split-K partials, divide by Z -----------------------
__global__ void __launch_bounds__(256) k_reduce(float* __restrict__ out1) {
    int idx = blockIdx.x * 256 + threadIdx.x;   // [0, 131072)
    int b = idx >> 8;
    float s = 0.f;
    #pragma unroll 8
    for (int z = 0; z < SPLITS; z++) s += g_partial[(size_t)z * NB * DD + idx];
    out1[idx] = s / g_rowZ[b];
}

// ---------------- new_mem GEMM: out = mem*erase + w_write^T @ value ----------
__global__ void __launch_bounds__(256) k_newmem(const float* __restrict__ mem,
                                                const float* __restrict__ value,
                                                float* __restrict__ out3) {
    __shared__ float As[16][128];   // [k=b][n]  = w_write
    __shared__ float Bs[16][128];   // [k=b][d]  = value
    int bd = blockIdx.x * 128;
    int bn = blockIdx.y * 128;
    int tid = threadIdx.x, tx = tid & 15, ty = tid >> 4;
    float acc[8][8];
    #pragma unroll
    for (int i = 0; i < 8; i++)
        #pragma unroll
        for (int j = 0; j < 8; j++) acc[i][j] = 0.f;

    for (int k0 = 0; k0 < NB; k0 += 16) {
        #pragma unroll
        for (int l = 0; l < 2; l++) {
            int v = tid + l * 256;
            int kr = v >> 5;
            int c4 = (v & 31) << 2;
            float zi = g_wZinv[k0 + kr];
            float4 a = *reinterpret_cast<const float4*>(g_ww + (size_t)(k0 + kr) * NS + bn + c4);
            a.x *= zi; a.y *= zi; a.z *= zi; a.w *= zi;
            *(float4*)&As[kr][c4] = a;
            *(float4*)&Bs[kr][c4] =
                *reinterpret_cast<const float4*>(value + (size_t)(k0 + kr) * DD + bd + c4);
        }
        __syncthreads();
        #pragma unroll
        for (int kk = 0; kk < 16; kk++) {
            float a[8], b[8];
            *(float4*)(a)   = *(const float4*)&As[kk][ty*4];
            *(float4*)(a+4) = *(const float4*)&As[kk][64 + ty*4];
            *(float4*)(b)   = *(const float4*)&Bs[kk][tx*4];
            *(float4*)(b+4) = *(const float4*)&Bs[kk][64 + tx*4];
            #pragma unroll
            for (int i = 0; i < 8; i++)
                #pragma unroll
                for (int j = 0; j < 8; j++) acc[i][j] += a[i]*b[j];
        }
        __syncthreads();
    }
    #pragma unroll
    for (int i = 0; i < 8; i++) {
        int n = bn + ((i < 4) ? (ty*4 + i) : (64 + ty*4 + (i-4)));
        float er = g_erase[n];
        const float* mrow = mem + (size_t)n * DD + bd;
        float* dst = out3 + (size_t)n * DD + bd;
        float4 m0 = *reinterpret_cast<const float4*>(mrow + tx*4);
        float4 m1 = *reinterpret_cast<const float4*>(mrow + 64 + tx*4);
        float4 o0 = make_float4(m0.x*er + acc[i][0], m0.y*er + acc[i][1],
                                m0.z*er + acc[i][2], m0.w*er + acc[i][3]);
        float4 o1 = make_float4(m1.x*er + acc[i][4], m1.y*er + acc[i][5],
                                m1.z*er + acc[i][6], m1.w*er + acc[i][7]);
        *reinterpret_cast<float4*>(dst + tx*4)      = o0;
        *reinterpret_cast<float4*>(dst + 64 + tx*4) = o1;
    }
}

// ---------------- launch ----------------------------------------------------
extern "C" void kernel_launch(void* const* d_in, const int* in_sizes, int n_in,
                              void* d_out, int out_size) {
    const float* memory  = (const float*)d_in[0];
    const float* query   = (const float*)d_in[1];
    const float* value   = (const float*)d_in[2];
    const float* prev    = (const float*)d_in[3];
    const float* shiftw  = (const float*)d_in[4];
    // d_in[5] = k (unused: top-k softmax is provably one-hot at argmax(sim))

    float* out  = (float*)d_out;
    float* out1 = out;                     // read_content [512,256]
    float* out2 = out + NB * DD;           // read_topk    [512,256]
    float* out3 = out + 2 * NB * DD;       // new_mem      [65536,256]

    k_norms  <<<(NS + NB) / 8, dim3(32, 8)>>>(memory, query);
    k_sim    <<<dim3(NS / 128, NB / 128), 256>>>(memory);
    k_cstats <<<NB, 256>>>();
    k_wstats <<<NB, 256>>>(prev, shiftw);
    k_wexp   <<<NB, 256>>>(prev, shiftw);
    k_erase  <<<NS / 256, 256>>>();
    k_topk   <<<NB, 256>>>(memory, out2);
    k_content<<<dim3(DD / 128, NB / 128, SPLITS), 256>>>(memory);
    k_reduce <<<(NB * DD) / 256, 256>>>(out1);
    k_newmem <<<dim3(DD / 128, NS / 128), 256>>>(memory, value, out3);
}

// round 3
// speedup vs baseline: 1.1263x; 1.1263x over previous
#include <cuda_runtime.h>
#include <math.h>

#define NB 512
#define NS 65536
#define DD 256
#define SPLITS 64
#define KCH (NS / SPLITS)   // 1024
#define NBLK (NS / 128)     // 512 n-blocks in k_sim

// ---------------- scratch (device globals; no allocations allowed) ----------
__device__ float g_sim[(size_t)NB * NS];          // 128 MB : E = exp(sim)
__device__ float g_ww [(size_t)NB * NS];          // 128 MB : unnormalized write softmax
__device__ float g_qn [NB * DD];
__device__ float g_minv[NS];
__device__ float g_pmax[(size_t)NB * NBLK];       // per-block partial max (pre-exp sim)
__device__ int   g_parg[(size_t)NB * NBLK];       // per-block partial argmax
__device__ float g_psum[(size_t)NB * NBLK];       // per-block partial sum of exp
__device__ int   g_argmax[NB];
__device__ float g_cZinv[NB];
__device__ float g_wZinv[NB];
__device__ float g_partial[(size_t)SPLITS * NB * DD];  // 32 MB

// ---------------- norms: memory row inv-norms + normalized query ------------
__global__ void k_norms(const float* __restrict__ mem, const float* __restrict__ q) {
    int lane = threadIdx.x;
    int row  = blockIdx.x * 8 + threadIdx.y;
    if (row < NS) {
        const float4* p = reinterpret_cast<const float4*>(mem + (size_t)row * DD);
        float4 v0 = p[lane];
        float4 v1 = p[lane + 32];
        float s = v0.x*v0.x + v0.y*v0.y + v0.z*v0.z + v0.w*v0.w
                + v1.x*v1.x + v1.y*v1.y + v1.z*v1.z + v1.w*v1.w;
        #pragma unroll
        for (int o = 16; o; o >>= 1) s += __shfl_xor_sync(0xffffffffu, s, o);
        if (lane == 0) g_minv[row] = 1.0f / fmaxf(sqrtf(s), 1e-12f);
    } else {
        int qr = row - NS;
        if (qr < NB) {
            const float4* p = reinterpret_cast<const float4*>(q + (size_t)qr * DD);
            float4 v0 = p[lane];
            float4 v1 = p[lane + 32];
            float s = v0.x*v0.x + v0.y*v0.y + v0.z*v0.z + v0.w*v0.w
                    + v1.x*v1.x + v1.y*v1.y + v1.z*v1.z + v1.w*v1.w;
            #pragma unroll
            for (int o = 16; o; o >>= 1) s += __shfl_xor_sync(0xffffffffu, s, o);
            float inv = 1.0f / fmaxf(sqrtf(s), 1e-12f);
            v0.x *= inv; v0.y *= inv; v0.z *= inv; v0.w *= inv;
            v1.x *= inv; v1.y *= inv; v1.z *= inv; v1.w *= inv;
            float4* o4 = reinterpret_cast<float4*>(g_qn + (size_t)qr * DD);
            o4[lane] = v0; o4[lane + 32] = v1;
        }
    }
}

// ---------------- sim GEMM + exp + per-block softmax partials ----------------
// g_sim[b][n] = exp((qn[b].mem[n]) * minv[n]); partial max/argmax/sum per block.
__global__ void __launch_bounds__(256) k_sim(const float* __restrict__ mem) {
    __shared__ float As[16][132];   // [k][b]
    __shared__ float Bs[16][132];   // [k][n]
    int bn = blockIdx.x * 128;
    int bm = blockIdx.y * 128;
    int bnblk = blockIdx.x;
    int tid = threadIdx.x;
    int tx = tid & 15, ty = tid >> 4;
    float acc[8][8];
    #pragma unroll
    for (int i = 0; i < 8; i++)
        #pragma unroll
        for (int j = 0; j < 8; j++) acc[i][j] = 0.f;

    for (int k0 = 0; k0 < DD; k0 += 16) {
        #pragma unroll
        for (int l = 0; l < 2; l++) {
            int v = tid + l * 256;
            int m  = v >> 2;
            int kq = (v & 3) << 2;
            float4 a = *reinterpret_cast<const float4*>(g_qn + (size_t)(bm + m) * DD + k0 + kq);
            As[kq+0][m] = a.x; As[kq+1][m] = a.y; As[kq+2][m] = a.z; As[kq+3][m] = a.w;
            float4 b = *reinterpret_cast<const float4*>(mem + (size_t)(bn + m) * DD + k0 + kq);
            Bs[kq+0][m] = b.x; Bs[kq+1][m] = b.y; Bs[kq+2][m] = b.z; Bs[kq+3][m] = b.w;
        }
        __syncthreads();
        #pragma unroll
        for (int kk = 0; kk < 16; kk++) {
            float a[8], b[8];
            *(float4*)(a)   = *(const float4*)&As[kk][ty*4];
            *(float4*)(a+4) = *(const float4*)&As[kk][64 + ty*4];
            *(float4*)(b)   = *(const float4*)&Bs[kk][tx*4];
            *(float4*)(b+4) = *(const float4*)&Bs[kk][64 + tx*4];
            #pragma unroll
            for (int i = 0; i < 8; i++)
                #pragma unroll
                for (int j = 0; j < 8; j++) acc[i][j] += a[i]*b[j];
        }
        __syncthreads();
    }
    float mv[8];
    *(float4*)(mv)   = *reinterpret_cast<const float4*>(g_minv + bn + tx*4);
    *(float4*)(mv+4) = *reinterpret_cast<const float4*>(g_minv + bn + 64 + tx*4);
    #pragma unroll
    for (int i = 0; i < 8; i++) {
        int rl = (i < 4) ? (ty*4 + i) : (64 + ty*4 + (i-4));
        float lmax = -1e30f; int larg = 0; float lsum = 0.f;
        float ev[8];
        #pragma unroll
        for (int j = 0; j < 8; j++) {
            float s = acc[i][j] * mv[j];
            int col = bn + ((j < 4) ? (tx*4 + j) : (64 + tx*4 + (j-4)));
            if (s > lmax) { lmax = s; larg = col; }
            float e = __expf(s);
            ev[j] = e; lsum += e;
        }
        float* dst = g_sim + (size_t)(bm + rl) * NS + bn;
        *reinterpret_cast<float4*>(dst + tx*4)      = make_float4(ev[0],ev[1],ev[2],ev[3]);
        *reinterpret_cast<float4*>(dst + 64 + tx*4) = make_float4(ev[4],ev[5],ev[6],ev[7]);
        // reduce across the 16 lanes owning this row
        #pragma unroll
        for (int o = 8; o; o >>= 1) {
            float om = __shfl_xor_sync(0xffffffffu, lmax, o, 16);
            int   oa = __shfl_xor_sync(0xffffffffu, larg, o, 16);
            float os = __shfl_xor_sync(0xffffffffu, lsum, o, 16);
            lsum += os;
            if (om > lmax || (om == lmax && oa < larg)) { lmax = om; larg = oa; }
        }
        if (tx == 0) {
            size_t r = (size_t)(bm + rl) * NBLK + bnblk;
            g_pmax[r] = lmax; g_parg[r] = larg; g_psum[r] = lsum;
        }
    }
}

// ---------------- combine per-block partials: argmax + 1/Z per batch row ----
__global__ void __launch_bounds__(256) k_combine() {
    int b = blockIdx.x, t = threadIdx.x;
    size_t base = (size_t)b * NBLK;
    float m1 = g_pmax[base + t],       m2 = g_pmax[base + t + 256];
    int   a1 = g_parg[base + t],       a2 = g_parg[base + t + 256];
    float s  = g_psum[base + t] + g_psum[base + t + 256];
    float m; int a;
    if (m1 > m2 || (m1 == m2 && a1 <= a2)) { m = m1; a = a1; } else { m = m2; a = a2; }
    __shared__ float sm[256]; __shared__ int sa[256]; __shared__ float ss[256];
    sm[t] = m; sa[t] = a; ss[t] = s; __syncthreads();
    for (int o = 128; o; o >>= 1) {
        if (t < o) {
            ss[t] += ss[t+o];
            if (sm[t+o] > sm[t] || (sm[t+o] == sm[t] && sa[t+o] < sa[t])) {
                sm[t] = sm[t+o]; sa[t] = sa[t+o];
            }
        }
        __syncthreads();
    }
    if (t == 0) { g_argmax[b] = sa[0]; g_cZinv[b] = 1.0f / ss[0]; }
}

// ---------------- write weights: fused stats + exp (one block per row) ------
__global__ void __launch_bounds__(512) k_write(const float* __restrict__ prev,
                                               const float* __restrict__ sw) {
    int b = blockIdx.x, t = threadIdx.x, lane = t & 31;
    const float* row = prev + (size_t)b * NS;
    float w0 = sw[0], w1 = sw[1], w2 = sw[2];
    __shared__ float red[512];

    // pass 1: S1 = sum of sharp
    float sum = 0.f;
    for (int it = 0; it < NS / 2048; it++) {
        int i4 = (it * 512 + t) * 4;
        float4 v = *reinterpret_cast<const float4*>(row + i4);
        float pl = __shfl_up_sync(0xffffffffu, v.w, 1);
        float nx = __shfl_down_sync(0xffffffffu, v.x, 1);
        if (lane == 0)  pl = (i4 > 0) ? row[i4 - 1] : 0.f;
        if (lane == 31) nx = (i4 + 4 < NS) ? row[i4 + 4] : 0.f;
        float s0 = pl*w0 + v.x*w1 + v.y*w2;
        float s1 = v.x*w0 + v.y*w1 + v.z*w2;
        float s2 = v.y*w0 + v.z*w1 + v.w*w2;
        float s3 = v.z*w0 + v.w*w1 + nx*w2;
        sum += s0*sqrtf(s0) + s1*sqrtf(s1) + s2*sqrtf(s2) + s3*sqrtf(s3);
    }
    red[t] = sum; __syncthreads();
    for (int o = 256; o; o >>= 1) { if (t < o) red[t] += red[t+o]; __syncthreads(); }
    float sinv = 1.0f / (red[0] + 1e-8f);
    __syncthreads();

    // pass 2: e = exp(w_loc) (w_loc in [0,1], no max needed), Z
    float* wr = g_ww + (size_t)b * NS;
    float z = 0.f;
    for (int it = 0; it < NS / 2048; it++) {
        int i4 = (it * 512 + t) * 4;
        float4 v = *reinterpret_cast<const float4*>(row + i4);
        float pl = __shfl_up_sync(0xffffffffu, v.w, 1);
        float nx = __shfl_down_sync(0xffffffffu, v.x, 1);
        if (lane == 0)  pl = (i4 > 0) ? row[i4 - 1] : 0.f;
        if (lane == 31) nx = (i4 + 4 < NS) ? row[i4 + 4] : 0.f;
        float s0 = pl*w0 + v.x*w1 + v.y*w2;
        float s1 = v.x*w0 + v.y*w1 + v.z*w2;
        float s2 = v.y*w0 + v.z*w1 + v.w*w2;
        float s3 = v.z*w0 + v.w*w1 + nx*w2;
        float4 e;
        e.x = __expf(s0*sqrtf(s0) * sinv);
        e.y = __expf(s1*sqrtf(s1) * sinv);
        e.z = __expf(s2*sqrtf(s2) * sinv);
        e.w = __expf(s3*sqrtf(s3) * sinv);
        *reinterpret_cast<float4*>(wr + i4) = e;
        z += e.x + e.y + e.z + e.w;
    }
    red[t] = z; __syncthreads();
    for (int o = 256; o; o >>= 1) { if (t < o) red[t] += red[t+o]; __syncthreads(); }
    if (t == 0) g_wZinv[b] = 1.0f / red[0];
}

// ---------------- read_topk: one-hot gather of argmax row --------------------
__global__ void k_topk(const float* __restrict__ mem, float* __restrict__ out2) {
    int b = blockIdx.x;
    int t = threadIdx.x;
    out2[(size_t)b * DD + t] = mem[(size_t)g_argmax[b] * DD + t];
}

// ---------------- content GEMM (split-K over n): partial = E @ memory -------
// tile 128b x 256d, 512 threads
__global__ void __launch_bounds__(512) k_content(const float* __restrict__ mem) {
    __shared__ float As[16][132];   // [k][b]  = E
    __shared__ float Bs[16][256];   // [k][d]
    int bm = blockIdx.x * 128;
    int z  = blockIdx.y;
    int tid = threadIdx.x, tx = tid & 31, ty = tid >> 5;
    float acc[8][8];
    #pragma unroll
    for (int i = 0; i < 8; i++)
        #pragma unroll
        for (int j = 0; j < 8; j++) acc[i][j] = 0.f;

    int kbase = z * KCH;
    int am = tid >> 2;
    int akq = (tid & 3) << 2;
    int bkr = tid >> 5;
    int bdc = (tid & 31) << 2;
    for (int k0 = kbase; k0 < kbase + KCH; k0 += 16) {
        float4 a = *reinterpret_cast<const float4*>(g_sim + (size_t)(bm + am) * NS + k0 + akq);
        As[akq+0][am] = a.x; As[akq+1][am] = a.y; As[akq+2][am] = a.z; As[akq+3][am] = a.w;
        *(float4*)&Bs[bkr][bdc] =
            *reinterpret_cast<const float4*>(mem + (size_t)(k0 + bkr) * DD + bdc);
        *(float4*)&Bs[bkr][bdc + 128] =
            *reinterpret_cast<const float4*>(mem + (size_t)(k0 + bkr) * DD + bdc + 128);
        __syncthreads();
        #pragma unroll
        for (int kk = 0; kk < 16; kk++) {
            float a8[8], b8[8];
            *(float4*)(a8)   = *(const float4*)&As[kk][ty*4];
            *(float4*)(a8+4) = *(const float4*)&As[kk][64 + ty*4];
            *(float4*)(b8)   = *(const float4*)&Bs[kk][tx*4];
            *(float4*)(b8+4) = *(const float4*)&Bs[kk][128 + tx*4];
            #pragma unroll
            for (int i = 0; i < 8; i++)
                #pragma unroll
                for (int j = 0; j < 8; j++) acc[i][j] += a8[i]*b8[j];
        }
        __syncthreads();
    }
    #pragma unroll
    for (int i = 0; i < 8; i++) {
        int r = bm + ((i < 4) ? (ty*4 + i) : (64 + ty*4 + (i-4)));
        float* dst = g_partial + ((size_t)z * NB + r) * DD;
        *(float4*)(dst + tx*4)       = make_float4(acc[i][0], acc[i][1], acc[i][2], acc[i][3]);
        *(float4*)(dst + 128 + tx*4) = make_float4(acc[i][4], acc[i][5], acc[i][6], acc[i][7]);
    }
}

// ---------------- reduce split-K partials, scale by 1/Z ----------------------
__global__ void __launch_bounds__(256) k_reduce(float* __restrict__ out1) {
    int idx = blockIdx.x * 256 + threadIdx.x;   // [0, 131072)
    int b = idx >> 8;
    float s = 0.f;
    #pragma unroll 8
    for (int z = 0; z < SPLITS; z++) s += g_partial[(size_t)z * NB * DD + idx];
    out1[idx] = s * g_cZinv[b];
}

// ------- new_mem GEMM + fused erase: out = mem*prod(1-w/2) + w^T @ value ----
// tile 128n x 256d, 512 threads, K = batch (512)
__global__ void __launch_bounds__(512) k_newmem(const float* __restrict__ mem,
                                                const float* __restrict__ value,
                                                float* __restrict__ out3) {
    __shared__ float As[16][128];   // [k=b][n]  = w_write (normalized)
    __shared__ float Bs[16][256];   // [k=b][d]  = value
    __shared__ float red[16][128];
    __shared__ float erase_s[128];
    int bn = blockIdx.x * 128;
    int tid = threadIdx.x, tx = tid & 31, ty = tid >> 5;
    int kr = tid >> 5;              // 0..15
    int c4 = (tid & 31) << 2;       // 0..124
    float acc[8][8];
    #pragma unroll
    for (int i = 0; i < 8; i++)
        #pragma unroll
        for (int j = 0; j < 8; j++) acc[i][j] = 0.f;
    float p0 = 1.f, p1 = 1.f, p2 = 1.f, p3 = 1.f;

    for (int k0 = 0; k0 < NB; k0 += 16) {
        float zi = g_wZinv[k0 + kr];
        float4 a = *reinterpret_cast<const float4*>(g_ww + (size_t)(k0 + kr) * NS + bn + c4);
        a.x *= zi; a.y *= zi; a.z *= zi; a.w *= zi;
        p0 *= (1.0f - 0.5f * a.x);
        p1 *= (1.0f - 0.5f * a.y);
        p2 *= (1.0f - 0.5f * a.z);
        p3 *= (1.0f - 0.5f * a.w);
        *(float4*)&As[kr][c4] = a;
        *(float4*)&Bs[kr][c4] =
            *reinterpret_cast<const float4*>(value + (size_t)(k0 + kr) * DD + c4);
        *(float4*)&Bs[kr][c4 + 128] =
            *reinterpret_cast<const float4*>(value + (size_t)(k0 + kr) * DD + c4 + 128);
        __syncthreads();
        #pragma unroll
        for (int kk = 0; kk < 16; kk++) {
            float a8[8], b8[8];
            *(float4*)(a8)   = *(const float4*)&As[kk][ty*4];
            *(float4*)(a8+4) = *(const float4*)&As[kk][64 + ty*4];
            *(float4*)(b8)   = *(const float4*)&Bs[kk][tx*4];
            *(float4*)(b8+4) = *(const float4*)&Bs[kk][128 + tx*4];
            #pragma unroll
            for (int i = 0; i < 8; i++)
                #pragma unroll
                for (int j = 0; j < 8; j++) acc[i][j] += a8[i]*b8[j];
        }
        __syncthreads();
    }
    // combine erase partials across the 16 kr groups
    red[kr][c4+0] = p0; red[kr][c4+1] = p1; red[kr][c4+2] = p2; red[kr][c4+3] = p3;
    __syncthreads();
    if (tid < 128) {
        float p = 1.f;
        #pragma unroll
        for (int k = 0; k < 16; k++) p *= red[k][tid];
        erase_s[tid] = p;
    }
    __syncthreads();
    #pragma unroll
    for (int i = 0; i < 8; i++) {
        int nl = (i < 4) ? (ty*4 + i) : (64 + ty*4 + (i-4));
        int n = bn + nl;
        float er = erase_s[nl];
        const float* mrow = mem + (size_t)n * DD;
        float* dst = out3 + (size_t)n * DD;
        float4 m0 = *reinterpret_cast<const float4*>(mrow + tx*4);
        float4 m1 = *reinterpret_cast<const float4*>(mrow + 128 + tx*4);
        float4 o0 = make_float4(m0.x*er + acc[i][0], m0.y*er + acc[i][1],
                                m0.z*er + acc[i][2], m0.w*er + acc[i][3]);
        float4 o1 = make_float4(m1.x*er + acc[i][4], m1.y*er + acc[i][5],
                                m1.z*er + acc[i][6], m1.w*er + acc[i][7]);
        *reinterpret_cast<float4*>(dst + tx*4)       = o0;
        *reinterpret_cast<float4*>(dst + 128 + tx*4) = o1;
    }
}

// ---------------- launch ----------------------------------------------------
extern "C" void kernel_launch(void* const* d_in, const int* in_sizes, int n_in,
                              void* d_out, int out_size) {
    const float* memory  = (const float*)d_in[0];
    const float* query   = (const float*)d_in[1];
    const float* value   = (const float*)d_in[2];
    const float* prev    = (const float*)d_in[3];
    const float* shiftw  = (const float*)d_in[4];
    // d_in[5] = k (unused: top-k softmax is provably one-hot at argmax(sim))

    float* out  = (float*)d_out;
    float* out1 = out;                     // read_content [512,256]
    float* out2 = out + NB * DD;           // read_topk    [512,256]
    float* out3 = out + 2 * NB * DD;       // new_mem      [65536,256]

    k_norms  <<<(NS + NB) / 8, dim3(32, 8)>>>(memory, query);
    k_sim    <<<dim3(NBLK, NB / 128), 256>>>(memory);
    k_combine<<<NB, 256>>>();
    k_write  <<<NB, 512>>>(prev, shiftw);
    k_topk   <<<NB, 256>>>(memory, out2);
    k_content<<<dim3(NB / 128, SPLITS), 512>>>(memory);
    k_reduce <<<(NB * DD) / 256, 256>>>(out1);
    k_newmem <<<NS / 128, 512>>>(memory, value, out3);
}

// round 5
// speedup vs baseline: 3.0473x; 2.7055x over previous
#include <cuda_runtime.h>
#include <cuda_bf16.h>
#include <math.h>
#include <stdint.h>

#define NB 512
#define NS 65536
#define DD 256
#define SPLITS 64
#define NBLK 512

// ---------------- scratch (device globals; no allocations allowed) ----------
__device__ __nv_bfloat16 g_simb[(size_t)NB * NS];   // 64 MB : E = exp(sim), bf16
__device__ __nv_bfloat16 g_wwb [(size_t)NB * NS];   // 64 MB : unnorm write softmax, bf16
__device__ float g_qn [NB * DD];
__device__ float g_minv[NS];
__device__ float g_pmax[(size_t)NB * NBLK];
__device__ int   g_parg[(size_t)NB * NBLK];
__device__ float g_psum[(size_t)NB * NBLK];
__device__ int   g_argmax[NB];
__device__ float g_cZinv[NB];
__device__ float g_wZinv[NB];
__device__ float g_partial[(size_t)SPLITS * NB * DD];  // 32 MB

// ======================= helpers ============================================
__device__ __forceinline__ uint32_t smem_u32(const void* p) {
    uint32_t a;
    asm("{ .reg .u64 t; cvta.to.shared.u64 t, %1; cvt.u32.u64 %0, t; }" : "=r"(a) : "l"(p));
    return a;
}
__device__ __forceinline__ uint32_t pack_bf16x2(float lo, float hi) {
    uint32_t r;
    asm("cvt.rn.bf16x2.f32 %0, %1, %2;" : "=r"(r) : "f"(hi), "f"(lo));
    return r;
}
__device__ __forceinline__ void unpack2(uint32_t u, float& a, float& b) {
    __nv_bfloat162 h = *reinterpret_cast<__nv_bfloat162*>(&u);
    a = __bfloat162float(h.x); b = __bfloat162float(h.y);
}
__device__ __forceinline__ void ldsm4(uint32_t* r, uint32_t addr) {
    asm volatile("ldmatrix.sync.aligned.m8n8.x4.shared.b16 {%0,%1,%2,%3}, [%4];"
        : "=r"(r[0]), "=r"(r[1]), "=r"(r[2]), "=r"(r[3]) : "r"(addr));
}
__device__ __forceinline__ void ldsm4t(uint32_t* r, uint32_t addr) {
    asm volatile("ldmatrix.sync.aligned.m8n8.x4.trans.shared.b16 {%0,%1,%2,%3}, [%4];"
        : "=r"(r[0]), "=r"(r[1]), "=r"(r[2]), "=r"(r[3]) : "r"(addr));
}
__device__ __forceinline__ void mma_bf16(float* c, const uint32_t* a, uint32_t b0, uint32_t b1) {
    asm volatile("mma.sync.aligned.m16n8k16.row.col.f32.bf16.bf16.f32 "
        "{%0,%1,%2,%3}, {%4,%5,%6,%7}, {%8,%9}, {%0,%1,%2,%3};"
        : "+f"(c[0]), "+f"(c[1]), "+f"(c[2]), "+f"(c[3])
        : "r"(a[0]), "r"(a[1]), "r"(a[2]), "r"(a[3]), "r"(b0), "r"(b1));
}

// ---------------- norms: memory row inv-norms + normalized query ------------
__global__ void k_norms(const float* __restrict__ mem, const float* __restrict__ q) {
    int lane = threadIdx.x;
    int row  = blockIdx.x * 8 + threadIdx.y;
    if (row < NS) {
        const float4* p = reinterpret_cast<const float4*>(mem + (size_t)row * DD);
        float4 v0 = p[lane];
        float4 v1 = p[lane + 32];
        float s = v0.x*v0.x + v0.y*v0.y + v0.z*v0.z + v0.w*v0.w
                + v1.x*v1.x + v1.y*v1.y + v1.z*v1.z + v1.w*v1.w;
        #pragma unroll
        for (int o = 16; o; o >>= 1) s += __shfl_xor_sync(0xffffffffu, s, o);
        if (lane == 0) g_minv[row] = 1.0f / fmaxf(sqrtf(s), 1e-12f);
    } else {
        int qr = row - NS;
        if (qr < NB) {
            const float4* p = reinterpret_cast<const float4*>(q + (size_t)qr * DD);
            float4 v0 = p[lane];
            float4 v1 = p[lane + 32];
            float s = v0.x*v0.x + v0.y*v0.y + v0.z*v0.z + v0.w*v0.w
                    + v1.x*v1.x + v1.y*v1.y + v1.z*v1.z + v1.w*v1.w;
            #pragma unroll
            for (int o = 16; o; o >>= 1) s += __shfl_xor_sync(0xffffffffu, s, o);
            float inv = 1.0f / fmaxf(sqrtf(s), 1e-12f);
            v0.x *= inv; v0.y *= inv; v0.z *= inv; v0.w *= inv;
            v1.x *= inv; v1.y *= inv; v1.z *= inv; v1.w *= inv;
            float4* o4 = reinterpret_cast<float4*>(g_qn + (size_t)qr * DD);
            o4[lane] = v0; o4[lane + 32] = v1;
        }
    }
}

// ============ sim GEMM (HMMA, split-bf16 3-MMA) + exp epilogue ==============
// CTA 128(b) x 128(n), K=256 in 8 chunks of 32. 8 warps = 2(m) x 4(n).
__global__ void __launch_bounds__(256) k_sim(const float* __restrict__ mem) {
    __shared__ __align__(16) uint16_t sAh[128*40], sAl[128*40], sBh[128*40], sBl[128*40];
    __shared__ float s_minv[128];
    int tid = threadIdx.x, lane = tid & 31, w = tid >> 5;
    int wm = w >> 2, wn = w & 3;
    int bn = blockIdx.x * 128, bm = blockIdx.y * 128;
    if (tid < 32) reinterpret_cast<float4*>(s_minv)[tid] =
        reinterpret_cast<const float4*>(g_minv + bn)[tid];

    float acc[4][4][4];
    #pragma unroll
    for (int i = 0; i < 4; i++)
        #pragma unroll
        for (int j = 0; j < 4; j++)
            #pragma unroll
            for (int u = 0; u < 4; u++) acc[i][j][u] = 0.f;

    uint32_t aAh = smem_u32(sAh), aAl = smem_u32(sAl);
    uint32_t aBh = smem_u32(sBh), aBl = smem_u32(sBl);
    int r = lane & 7, gq = lane >> 3;

    for (int ch = 0; ch < 8; ch++) {
        int k0 = ch * 32;
        #pragma unroll
        for (int i = 0; i < 4; i++) {
            int idx = tid + i * 256;
            int row = idx >> 3, c4 = (idx & 7) * 4;
            float4 v = *reinterpret_cast<const float4*>(g_qn + (size_t)(bm + row) * DD + k0 + c4);
            float hx = __bfloat162float(__float2bfloat16_rn(v.x));
            float hy = __bfloat162float(__float2bfloat16_rn(v.y));
            float hz = __bfloat162float(__float2bfloat16_rn(v.z));
            float hw = __bfloat162float(__float2bfloat16_rn(v.w));
            *reinterpret_cast<uint2*>(&sAh[row*40 + c4]) =
                make_uint2(pack_bf16x2(hx, hy), pack_bf16x2(hz, hw));
            *reinterpret_cast<uint2*>(&sAl[row*40 + c4]) =
                make_uint2(pack_bf16x2(v.x - hx, v.y - hy), pack_bf16x2(v.z - hz, v.w - hw));
            float4 b = *reinterpret_cast<const float4*>(mem + (size_t)(bn + row) * DD + k0 + c4);
            float bx = __bfloat162float(__float2bfloat16_rn(b.x));
            float by = __bfloat162float(__float2bfloat16_rn(b.y));
            float bz = __bfloat162float(__float2bfloat16_rn(b.z));
            float bw = __bfloat162float(__float2bfloat16_rn(b.w));
            *reinterpret_cast<uint2*>(&sBh[row*40 + c4]) =
                make_uint2(pack_bf16x2(bx, by), pack_bf16x2(bz, bw));
            *reinterpret_cast<uint2*>(&sBl[row*40 + c4]) =
                make_uint2(pack_bf16x2(b.x - bx, b.y - by), pack_bf16x2(b.z - bz, b.w - bw));
        }
        __syncthreads();
        #pragma unroll
        for (int ks = 0; ks < 2; ks++) {
            int kk = ks * 16;
            uint32_t ah[4][4], al[4][4], bh[2][4], bl[2][4];
            #pragma unroll
            for (int mt = 0; mt < 4; mt++) {
                int arow = wm*64 + mt*16 + r + 8*(gq & 1);
                int acol = kk + 8*(gq >> 1);
                uint32_t off = (uint32_t)(arow*80 + acol*2);
                ldsm4(ah[mt], aAh + off);
                ldsm4(al[mt], aAl + off);
            }
            #pragma unroll
            for (int np = 0; np < 2; np++) {
                int brow = wn*32 + np*16 + r + 8*(gq >> 1);
                int bcol = kk + 8*(gq & 1);
                uint32_t off = (uint32_t)(brow*80 + bcol*2);
                ldsm4(bh[np], aBh + off);
                ldsm4(bl[np], aBl + off);
            }
            #pragma unroll
            for (int mt = 0; mt < 4; mt++)
                #pragma unroll
                for (int nt = 0; nt < 4; nt++) {
                    int np = nt >> 1, hb = (nt & 1) * 2;
                    mma_bf16(acc[mt][nt], ah[mt], bh[np][hb], bh[np][hb+1]);
                    mma_bf16(acc[mt][nt], ah[mt], bl[np][hb], bl[np][hb+1]);
                    mma_bf16(acc[mt][nt], al[mt], bh[np][hb], bh[np][hb+1]);
                }
        }
        __syncthreads();
    }

    // epilogue — stats arrays alias the (now idle) operand buffers
    float* s_max = reinterpret_cast<float*>(sAh);   // [4][128]
    int*   s_arg = reinterpret_cast<int*>(sAl);
    float* s_sum = reinterpret_cast<float*>(sBh);
    int g = lane >> 2, t = lane & 3;
    #pragma unroll
    for (int mt = 0; mt < 4; mt++)
        #pragma unroll
        for (int rs = 0; rs < 2; rs++) {
            int mloc = wm*64 + mt*16 + g + rs*8;
            float lm = -1e30f; int la = 0; float ls = 0.f;
            #pragma unroll
            for (int nt = 0; nt < 4; nt++) {
                int ncl = wn*32 + nt*8 + t*2;
                float s0 = acc[mt][nt][rs*2]   * s_minv[ncl];
                float s1 = acc[mt][nt][rs*2+1] * s_minv[ncl+1];
                int col0 = bn + ncl;
                if (s0 > lm) { lm = s0; la = col0; }
                if (s1 > lm) { lm = s1; la = col0 + 1; }
                float e0 = __expf(s0), e1 = __expf(s1);
                ls += e0 + e1;
                *reinterpret_cast<uint32_t*>(g_simb + (size_t)(bm + mloc) * NS + col0) =
                    pack_bf16x2(e0, e1);
            }
            #pragma unroll
            for (int o = 1; o < 4; o <<= 1) {
                float om = __shfl_xor_sync(0xffffffffu, lm, o);
                int   oa = __shfl_xor_sync(0xffffffffu, la, o);
                float os = __shfl_xor_sync(0xffffffffu, ls, o);
                ls += os;
                if (om > lm || (om == lm && oa < la)) { lm = om; la = oa; }
            }
            if (t == 0) {
                s_max[wn*128 + mloc] = lm;
                s_arg[wn*128 + mloc] = la;
                s_sum[wn*128 + mloc] = ls;
            }
        }
    __syncthreads();
    if (tid < 128) {
        float m = s_max[tid]; int a = s_arg[tid]; float s = s_sum[tid];
        #pragma unroll
        for (int wq = 1; wq < 4; wq++) {
            float om = s_max[wq*128 + tid]; int oa = s_arg[wq*128 + tid];
            s += s_sum[wq*128 + tid];
            if (om > m || (om == m && oa < a)) { m = om; a = oa; }
        }
        size_t pidx = (size_t)(bm + tid) * NBLK + blockIdx.x;
        g_pmax[pidx] = m; g_parg[pidx] = a; g_psum[pidx] = s;
    }
}

// ---------------- combine per-block partials: argmax + 1/Z per batch row ----
__global__ void __launch_bounds__(256) k_combine() {
    int b = blockIdx.x, t = threadIdx.x;
    size_t base = (size_t)b * NBLK;
    float m1 = g_pmax[base + t],       m2 = g_pmax[base + t + 256];
    int   a1 = g_parg[base + t],       a2 = g_parg[base + t + 256];
    float s  = g_psum[base + t] + g_psum[base + t + 256];
    float m; int a;
    if (m1 > m2 || (m1 == m2 && a1 <= a2)) { m = m1; a = a1; } else { m = m2; a = a2; }
    __shared__ float sm[256]; __shared__ int sa[256]; __shared__ float ss[256];
    sm[t] = m; sa[t] = a; ss[t] = s; __syncthreads();
    for (int o = 128; o; o >>= 1) {
        if (t < o) {
            ss[t] += ss[t+o];
            if (sm[t+o] > sm[t] || (sm[t+o] == sm[t] && sa[t+o] < sa[t])) {
                sm[t] = sm[t+o]; sa[t] = sa[t+o];
            }
        }
        __syncthreads();
    }
    if (t == 0) { g_argmax[b] = sa[0]; g_cZinv[b] = 1.0f / ss[0]; }
}

// ---------------- write weights: fused stats + exp, bf16 out ----------------
__global__ void __launch_bounds__(512) k_write(const float* __restrict__ prev,
                                               const float* __restrict__ sw) {
    int b = blockIdx.x, t = threadIdx.x, lane = t & 31;
    const float* row = prev + (size_t)b * NS;
    float w0 = sw[0], w1 = sw[1], w2 = sw[2];
    __shared__ float red[512];

    float sum = 0.f;
    for (int it = 0; it < NS / 2048; it++) {
        int i4 = (it * 512 + t) * 4;
        float4 v = *reinterpret_cast<const float4*>(row + i4);
        float pl = __shfl_up_sync(0xffffffffu, v.w, 1);
        float nx = __shfl_down_sync(0xffffffffu, v.x, 1);
        if (lane == 0)  pl = (i4 > 0) ? row[i4 - 1] : 0.f;
        if (lane == 31) nx = (i4 + 4 < NS) ? row[i4 + 4] : 0.f;
        float s0 = pl*w0 + v.x*w1 + v.y*w2;
        float s1 = v.x*w0 + v.y*w1 + v.z*w2;
        float s2 = v.y*w0 + v.z*w1 + v.w*w2;
        float s3 = v.z*w0 + v.w*w1 + nx*w2;
        sum += s0*sqrtf(s0) + s1*sqrtf(s1) + s2*sqrtf(s2) + s3*sqrtf(s3);
    }
    red[t] = sum; __syncthreads();
    for (int o = 256; o; o >>= 1) { if (t < o) red[t] += red[t+o]; __syncthreads(); }
    float sinv = 1.0f / (red[0] + 1e-8f);
    __syncthreads();

    __nv_bfloat16* wr = g_wwb + (size_t)b * NS;
    float z = 0.f;
    for (int it = 0; it < NS / 2048; it++) {
        int i4 = (it * 512 + t) * 4;
        float4 v = *reinterpret_cast<const float4*>(row + i4);
        float pl = __shfl_up_sync(0xffffffffu, v.w, 1);
        float nx = __shfl_down_sync(0xffffffffu, v.x, 1);
        if (lane == 0)  pl = (i4 > 0) ? row[i4 - 1] : 0.f;
        if (lane == 31) nx = (i4 + 4 < NS) ? row[i4 + 4] : 0.f;
        float s0 = pl*w0 + v.x*w1 + v.y*w2;
        float s1 = v.x*w0 + v.y*w1 + v.z*w2;
        float s2 = v.y*w0 + v.z*w1 + v.w*w2;
        float s3 = v.z*w0 + v.w*w1 + nx*w2;
        float e0 = __expf(s0*sqrtf(s0) * sinv);
        float e1 = __expf(s1*sqrtf(s1) * sinv);
        float e2 = __expf(s2*sqrtf(s2) * sinv);
        float e3 = __expf(s3*sqrtf(s3) * sinv);
        z += e0 + e1 + e2 + e3;
        *reinterpret_cast<uint2*>(wr + i4) =
            make_uint2(pack_bf16x2(e0, e1), pack_bf16x2(e2, e3));
    }
    red[t] = z; __syncthreads();
    for (int o = 256; o; o >>= 1) { if (t < o) red[t] += red[t+o]; __syncthreads(); }
    if (t == 0) g_wZinv[b] = 1.0f / red[0];
}

// ---------------- read_topk: one-hot gather of argmax row --------------------
__global__ void k_topk(const float* __restrict__ mem, float* __restrict__ out2) {
    int b = blockIdx.x;
    int t = threadIdx.x;
    out2[(size_t)b * DD + t] = mem[(size_t)g_argmax[b] * DD + t];
}

// ============ content GEMM (HMMA bf16, split-K over n) ======================
// C[b][d] partials. CTA 128(b) x 128(d), k-chunk 1024 per z, 32 sub-chunks.
__global__ void __launch_bounds__(256) k_content(const float* __restrict__ mem) {
    __shared__ __align__(16) uint16_t sA[128*40], sB[32*136];
    int tid = threadIdx.x, lane = tid & 31, w = tid >> 5;
    int wm = w >> 2, wn = w & 3;
    int bm = blockIdx.x * 128, bn2 = blockIdx.y * 128, z = blockIdx.z;
    float acc[4][4][4];
    #pragma unroll
    for (int i = 0; i < 4; i++)
        #pragma unroll
        for (int j = 0; j < 4; j++)
            #pragma unroll
            for (int u = 0; u < 4; u++) acc[i][j][u] = 0.f;
    uint32_t aA = smem_u32(sA), aB = smem_u32(sB);
    int r = lane & 7, gq = lane >> 3;

    for (int it = 0; it < 32; it++) {
        int k0 = z * 1024 + it * 32;
        #pragma unroll
        for (int i = 0; i < 4; i++) {
            int idx = tid + i * 256;
            int row = idx >> 3, c2 = (idx & 7);
            *reinterpret_cast<uint2*>(&sA[row*40 + c2*4]) =
                *reinterpret_cast<const uint2*>(g_simb + (size_t)(bm + row) * NS + k0 + c2*4);
        }
        #pragma unroll
        for (int i = 0; i < 4; i++) {
            int idx = tid + i * 256;
            int row = idx >> 5, c4 = (idx & 31) * 4;
            float4 v = *reinterpret_cast<const float4*>(mem + (size_t)(k0 + row) * DD + bn2 + c4);
            *reinterpret_cast<uint2*>(&sB[row*136 + c4]) =
                make_uint2(pack_bf16x2(v.x, v.y), pack_bf16x2(v.z, v.w));
        }
        __syncthreads();
        #pragma unroll
        for (int ks = 0; ks < 2; ks++) {
            int kk = ks * 16;
            uint32_t af[4][4], bf[2][4];
            #pragma unroll
            for (int mt = 0; mt < 4; mt++) {
                int arow = wm*64 + mt*16 + r + 8*(gq & 1);
                int acol = kk + 8*(gq >> 1);
                ldsm4(af[mt], aA + (uint32_t)(arow*80 + acol*2));
            }
            #pragma unroll
            for (int np = 0; np < 2; np++) {
                int brow = kk + r + 8*(gq & 1);
                int bcol = wn*32 + np*16 + 8*(gq >> 1);
                ldsm4t(bf[np], aB + (uint32_t)(brow*272 + bcol*2));
            }
            #pragma unroll
            for (int mt = 0; mt < 4; mt++)
                #pragma unroll
                for (int nt = 0; nt < 4; nt++) {
                    int np = nt >> 1, hb = (nt & 1) * 2;
                    mma_bf16(acc[mt][nt], af[mt], bf[np][hb], bf[np][hb+1]);
                }
        }
        __syncthreads();
    }
    int g = lane >> 2, t = lane & 3;
    #pragma unroll
    for (int mt = 0; mt < 4; mt++)
        #pragma unroll
        for (int rs = 0; rs < 2; rs++) {
            int mloc = wm*64 + mt*16 + g + rs*8;
            float* dst = g_partial + ((size_t)z * NB + bm + mloc) * DD + bn2;
            #pragma unroll
            for (int nt = 0; nt < 4; nt++) {
                int off = wn*32 + nt*8 + t*2;
                *reinterpret_cast<float2*>(dst + off) =
                    make_float2(acc[mt][nt][rs*2], acc[mt][nt][rs*2+1]);
            }
        }
}

// ---------------- reduce split-K partials, scale by 1/Z ----------------------
__global__ void __launch_bounds__(256) k_reduce(float* __restrict__ out1) {
    int idx = blockIdx.x * 256 + threadIdx.x;
    int b = idx >> 8;
    float s = 0.f;
    #pragma unroll 8
    for (int z = 0; z < SPLITS; z++) s += g_partial[(size_t)z * NB * DD + idx];
    out1[idx] = s * g_cZinv[b];
}

// ======= new_mem GEMM (HMMA bf16) + fused erase ==============================
// C[slot][d] = mem*erase + w^T v. CTA 128(slot) x 128(d), K=512 in 16 chunks.
__global__ void __launch_bounds__(256) k_newmem(const float* __restrict__ mem,
                                                const float* __restrict__ value,
                                                float* __restrict__ out3) {
    __shared__ __align__(16) uint16_t sA[32*136], sB[32*136];
    __shared__ float s_red[16][128];
    __shared__ float s_zinv[NB];
    __shared__ float s_erase[128];
    int tid = threadIdx.x, lane = tid & 31, w = tid >> 5;
    int wm = w >> 2, wn = w & 3;
    int bm = blockIdx.x * 128, bn2 = blockIdx.y * 128;
    if (tid < 128) reinterpret_cast<float4*>(s_zinv)[tid] =
        reinterpret_cast<const float4*>(g_wZinv)[tid];
    float acc[4][4][4];
    #pragma unroll
    for (int i = 0; i < 4; i++)
        #pragma unroll
        for (int j = 0; j < 4; j++)
            #pragma unroll
            for (int u = 0; u < 4; u++) acc[i][j][u] = 0.f;
    float pr[8];
    #pragma unroll
    for (int j = 0; j < 8; j++) pr[j] = 1.f;
    uint32_t aA = smem_u32(sA), aB = smem_u32(sB);
    int r = lane & 7, gq = lane >> 3;
    int mc8 = (tid & 15) * 8;
    __syncthreads();

    for (int ch = 0; ch < 16; ch++) {
        int k0 = ch * 32;
        #pragma unroll
        for (int i = 0; i < 2; i++) {
            int idx = tid + i * 256;
            int row = idx >> 4;
            uint4 u = *reinterpret_cast<const uint4*>(g_wwb + (size_t)(k0 + row) * NS + bm + mc8);
            float zi = s_zinv[k0 + row];
            float f0, f1, f2, f3, f4, f5, f6, f7;
            unpack2(u.x, f0, f1); unpack2(u.y, f2, f3);
            unpack2(u.z, f4, f5); unpack2(u.w, f6, f7);
            f0 *= zi; f1 *= zi; f2 *= zi; f3 *= zi;
            f4 *= zi; f5 *= zi; f6 *= zi; f7 *= zi;
            pr[0] *= (1.f - 0.5f*f0); pr[1] *= (1.f - 0.5f*f1);
            pr[2] *= (1.f - 0.5f*f2); pr[3] *= (1.f - 0.5f*f3);
            pr[4] *= (1.f - 0.5f*f4); pr[5] *= (1.f - 0.5f*f5);
            pr[6] *= (1.f - 0.5f*f6); pr[7] *= (1.f - 0.5f*f7);
            uint4 st;
            st.x = pack_bf16x2(f0, f1); st.y = pack_bf16x2(f2, f3);
            st.z = pack_bf16x2(f4, f5); st.w = pack_bf16x2(f6, f7);
            *reinterpret_cast<uint4*>(&sA[row*136 + mc8]) = st;
        }
        #pragma unroll
        for (int i = 0; i < 4; i++) {
            int idx = tid + i * 256;
            int row = idx >> 5, c4 = (idx & 31) * 4;
            float4 v = *reinterpret_cast<const float4*>(value + (size_t)(k0 + row) * DD + bn2 + c4);
            *reinterpret_cast<uint2*>(&sB[row*136 + c4]) =
                make_uint2(pack_bf16x2(v.x, v.y), pack_bf16x2(v.z, v.w));
        }
        __syncthreads();
        #pragma unroll
        for (int ks = 0; ks < 2; ks++) {
            int kk = ks * 16;
            uint32_t af[4][4], bf[2][4];
            #pragma unroll
            for (int mt = 0; mt < 4; mt++) {
                int arow = kk + r + 8*(gq >> 1);
                int acol = wm*64 + mt*16 + 8*(gq & 1);
                ldsm4t(af[mt], aA + (uint32_t)(arow*272 + acol*2));
            }
            #pragma unroll
            for (int np = 0; np < 2; np++) {
                int brow = kk + r + 8*(gq & 1);
                int bcol = wn*32 + np*16 + 8*(gq >> 1);
                ldsm4t(bf[np], aB + (uint32_t)(brow*272 + bcol*2));
            }
            #pragma unroll
            for (int mt = 0; mt < 4; mt++)
                #pragma unroll
                for (int nt = 0; nt < 4; nt++) {
                    int np = nt >> 1, hb = (nt & 1) * 2;
                    mma_bf16(acc[mt][nt], af[mt], bf[np][hb], bf[np][hb+1]);
                }
        }
        __syncthreads();
    }
    #pragma unroll
    for (int j = 0; j < 8; j++) s_red[tid >> 4][mc8 + j] = pr[j];
    __syncthreads();
    if (tid < 128) {
        float p = 1.f;
        #pragma unroll
        for (int k = 0; k < 16; k++) p *= s_red[k][tid];
        s_erase[tid] = p;
    }
    __syncthreads();
    int g = lane >> 2, t = lane & 3;
    #pragma unroll
    for (int mt = 0; mt < 4; mt++)
        #pragma unroll
        for (int rs = 0; rs < 2; rs++) {
            int mloc = wm*64 + mt*16 + g + rs*8;
            int slot = bm + mloc;
            float er = s_erase[mloc];
            const float* mrow = mem + (size_t)slot * DD + bn2;
            float* dst = out3 + (size_t)slot * DD + bn2;
            #pragma unroll
            for (int nt = 0; nt < 4; nt++) {
                int off = wn*32 + nt*8 + t*2;
                float2 mv = *reinterpret_cast<const float2*>(mrow + off);
                *reinterpret_cast<float2*>(dst + off) =
                    make_float2(mv.x*er + acc[mt][nt][rs*2], mv.y*er + acc[mt][nt][rs*2+1]);
            }
        }
}

// ---------------- launch ----------------------------------------------------
extern "C" void kernel_launch(void* const* d_in, const int* in_sizes, int n_in,
                              void* d_out, int out_size) {
    const float* memory  = (const float*)d_in[0];
    const float* query   = (const float*)d_in[1];
    const float* value   = (const float*)d_in[2];
    const float* prev    = (const float*)d_in[3];
    const float* shiftw  = (const float*)d_in[4];

    float* out  = (float*)d_out;
    float* out1 = out;                     // read_content [512,256]
    float* out2 = out + NB * DD;           // read_topk    [512,256]
    float* out3 = out + 2 * NB * DD;       // new_mem      [65536,256]

    k_norms  <<<(NS + NB) / 8, dim3(32, 8)>>>(memory, query);
    k_sim    <<<dim3(NS / 128, NB / 128), 256>>>(memory);
    k_combine<<<NB, 256>>>();
    k_write  <<<NB, 512>>>(prev, shiftw);
    k_topk   <<<NB, 256>>>(memory, out2);
    k_content<<<dim3(NB / 128, DD / 128, SPLITS), 256>>>(memory);
    k_reduce <<<(NB * DD) / 256, 256>>>(out1);
    k_newmem <<<dim3(NS / 128, DD / 128), 256>>>(memory, value, out3);
}

// round 6
// speedup vs baseline: 3.0614x; 1.0046x over previous
#include <cuda_runtime.h>
#include <cuda_bf16.h>
#include <math.h>
#include <stdint.h>

#define NB 512
#define NS 65536
#define DD 256
#define SPLITS 64
#define NBLK 512

// ---------------- scratch (device globals; no allocations allowed) ----------
__device__ __nv_bfloat16 g_simb[(size_t)NB * NS];   // 64 MB : E = exp(sim), bf16
__device__ __nv_bfloat16 g_wwb [(size_t)NB * NS];   // 64 MB : unnorm write softmax, bf16
__device__ float g_qn [NB * DD];
__device__ float g_minv[NS];
__device__ float g_pmax[(size_t)NB * NBLK];
__device__ float g_psum[(size_t)NB * NBLK];
__device__ float g_rowmax[NB];
__device__ int   g_argmax[NB];
__device__ float g_cZinv[NB];
__device__ float g_wZinv[NB];
__device__ float g_partial[(size_t)SPLITS * NB * DD];  // 32 MB

// ======================= helpers ============================================
__device__ __forceinline__ uint32_t smem_u32(const void* p) {
    uint32_t a;
    asm("{ .reg .u64 t; cvta.to.shared.u64 t, %1; cvt.u32.u64 %0, t; }" : "=r"(a) : "l"(p));
    return a;
}
__device__ __forceinline__ uint32_t pack_bf16x2(float lo, float hi) {
    uint32_t r;
    asm("cvt.rn.bf16x2.f32 %0, %1, %2;" : "=r"(r) : "f"(hi), "f"(lo));
    return r;
}
__device__ __forceinline__ void unpack2(uint32_t u, float& a, float& b) {
    __nv_bfloat162 h = *reinterpret_cast<__nv_bfloat162*>(&u);
    a = __bfloat162float(h.x); b = __bfloat162float(h.y);
}
__device__ __forceinline__ void ldsm4(uint32_t* r, uint32_t addr) {
    asm volatile("ldmatrix.sync.aligned.m8n8.x4.shared.b16 {%0,%1,%2,%3}, [%4];"
        : "=r"(r[0]), "=r"(r[1]), "=r"(r[2]), "=r"(r[3]) : "r"(addr));
}
__device__ __forceinline__ void ldsm4t(uint32_t* r, uint32_t addr) {
    asm volatile("ldmatrix.sync.aligned.m8n8.x4.trans.shared.b16 {%0,%1,%2,%3}, [%4];"
        : "=r"(r[0]), "=r"(r[1]), "=r"(r[2]), "=r"(r[3]) : "r"(addr));
}
__device__ __forceinline__ void mma_bf16(float* c, const uint32_t* a, uint32_t b0, uint32_t b1) {
    asm volatile("mma.sync.aligned.m16n8k16.row.col.f32.bf16.bf16.f32 "
        "{%0,%1,%2,%3}, {%4,%5,%6,%7}, {%8,%9}, {%0,%1,%2,%3};"
        : "+f"(c[0]), "+f"(c[1]), "+f"(c[2]), "+f"(c[3])
        : "r"(a[0]), "r"(a[1]), "r"(a[2]), "r"(a[3]), "r"(b0), "r"(b1));
}

// ---------------- norms: memory row inv-norms + normalized query ------------
__global__ void k_norms(const float* __restrict__ mem, const float* __restrict__ q) {
    int lane = threadIdx.x;
    int row  = blockIdx.x * 8 + threadIdx.y;
    if (row < NS) {
        const float4* p = reinterpret_cast<const float4*>(mem + (size_t)row * DD);
        float4 v0 = p[lane];
        float4 v1 = p[lane + 32];
        float s = v0.x*v0.x + v0.y*v0.y + v0.z*v0.z + v0.w*v0.w
                + v1.x*v1.x + v1.y*v1.y + v1.z*v1.z + v1.w*v1.w;
        #pragma unroll
        for (int o = 16; o; o >>= 1) s += __shfl_xor_sync(0xffffffffu, s, o);
        if (lane == 0) g_minv[row] = 1.0f / fmaxf(sqrtf(s), 1e-12f);
    } else {
        int qr = row - NS;
        if (qr < NB) {
            const float4* p = reinterpret_cast<const float4*>(q + (size_t)qr * DD);
            float4 v0 = p[lane];
            float4 v1 = p[lane + 32];
            float s = v0.x*v0.x + v0.y*v0.y + v0.z*v0.z + v0.w*v0.w
                    + v1.x*v1.x + v1.y*v1.y + v1.z*v1.z + v1.w*v1.w;
            #pragma unroll
            for (int o = 16; o; o >>= 1) s += __shfl_xor_sync(0xffffffffu, s, o);
            float inv = 1.0f / fmaxf(sqrtf(s), 1e-12f);
            v0.x *= inv; v0.y *= inv; v0.z *= inv; v0.w *= inv;
            v1.x *= inv; v1.y *= inv; v1.z *= inv; v1.w *= inv;
            float4* o4 = reinterpret_cast<float4*>(g_qn + (size_t)qr * DD);
            o4[lane] = v0; o4[lane + 32] = v1;
        }
    }
}

// ============ sim GEMM (HMMA, 1-term bf16) + exp epilogue ====================
// CTA 128(b) x 128(n), K=256 in 8 chunks of 32. 8 warps = 2(m) x 4(n).
__global__ void __launch_bounds__(256) k_sim(const float* __restrict__ mem) {
    __shared__ __align__(16) uint16_t sA[128*40], sB[128*40];
    __shared__ float s_minv[128];
    int tid = threadIdx.x, lane = tid & 31, w = tid >> 5;
    int wm = w >> 2, wn = w & 3;
    int bn = blockIdx.x * 128, bm = blockIdx.y * 128;
    if (tid < 32) reinterpret_cast<float4*>(s_minv)[tid] =
        reinterpret_cast<const float4*>(g_minv + bn)[tid];

    float acc[4][4][4];
    #pragma unroll
    for (int i = 0; i < 4; i++)
        #pragma unroll
        for (int j = 0; j < 4; j++)
            #pragma unroll
            for (int u = 0; u < 4; u++) acc[i][j][u] = 0.f;

    uint32_t aA = smem_u32(sA), aB = smem_u32(sB);
    int r = lane & 7, gq = lane >> 3;

    for (int ch = 0; ch < 8; ch++) {
        int k0 = ch * 32;
        #pragma unroll
        for (int i = 0; i < 4; i++) {
            int idx = tid + i * 256;
            int row = idx >> 3, c4 = (idx & 7) * 4;
            float4 v = *reinterpret_cast<const float4*>(g_qn + (size_t)(bm + row) * DD + k0 + c4);
            *reinterpret_cast<uint2*>(&sA[row*40 + c4]) =
                make_uint2(pack_bf16x2(v.x, v.y), pack_bf16x2(v.z, v.w));
            float4 b = *reinterpret_cast<const float4*>(mem + (size_t)(bn + row) * DD + k0 + c4);
            *reinterpret_cast<uint2*>(&sB[row*40 + c4]) =
                make_uint2(pack_bf16x2(b.x, b.y), pack_bf16x2(b.z, b.w));
        }
        __syncthreads();
        #pragma unroll
        for (int ks = 0; ks < 2; ks++) {
            int kk = ks * 16;
            uint32_t ah[4][4], bh[2][4];
            #pragma unroll
            for (int mt = 0; mt < 4; mt++) {
                int arow = wm*64 + mt*16 + r + 8*(gq & 1);
                int acol = kk + 8*(gq >> 1);
                ldsm4(ah[mt], aA + (uint32_t)(arow*80 + acol*2));
            }
            #pragma unroll
            for (int np = 0; np < 2; np++) {
                int brow = wn*32 + np*16 + r + 8*(gq >> 1);
                int bcol = kk + 8*(gq & 1);
                ldsm4(bh[np], aB + (uint32_t)(brow*80 + bcol*2));
            }
            #pragma unroll
            for (int mt = 0; mt < 4; mt++)
                #pragma unroll
                for (int nt = 0; nt < 4; nt++) {
                    int np = nt >> 1, hb = (nt & 1) * 2;
                    mma_bf16(acc[mt][nt], ah[mt], bh[np][hb], bh[np][hb+1]);
                }
        }
        __syncthreads();
    }

    // epilogue — stats arrays alias the (now idle) operand buffers
    float* s_max = reinterpret_cast<float*>(sA);   // [4][128]
    float* s_sum = reinterpret_cast<float*>(sB);
    int g = lane >> 2, t = lane & 3;
    #pragma unroll
    for (int mt = 0; mt < 4; mt++)
        #pragma unroll
        for (int rs = 0; rs < 2; rs++) {
            int mloc = wm*64 + mt*16 + g + rs*8;
            float lm = -1e30f; float ls = 0.f;
            #pragma unroll
            for (int nt = 0; nt < 4; nt++) {
                int ncl = wn*32 + nt*8 + t*2;
                float s0 = acc[mt][nt][rs*2]   * s_minv[ncl];
                float s1 = acc[mt][nt][rs*2+1] * s_minv[ncl+1];
                lm = fmaxf(lm, fmaxf(s0, s1));
                float e0 = __expf(s0), e1 = __expf(s1);
                ls += e0 + e1;
                *reinterpret_cast<uint32_t*>(g_simb + (size_t)(bm + mloc) * NS + bn + ncl) =
                    pack_bf16x2(e0, e1);
            }
            #pragma unroll
            for (int o = 1; o < 4; o <<= 1) {
                lm = fmaxf(lm, __shfl_xor_sync(0xffffffffu, lm, o));
                ls += __shfl_xor_sync(0xffffffffu, ls, o);
            }
            if (t == 0) {
                s_max[wn*128 + mloc] = lm;
                s_sum[wn*128 + mloc] = ls;
            }
        }
    __syncthreads();
    if (tid < 128) {
        float m = s_max[tid]; float s = s_sum[tid];
        #pragma unroll
        for (int wq = 1; wq < 4; wq++) {
            m = fmaxf(m, s_max[wq*128 + tid]);
            s += s_sum[wq*128 + tid];
        }
        size_t pidx = (size_t)(bm + tid) * NBLK + blockIdx.x;
        g_pmax[pidx] = m; g_psum[pidx] = s;
    }
}

// ---------------- combine per-block partials: row max + 1/Z ------------------
__global__ void __launch_bounds__(256) k_combine() {
    int b = blockIdx.x, t = threadIdx.x;
    size_t base = (size_t)b * NBLK;
    float m = fmaxf(g_pmax[base + t], g_pmax[base + t + 256]);
    float s = g_psum[base + t] + g_psum[base + t + 256];
    __shared__ float sm[256]; __shared__ float ss[256];
    sm[t] = m; ss[t] = s; __syncthreads();
    for (int o = 128; o; o >>= 1) {
        if (t < o) { ss[t] += ss[t+o]; sm[t] = fmaxf(sm[t], sm[t+o]); }
        __syncthreads();
    }
    if (t == 0) { g_rowmax[b] = sm[0]; g_cZinv[b] = 1.0f / ss[0]; }
}

// ------- exact argmax: candidate scan over E + fp32 rescore ------------------
__global__ void __launch_bounds__(256) k_argmax(const float* __restrict__ mem) {
    int b = blockIdx.x, t = threadIdx.x, lane = t & 31, w = t >> 5;
    __shared__ int s_cnt;
    __shared__ int s_cand[128];
    __shared__ float s_bv[8]; __shared__ int s_bi[8];
    if (t == 0) s_cnt = 0;
    __syncthreads();
    // threshold: 1-term sim error (<=1e-3) + bf16 E rounding (0.4%) << 0.006+1%
    float Eth = __expf(g_rowmax[b] - 0.006f) * 0.99f;
    const uint4* rp = reinterpret_cast<const uint4*>(g_simb + (size_t)b * NS);
    for (int i = t; i < NS / 8; i += 256) {
        uint4 u = rp[i];
        float f[8];
        unpack2(u.x, f[0], f[1]); unpack2(u.y, f[2], f[3]);
        unpack2(u.z, f[4], f[5]); unpack2(u.w, f[6], f[7]);
        #pragma unroll
        for (int j = 0; j < 8; j++) {
            if (f[j] > Eth) {
                int p = atomicAdd(&s_cnt, 1);
                if (p < 128) s_cand[p] = i * 8 + j;
            }
        }
    }
    __syncthreads();
    int nc = min(s_cnt, 128);
    float bv = -1e30f; int bi = 0x7fffffff;
    const float* q = g_qn + (size_t)b * DD;
    for (int c = w; c < nc; c += 8) {
        int n = s_cand[c];
        const float* mr = mem + (size_t)n * DD;
        float s = 0.f;
        #pragma unroll
        for (int j = 0; j < 8; j++) s += q[lane * 8 + j] * mr[lane * 8 + j];
        #pragma unroll
        for (int o = 16; o; o >>= 1) s += __shfl_xor_sync(0xffffffffu, s, o);
        s *= g_minv[n];
        if (lane == 0) {
            if (s > bv || (s == bv && n < bi)) { bv = s; bi = n; }
        }
    }
    if (lane == 0) { s_bv[w] = bv; s_bi[w] = bi; }
    __syncthreads();
    if (t == 0) {
        float v = s_bv[0]; int ix = s_bi[0];
        #pragma unroll
        for (int k = 1; k < 8; k++) {
            if (s_bv[k] > v || (s_bv[k] == v && s_bi[k] < ix)) { v = s_bv[k]; ix = s_bi[k]; }
        }
        g_argmax[b] = ix;
    }
}

// ------- write weights: single DRAM pass, sharp cached bf16 in smem ----------
extern __shared__ __nv_bfloat16 s_sp[];   // 65536 bf16 = 128 KB
__global__ void __launch_bounds__(512) k_write(const float* __restrict__ prev,
                                               const float* __restrict__ sw) {
    int b = blockIdx.x, t = threadIdx.x, lane = t & 31;
    const float* row = prev + (size_t)b * NS;
    float w0 = sw[0], w1 = sw[1], w2 = sw[2];
    __shared__ float red[512];

    float sum = 0.f;
    for (int it = 0; it < NS / 2048; it++) {
        int i4 = (it * 512 + t) * 4;
        float4 v = *reinterpret_cast<const float4*>(row + i4);
        float pl = __shfl_up_sync(0xffffffffu, v.w, 1);
        float nx = __shfl_down_sync(0xffffffffu, v.x, 1);
        if (lane == 0)  pl = (i4 > 0) ? row[i4 - 1] : 0.f;
        if (lane == 31) nx = (i4 + 4 < NS) ? row[i4 + 4] : 0.f;
        float s0 = pl*w0 + v.x*w1 + v.y*w2;
        float s1 = v.x*w0 + v.y*w1 + v.z*w2;
        float s2 = v.y*w0 + v.z*w1 + v.w*w2;
        float s3 = v.z*w0 + v.w*w1 + nx*w2;
        float p0 = s0*sqrtf(s0), p1 = s1*sqrtf(s1);
        float p2 = s2*sqrtf(s2), p3 = s3*sqrtf(s3);
        sum += p0 + p1 + p2 + p3;
        *reinterpret_cast<uint2*>(s_sp + i4) =
            make_uint2(pack_bf16x2(p0, p1), pack_bf16x2(p2, p3));
    }
    red[t] = sum; __syncthreads();
    for (int o = 256; o; o >>= 1) { if (t < o) red[t] += red[t+o]; __syncthreads(); }
    float sinv = 1.0f / (red[0] + 1e-8f);
    __syncthreads();

    __nv_bfloat16* wr = g_wwb + (size_t)b * NS;
    float z = 0.f;
    for (int it = 0; it < NS / 2048; it++) {
        int i4 = (it * 512 + t) * 4;
        uint2 u = *reinterpret_cast<const uint2*>(s_sp + i4);
        float p0, p1, p2, p3;
        unpack2(u.x, p0, p1); unpack2(u.y, p2, p3);
        float e0 = __expf(p0 * sinv);
        float e1 = __expf(p1 * sinv);
        float e2 = __expf(p2 * sinv);
        float e3 = __expf(p3 * sinv);
        z += e0 + e1 + e2 + e3;
        *reinterpret_cast<uint2*>(wr + i4) =
            make_uint2(pack_bf16x2(e0, e1), pack_bf16x2(e2, e3));
    }
    red[t] = z; __syncthreads();
    for (int o = 256; o; o >>= 1) { if (t < o) red[t] += red[t+o]; __syncthreads(); }
    if (t == 0) g_wZinv[b] = 1.0f / red[0];
}

// ---------------- read_topk: one-hot gather of argmax row --------------------
__global__ void k_topk(const float* __restrict__ mem, float* __restrict__ out2) {
    int b = blockIdx.x;
    int t = threadIdx.x;
    out2[(size_t)b * DD + t] = mem[(size_t)g_argmax[b] * DD + t];
}

// ============ content GEMM (HMMA bf16, split-K over n) ======================
__global__ void __launch_bounds__(256) k_content(const float* __restrict__ mem) {
    __shared__ __align__(16) uint16_t sA[128*40], sB[32*136];
    int tid = threadIdx.x, lane = tid & 31, w = tid >> 5;
    int wm = w >> 2, wn = w & 3;
    int bm = blockIdx.x * 128, bn2 = blockIdx.y * 128, z = blockIdx.z;
    float acc[4][4][4];
    #pragma unroll
    for (int i = 0; i < 4; i++)
        #pragma unroll
        for (int j = 0; j < 4; j++)
            #pragma unroll
            for (int u = 0; u < 4; u++) acc[i][j][u] = 0.f;
    uint32_t aA = smem_u32(sA), aB = smem_u32(sB);
    int r = lane & 7, gq = lane >> 3;

    for (int it = 0; it < 32; it++) {
        int k0 = z * 1024 + it * 32;
        #pragma unroll
        for (int i = 0; i < 4; i++) {
            int idx = tid + i * 256;
            int row = idx >> 3, c2 = (idx & 7);
            *reinterpret_cast<uint2*>(&sA[row*40 + c2*4]) =
                *reinterpret_cast<const uint2*>(g_simb + (size_t)(bm + row) * NS + k0 + c2*4);
        }
        #pragma unroll
        for (int i = 0; i < 4; i++) {
            int idx = tid + i * 256;
            int row = idx >> 5, c4 = (idx & 31) * 4;
            float4 v = *reinterpret_cast<const float4*>(mem + (size_t)(k0 + row) * DD + bn2 + c4);
            *reinterpret_cast<uint2*>(&sB[row*136 + c4]) =
                make_uint2(pack_bf16x2(v.x, v.y), pack_bf16x2(v.z, v.w));
        }
        __syncthreads();
        #pragma unroll
        for (int ks = 0; ks < 2; ks++) {
            int kk = ks * 16;
            uint32_t af[4][4], bf[2][4];
            #pragma unroll
            for (int mt = 0; mt < 4; mt++) {
                int arow = wm*64 + mt*16 + r + 8*(gq & 1);
                int acol = kk + 8*(gq >> 1);
                ldsm4(af[mt], aA + (uint32_t)(arow*80 + acol*2));
            }
            #pragma unroll
            for (int np = 0; np < 2; np++) {
                int brow = kk + r + 8*(gq & 1);
                int bcol = wn*32 + np*16 + 8*(gq >> 1);
                ldsm4t(bf[np], aB + (uint32_t)(brow*272 + bcol*2));
            }
            #pragma unroll
            for (int mt = 0; mt < 4; mt++)
                #pragma unroll
                for (int nt = 0; nt < 4; nt++) {
                    int np = nt >> 1, hb = (nt & 1) * 2;
                    mma_bf16(acc[mt][nt], af[mt], bf[np][hb], bf[np][hb+1]);
                }
        }
        __syncthreads();
    }
    int g = lane >> 2, t = lane & 3;
    #pragma unroll
    for (int mt = 0; mt < 4; mt++)
        #pragma unroll
        for (int rs = 0; rs < 2; rs++) {
            int mloc = wm*64 + mt*16 + g + rs*8;
            float* dst = g_partial + ((size_t)z * NB + bm + mloc) * DD + bn2;
            #pragma unroll
            for (int nt = 0; nt < 4; nt++) {
                int off = wn*32 + nt*8 + t*2;
                *reinterpret_cast<float2*>(dst + off) =
                    make_float2(acc[mt][nt][rs*2], acc[mt][nt][rs*2+1]);
            }
        }
}

// ---------------- reduce split-K partials, scale by 1/Z ----------------------
__global__ void __launch_bounds__(256) k_reduce(float* __restrict__ out1) {
    int idx = blockIdx.x * 256 + threadIdx.x;
    int b = idx >> 8;
    float s = 0.f;
    #pragma unroll 8
    for (int z = 0; z < SPLITS; z++) s += g_partial[(size_t)z * NB * DD + idx];
    out1[idx] = s * g_cZinv[b];
}

// ======= new_mem GEMM (HMMA bf16) + fused erase ==============================
__global__ void __launch_bounds__(256) k_newmem(const float* __restrict__ mem,
                                                const float* __restrict__ value,
                                                float* __restrict__ out3) {
    __shared__ __align__(16) uint16_t sA[32*136], sB[32*136];
    __shared__ float s_red[16][128];
    __shared__ float s_zinv[NB];
    __shared__ float s_erase[128];
    int tid = threadIdx.x, lane = tid & 31, w = tid >> 5;
    int wm = w >> 2, wn = w & 3;
    int bm = blockIdx.x * 128, bn2 = blockIdx.y * 128;
    if (tid < 128) reinterpret_cast<float4*>(s_zinv)[tid] =
        reinterpret_cast<const float4*>(g_wZinv)[tid];
    float acc[4][4][4];
    #pragma unroll
    for (int i = 0; i < 4; i++)
        #pragma unroll
        for (int j = 0; j < 4; j++)
            #pragma unroll
            for (int u = 0; u < 4; u++) acc[i][j][u] = 0.f;
    float pr[8];
    #pragma unroll
    for (int j = 0; j < 8; j++) pr[j] = 1.f;
    uint32_t aA = smem_u32(sA), aB = smem_u32(sB);
    int r = lane & 7, gq = lane >> 3;
    int mc8 = (tid & 15) * 8;
    __syncthreads();

    for (int ch = 0; ch < 16; ch++) {
        int k0 = ch * 32;
        #pragma unroll
        for (int i = 0; i < 2; i++) {
            int idx = tid + i * 256;
            int row = idx >> 4;
            uint4 u = *reinterpret_cast<const uint4*>(g_wwb + (size_t)(k0 + row) * NS + bm + mc8);
            float zi = s_zinv[k0 + row];
            float f0, f1, f2, f3, f4, f5, f6, f7;
            unpack2(u.x, f0, f1); unpack2(u.y, f2, f3);
            unpack2(u.z, f4, f5); unpack2(u.w, f6, f7);
            f0 *= zi; f1 *= zi; f2 *= zi; f3 *= zi;
            f4 *= zi; f5 *= zi; f6 *= zi; f7 *= zi;
            pr[0] *= (1.f - 0.5f*f0); pr[1] *= (1.f - 0.5f*f1);
            pr[2] *= (1.f - 0.5f*f2); pr[3] *= (1.f - 0.5f*f3);
            pr[4] *= (1.f - 0.5f*f4); pr[5] *= (1.f - 0.5f*f5);
            pr[6] *= (1.f - 0.5f*f6); pr[7] *= (1.f - 0.5f*f7);
            uint4 st;
            st.x = pack_bf16x2(f0, f1); st.y = pack_bf16x2(f2, f3);
            st.z = pack_bf16x2(f4, f5); st.w = pack_bf16x2(f6, f7);
            *reinterpret_cast<uint4*>(&sA[row*136 + mc8]) = st;
        }
        #pragma unroll
        for (int i = 0; i < 4; i++) {
            int idx = tid + i * 256;
            int row = idx >> 5, c4 = (idx & 31) * 4;
            float4 v = *reinterpret_cast<const float4*>(value + (size_t)(k0 + row) * DD + bn2 + c4);
            *reinterpret_cast<uint2*>(&sB[row*136 + c4]) =
                make_uint2(pack_bf16x2(v.x, v.y), pack_bf16x2(v.z, v.w));
        }
        __syncthreads();
        #pragma unroll
        for (int ks = 0; ks < 2; ks++) {
            int kk = ks * 16;
            uint32_t af[4][4], bf[2][4];
            #pragma unroll
            for (int mt = 0; mt < 4; mt++) {
                int arow = kk + r + 8*(gq >> 1);
                int acol = wm*64 + mt*16 + 8*(gq & 1);
                ldsm4t(af[mt], aA + (uint32_t)(arow*272 + acol*2));
            }
            #pragma unroll
            for (int np = 0; np < 2; np++) {
                int brow = kk + r + 8*(gq & 1);
                int bcol = wn*32 + np*16 + 8*(gq >> 1);
                ldsm4t(bf[np], aB + (uint32_t)(brow*272 + bcol*2));
            }
            #pragma unroll
            for (int mt = 0; mt < 4; mt++)
                #pragma unroll
                for (int nt = 0; nt < 4; nt++) {
                    int np = nt >> 1, hb = (nt & 1) * 2;
                    mma_bf16(acc[mt][nt], af[mt], bf[np][hb], bf[np][hb+1]);
                }
        }
        __syncthreads();
    }
    #pragma unroll
    for (int j = 0; j < 8; j++) s_red[tid >> 4][mc8 + j] = pr[j];
    __syncthreads();
    if (tid < 128) {
        float p = 1.f;
        #pragma unroll
        for (int k = 0; k < 16; k++) p *= s_red[k][tid];
        s_erase[tid] = p;
    }
    __syncthreads();
    int g = lane >> 2, t = lane & 3;
    #pragma unroll
    for (int mt = 0; mt < 4; mt++)
        #pragma unroll
        for (int rs = 0; rs < 2; rs++) {
            int mloc = wm*64 + mt*16 + g + rs*8;
            int slot = bm + mloc;
            float er = s_erase[mloc];
            const float* mrow = mem + (size_t)slot * DD + bn2;
            float* dst = out3 + (size_t)slot * DD + bn2;
            #pragma unroll
            for (int nt = 0; nt < 4; nt++) {
                int off = wn*32 + nt*8 + t*2;
                float2 mv = *reinterpret_cast<const float2*>(mrow + off);
                *reinterpret_cast<float2*>(dst + off) =
                    make_float2(mv.x*er + acc[mt][nt][rs*2], mv.y*er + acc[mt][nt][rs*2+1]);
            }
        }
}

// ---------------- launch ----------------------------------------------------
extern "C" void kernel_launch(void* const* d_in, const int* in_sizes, int n_in,
                              void* d_out, int out_size) {
    const float* memory  = (const float*)d_in[0];
    const float* query   = (const float*)d_in[1];
    const float* value   = (const float*)d_in[2];
    const float* prev    = (const float*)d_in[3];
    const float* shiftw  = (const float*)d_in[4];

    float* out  = (float*)d_out;
    float* out1 = out;                     // read_content [512,256]
    float* out2 = out + NB * DD;           // read_topk    [512,256]
    float* out3 = out + 2 * NB * DD;       // new_mem      [65536,256]

    cudaFuncSetAttribute(k_write, cudaFuncAttributeMaxDynamicSharedMemorySize, NS * 2);

    k_norms  <<<(NS + NB) / 8, dim3(32, 8)>>>(memory, query);
    k_sim    <<<dim3(NS / 128, NB / 128), 256>>>(memory);
    k_combine<<<NB, 256>>>();
    k_argmax <<<NB, 256>>>(memory);
    k_write  <<<NB, 512, NS * 2>>>(prev, shiftw);
    k_topk   <<<NB, 256>>>(memory, out2);
    k_content<<<dim3(NB / 128, DD / 128, SPLITS), 256>>>(memory);
    k_reduce <<<(NB * DD) / 256, 256>>>(out1);
    k_newmem <<<dim3(NS / 128, DD / 128), 256>>>(memory, value, out3);
}

// round 7
// speedup vs baseline: 3.4243x; 1.1186x over previous
#include <cuda_runtime.h>
#include <cuda_bf16.h>
#include <math.h>
#include <stdint.h>

#define NB 512
#define NS 65536
#define DD 256
#define SPLITS 64
#define NBLK 512
#define WCH 8          // k_sharp chunks per row

// ---------------- scratch (device globals; no allocations allowed) ----------
__device__ __nv_bfloat16 g_simb[(size_t)NB * NS];   // 64 MB : E = exp(sim), bf16
__device__ __nv_bfloat16 g_wwb [(size_t)NB * NS];   // 64 MB : sharp (pre-normalize), bf16
__device__ __nv_bfloat16 g_memb[(size_t)NS * DD];   // 32 MB : bf16 memory
__device__ __nv_bfloat16 g_qnb [NB * DD];
__device__ __nv_bfloat16 g_valb[NB * DD];
__device__ float g_qn [NB * DD];
__device__ float g_minv[NS];
__device__ float g_pmax[(size_t)NB * NBLK];
__device__ float g_psum[(size_t)NB * NBLK];
__device__ int   g_argmax[NB];
__device__ float g_cZinv[NB];
__device__ float g_ws1[NB * WCH];
__device__ float g_ws2[NB * WCH];
__device__ float g_wsinv[NB];
__device__ float g_wZinv[NB];
__device__ float g_partial[(size_t)SPLITS * NB * DD];  // 32 MB

// ======================= helpers ============================================
__device__ __forceinline__ uint32_t smem_u32(const void* p) {
    uint32_t a;
    asm("{ .reg .u64 t; cvta.to.shared.u64 t, %1; cvt.u32.u64 %0, t; }" : "=r"(a) : "l"(p));
    return a;
}
__device__ __forceinline__ uint32_t pack_bf16x2(float lo, float hi) {
    uint32_t r;
    asm("cvt.rn.bf16x2.f32 %0, %1, %2;" : "=r"(r) : "f"(hi), "f"(lo));
    return r;
}
__device__ __forceinline__ void unpack2(uint32_t u, float& a, float& b) {
    __nv_bfloat162 h = *reinterpret_cast<__nv_bfloat162*>(&u);
    a = __bfloat162float(h.x); b = __bfloat162float(h.y);
}
__device__ __forceinline__ void ldsm4(uint32_t* r, uint32_t addr) {
    asm volatile("ldmatrix.sync.aligned.m8n8.x4.shared.b16 {%0,%1,%2,%3}, [%4];"
        : "=r"(r[0]), "=r"(r[1]), "=r"(r[2]), "=r"(r[3]) : "r"(addr));
}
__device__ __forceinline__ void ldsm4t(uint32_t* r, uint32_t addr) {
    asm volatile("ldmatrix.sync.aligned.m8n8.x4.trans.shared.b16 {%0,%1,%2,%3}, [%4];"
        : "=r"(r[0]), "=r"(r[1]), "=r"(r[2]), "=r"(r[3]) : "r"(addr));
}
__device__ __forceinline__ void mma_bf16(float* c, const uint32_t* a, uint32_t b0, uint32_t b1) {
    asm volatile("mma.sync.aligned.m16n8k16.row.col.f32.bf16.bf16.f32 "
        "{%0,%1,%2,%3}, {%4,%5,%6,%7}, {%8,%9}, {%0,%1,%2,%3};"
        : "+f"(c[0]), "+f"(c[1]), "+f"(c[2]), "+f"(c[3])
        : "r"(a[0]), "r"(a[1]), "r"(a[2]), "r"(a[3]), "r"(b0), "r"(b1));
}

// ------- norms + bf16 pre-conversion of all GEMM operands -------------------
// rows [0,NS): memory -> minv + g_memb.  [NS,NS+NB): query -> qn/qnb.
// [NS+NB, NS+2NB): value -> g_valb.
__global__ void k_norms(const float* __restrict__ mem, const float* __restrict__ q,
                        const float* __restrict__ val) {
    int lane = threadIdx.x;
    int row  = blockIdx.x * 8 + threadIdx.y;
    if (row < NS) {
        const float4* p = reinterpret_cast<const float4*>(mem + (size_t)row * DD);
        float4 v0 = p[lane];
        float4 v1 = p[lane + 32];
        float s = v0.x*v0.x + v0.y*v0.y + v0.z*v0.z + v0.w*v0.w
                + v1.x*v1.x + v1.y*v1.y + v1.z*v1.z + v1.w*v1.w;
        #pragma unroll
        for (int o = 16; o; o >>= 1) s += __shfl_xor_sync(0xffffffffu, s, o);
        if (lane == 0) g_minv[row] = 1.0f / fmaxf(sqrtf(s), 1e-12f);
        __nv_bfloat16* d = g_memb + (size_t)row * DD;
        *reinterpret_cast<uint2*>(d + lane*4) =
            make_uint2(pack_bf16x2(v0.x, v0.y), pack_bf16x2(v0.z, v0.w));
        *reinterpret_cast<uint2*>(d + 128 + lane*4) =
            make_uint2(pack_bf16x2(v1.x, v1.y), pack_bf16x2(v1.z, v1.w));
    } else if (row < NS + NB) {
        int qr = row - NS;
        const float4* p = reinterpret_cast<const float4*>(q + (size_t)qr * DD);
        float4 v0 = p[lane];
        float4 v1 = p[lane + 32];
        float s = v0.x*v0.x + v0.y*v0.y + v0.z*v0.z + v0.w*v0.w
                + v1.x*v1.x + v1.y*v1.y + v1.z*v1.z + v1.w*v1.w;
        #pragma unroll
        for (int o = 16; o; o >>= 1) s += __shfl_xor_sync(0xffffffffu, s, o);
        float inv = 1.0f / fmaxf(sqrtf(s), 1e-12f);
        v0.x *= inv; v0.y *= inv; v0.z *= inv; v0.w *= inv;
        v1.x *= inv; v1.y *= inv; v1.z *= inv; v1.w *= inv;
        float4* o4 = reinterpret_cast<float4*>(g_qn + (size_t)qr * DD);
        o4[lane] = v0; o4[lane + 32] = v1;
        __nv_bfloat16* d = g_qnb + (size_t)qr * DD;
        *reinterpret_cast<uint2*>(d + lane*4) =
            make_uint2(pack_bf16x2(v0.x, v0.y), pack_bf16x2(v0.z, v0.w));
        *reinterpret_cast<uint2*>(d + 128 + lane*4) =
            make_uint2(pack_bf16x2(v1.x, v1.y), pack_bf16x2(v1.z, v1.w));
    } else {
        int vr = row - NS - NB;
        const float4* p = reinterpret_cast<const float4*>(val + (size_t)vr * DD);
        float4 v0 = p[lane];
        float4 v1 = p[lane + 32];
        __nv_bfloat16* d = g_valb + (size_t)vr * DD;
        *reinterpret_cast<uint2*>(d + lane*4) =
            make_uint2(pack_bf16x2(v0.x, v0.y), pack_bf16x2(v0.z, v0.w));
        *reinterpret_cast<uint2*>(d + 128 + lane*4) =
            make_uint2(pack_bf16x2(v1.x, v1.y), pack_bf16x2(v1.z, v1.w));
    }
}

// ============ sim GEMM (HMMA bf16) + exp epilogue ============================
// CTA 128(b) x 128(n), K=256 in 8 chunks of 32. 8 warps = 2(m) x 4(n).
__global__ void __launch_bounds__(256) k_sim() {
    __shared__ __align__(16) uint16_t sA[128*40], sB[128*40];
    __shared__ float s_minv[128];
    int tid = threadIdx.x, lane = tid & 31, w = tid >> 5;
    int wm = w >> 2, wn = w & 3;
    int bn = blockIdx.x * 128, bm = blockIdx.y * 128;
    if (tid < 32) reinterpret_cast<float4*>(s_minv)[tid] =
        reinterpret_cast<const float4*>(g_minv + bn)[tid];

    float acc[4][4][4];
    #pragma unroll
    for (int i = 0; i < 4; i++)
        #pragma unroll
        for (int j = 0; j < 4; j++)
            #pragma unroll
            for (int u = 0; u < 4; u++) acc[i][j][u] = 0.f;

    uint32_t aA = smem_u32(sA), aB = smem_u32(sB);
    int r = lane & 7, gq = lane >> 3;

    for (int ch = 0; ch < 8; ch++) {
        int k0 = ch * 32;
        #pragma unroll
        for (int i = 0; i < 2; i++) {
            int idx = tid + i * 256;        // 512 uint4 per tile
            int row = idx >> 2, q8 = (idx & 3) * 8;
            *reinterpret_cast<uint4*>(&sA[row*40 + q8]) =
                *reinterpret_cast<const uint4*>(g_qnb + (size_t)(bm + row) * DD + k0 + q8);
            *reinterpret_cast<uint4*>(&sB[row*40 + q8]) =
                *reinterpret_cast<const uint4*>(g_memb + (size_t)(bn + row) * DD + k0 + q8);
        }
        __syncthreads();
        #pragma unroll
        for (int ks = 0; ks < 2; ks++) {
            int kk = ks * 16;
            uint32_t ah[4][4], bh[2][4];
            #pragma unroll
            for (int mt = 0; mt < 4; mt++) {
                int arow = wm*64 + mt*16 + r + 8*(gq & 1);
                int acol = kk + 8*(gq >> 1);
                ldsm4(ah[mt], aA + (uint32_t)(arow*80 + acol*2));
            }
            #pragma unroll
            for (int np = 0; np < 2; np++) {
                int brow = wn*32 + np*16 + r + 8*(gq >> 1);
                int bcol = kk + 8*(gq & 1);
                ldsm4(bh[np], aB + (uint32_t)(brow*80 + bcol*2));
            }
            #pragma unroll
            for (int mt = 0; mt < 4; mt++)
                #pragma unroll
                for (int nt = 0; nt < 4; nt++) {
                    int np = nt >> 1, hb = (nt & 1) * 2;
                    mma_bf16(acc[mt][nt], ah[mt], bh[np][hb], bh[np][hb+1]);
                }
        }
        __syncthreads();
    }

    float* s_max = reinterpret_cast<float*>(sA);
    float* s_sum = reinterpret_cast<float*>(sB);
    int g = lane >> 2, t = lane & 3;
    #pragma unroll
    for (int mt = 0; mt < 4; mt++)
        #pragma unroll
        for (int rs = 0; rs < 2; rs++) {
            int mloc = wm*64 + mt*16 + g + rs*8;
            float lm = -1e30f; float ls = 0.f;
            #pragma unroll
            for (int nt = 0; nt < 4; nt++) {
                int ncl = wn*32 + nt*8 + t*2;
                float s0 = acc[mt][nt][rs*2]   * s_minv[ncl];
                float s1 = acc[mt][nt][rs*2+1] * s_minv[ncl+1];
                lm = fmaxf(lm, fmaxf(s0, s1));
                float e0 = __expf(s0), e1 = __expf(s1);
                ls += e0 + e1;
                *reinterpret_cast<uint32_t*>(g_simb + (size_t)(bm + mloc) * NS + bn + ncl) =
                    pack_bf16x2(e0, e1);
            }
            #pragma unroll
            for (int o = 1; o < 4; o <<= 1) {
                lm = fmaxf(lm, __shfl_xor_sync(0xffffffffu, lm, o));
                ls += __shfl_xor_sync(0xffffffffu, ls, o);
            }
            if (t == 0) {
                s_max[wn*128 + mloc] = lm;
                s_sum[wn*128 + mloc] = ls;
            }
        }
    __syncthreads();
    if (tid < 128) {
        float m = s_max[tid]; float s = s_sum[tid];
        #pragma unroll
        for (int wq = 1; wq < 4; wq++) {
            m = fmaxf(m, s_max[wq*128 + tid]);
            s += s_sum[wq*128 + tid];
        }
        size_t pidx = (size_t)(bm + tid) * NBLK + blockIdx.x;
        g_pmax[pidx] = m; g_psum[pidx] = s;
    }
}

// ------- combine partials + exact argmax via block candidates ----------------
__global__ void __launch_bounds__(256) k_combine(const float* __restrict__ mem) {
    int b = blockIdx.x, t = threadIdx.x, lane = t & 31, w = t >> 5;
    size_t base = (size_t)b * NBLK;
    float p1 = g_pmax[base + t], p2 = g_pmax[base + t + 256];
    float m = fmaxf(p1, p2);
    float s = g_psum[base + t] + g_psum[base + t + 256];
    __shared__ float sm[256]; __shared__ float ss[256];
    __shared__ float s_q[DD];
    __shared__ int s_cnt, s_cand[64];
    __shared__ float s_bv[8]; __shared__ int s_bi[8];
    if (t == 0) s_cnt = 0;
    if (t < 64) reinterpret_cast<float4*>(s_q)[t] =
        reinterpret_cast<const float4*>(g_qn + (size_t)b * DD)[t];
    sm[t] = m; ss[t] = s; __syncthreads();
    for (int o = 128; o; o >>= 1) {
        if (t < o) { ss[t] += ss[t+o]; sm[t] = fmaxf(sm[t], sm[t+o]); }
        __syncthreads();
    }
    float rm = sm[0];
    if (t == 0) g_cZinv[b] = 1.0f / ss[0];
    // candidate blocks: 1-term fp32 blockmax within worst-case bf16 dot error
    float thr = rm - 8e-3f;
    if (p1 >= thr) { int p = atomicAdd(&s_cnt, 1); if (p < 64) s_cand[p] = t; }
    if (p2 >= thr) { int p = atomicAdd(&s_cnt, 1); if (p < 64) s_cand[p] = t + 256; }
    __syncthreads();
    int nc = min(s_cnt, 64);
    float bv = -1e30f; int bi = 0x7fffffff;
    for (int si = w; si < nc * 128; si += 8) {
        int n = s_cand[si >> 7] * 128 + (si & 127);
        const float* mr = mem + (size_t)n * DD;
        float d = 0.f;
        #pragma unroll
        for (int j = 0; j < 8; j += 4) {
            float4 qv = *reinterpret_cast<const float4*>(s_q + lane*8 + j);
            float4 mv = *reinterpret_cast<const float4*>(mr + lane*8 + j);
            d += qv.x*mv.x + qv.y*mv.y + qv.z*mv.z + qv.w*mv.w;
        }
        #pragma unroll
        for (int o = 16; o; o >>= 1) d += __shfl_xor_sync(0xffffffffu, d, o);
        d *= g_minv[n];
        if (lane == 0) {
            if (d > bv || (d == bv && n < bi)) { bv = d; bi = n; }
        }
    }
    if (lane == 0) { s_bv[w] = bv; s_bi[w] = bi; }
    __syncthreads();
    if (t == 0) {
        float v = s_bv[0]; int ix = s_bi[0];
        #pragma unroll
        for (int k = 1; k < 8; k++)
            if (s_bv[k] > v || (s_bv[k] == v && s_bi[k] < ix)) { v = s_bv[k]; ix = s_bi[k]; }
        g_argmax[b] = ix;
    }
}

// ------- sharp: one streaming pass, store bf16, partial S1/S2 ----------------
__global__ void __launch_bounds__(256) k_sharp(const float* __restrict__ prev,
                                               const float* __restrict__ sw) {
    int b = blockIdx.x, ch = blockIdx.y, t = threadIdx.x, lane = t & 31;
    const float* row = prev + (size_t)b * NS;
    __nv_bfloat16* wr = g_wwb + (size_t)b * NS;
    float w0 = sw[0], w1 = sw[1], w2 = sw[2];
    int base = ch * (NS / WCH);
    float s1 = 0.f, s2 = 0.f;
    #pragma unroll
    for (int it = 0; it < NS / WCH / 1024; it++) {
        int i4 = base + (it * 256 + t) * 4;
        float4 v = *reinterpret_cast<const float4*>(row + i4);
        float pl = __shfl_up_sync(0xffffffffu, v.w, 1);
        float nx = __shfl_down_sync(0xffffffffu, v.x, 1);
        if (lane == 0)  pl = (i4 > 0) ? row[i4 - 1] : 0.f;
        if (lane == 31) nx = (i4 + 4 < NS) ? row[i4 + 4] : 0.f;
        float a0 = pl*w0 + v.x*w1 + v.y*w2;
        float a1 = v.x*w0 + v.y*w1 + v.z*w2;
        float a2 = v.y*w0 + v.z*w1 + v.w*w2;
        float a3 = v.z*w0 + v.w*w1 + nx*w2;
        float p0 = a0*sqrtf(a0), p1 = a1*sqrtf(a1);
        float p2 = a2*sqrtf(a2), p3 = a3*sqrtf(a3);
        s1 += p0 + p1 + p2 + p3;
        s2 += p0*p0 + p1*p1 + p2*p2 + p3*p3;
        *reinterpret_cast<uint2*>(wr + i4) =
            make_uint2(pack_bf16x2(p0, p1), pack_bf16x2(p2, p3));
    }
    __shared__ float r1[256], r2[256];
    r1[t] = s1; r2[t] = s2; __syncthreads();
    for (int o = 128; o; o >>= 1) {
        if (t < o) { r1[t] += r1[t+o]; r2[t] += r2[t+o]; }
        __syncthreads();
    }
    if (t == 0) { g_ws1[b * WCH + ch] = r1[0]; g_ws2[b * WCH + ch] = r2[0]; }
}

// ------- per-row write-softmax constants (Taylor closed form) ----------------
__global__ void k_wcomb() {
    int b = threadIdx.x;   // 512 threads, 1 block
    float s1 = 0.f, s2 = 0.f;
    #pragma unroll
    for (int c = 0; c < WCH; c++) { s1 += g_ws1[b*WCH + c]; s2 += g_ws2[b*WCH + c]; }
    float sinv = 1.0f / (s1 + 1e-8f);
    float z = (float)NS + s1 * sinv + 0.5f * s2 * sinv * sinv;
    g_wsinv[b] = sinv;
    g_wZinv[b] = 1.0f / z;
}

// ---------------- read_topk: one-hot gather of argmax row --------------------
__global__ void k_topk(const float* __restrict__ mem, float* __restrict__ out2) {
    int b = blockIdx.x;
    int t = threadIdx.x;
    out2[(size_t)b * DD + t] = mem[(size_t)g_argmax[b] * DD + t];
}

// ============ content GEMM (HMMA bf16, split-K over n), 256-d tile ==========
__global__ void __launch_bounds__(512) k_content() {
    __shared__ __align__(16) uint16_t sA[128*40], sB[32*264];
    int tid = threadIdx.x, lane = tid & 31, w = tid >> 5;
    int wm = w >> 3, wn = w & 7;
    int bm = blockIdx.x * 128, z = blockIdx.y;
    float acc[4][4][4];
    #pragma unroll
    for (int i = 0; i < 4; i++)
        #pragma unroll
        for (int j = 0; j < 4; j++)
            #pragma unroll
            for (int u = 0; u < 4; u++) acc[i][j][u] = 0.f;
    uint32_t aA = smem_u32(sA), aB = smem_u32(sB);
    int r = lane & 7, gq = lane >> 3;

    for (int it = 0; it < 32; it++) {
        int k0 = z * 1024 + it * 32;
        {   // A: 128 x 32 bf16 = 512 uint4, one per thread
            int row = tid >> 2, q8 = (tid & 3) * 8;
            *reinterpret_cast<uint4*>(&sA[row*40 + q8]) =
                *reinterpret_cast<const uint4*>(g_simb + (size_t)(bm + row) * NS + k0 + q8);
        }
        #pragma unroll
        for (int i = 0; i < 2; i++) {   // B: 32 x 256 bf16 = 1024 uint4
            int idx = tid + i * 512;
            int row = idx >> 5, q8 = (idx & 31) * 8;
            *reinterpret_cast<uint4*>(&sB[row*264 + q8]) =
                *reinterpret_cast<const uint4*>(g_memb + (size_t)(k0 + row) * DD + q8);
        }
        __syncthreads();
        #pragma unroll
        for (int ks = 0; ks < 2; ks++) {
            int kk = ks * 16;
            uint32_t af[4][4], bf[2][4];
            #pragma unroll
            for (int mt = 0; mt < 4; mt++) {
                int arow = wm*64 + mt*16 + r + 8*(gq & 1);
                int acol = kk + 8*(gq >> 1);
                ldsm4(af[mt], aA + (uint32_t)(arow*80 + acol*2));
            }
            #pragma unroll
            for (int np = 0; np < 2; np++) {
                int brow = kk + r + 8*(gq & 1);
                int bcol = wn*32 + np*16 + 8*(gq >> 1);
                ldsm4t(bf[np], aB + (uint32_t)(brow*528 + bcol*2));
            }
            #pragma unroll
            for (int mt = 0; mt < 4; mt++)
                #pragma unroll
                for (int nt = 0; nt < 4; nt++) {
                    int np = nt >> 1, hb = (nt & 1) * 2;
                    mma_bf16(acc[mt][nt], af[mt], bf[np][hb], bf[np][hb+1]);
                }
        }
        __syncthreads();
    }
    int g = lane >> 2, tq = lane & 3;
    #pragma unroll
    for (int mt = 0; mt < 4; mt++)
        #pragma unroll
        for (int rs = 0; rs < 2; rs++) {
            int mloc = wm*64 + mt*16 + g + rs*8;
            float* dst = g_partial + ((size_t)z * NB + bm + mloc) * DD;
            #pragma unroll
            for (int nt = 0; nt < 4; nt++) {
                int off = wn*32 + nt*8 + tq*2;
                *reinterpret_cast<float2*>(dst + off) =
                    make_float2(acc[mt][nt][rs*2], acc[mt][nt][rs*2+1]);
            }
        }
}

// ---------------- reduce split-K partials, scale by 1/Z ----------------------
__global__ void __launch_bounds__(256) k_reduce(float* __restrict__ out1) {
    int idx = blockIdx.x * 256 + threadIdx.x;
    int b = idx >> 8;
    float s = 0.f;
    #pragma unroll 8
    for (int z = 0; z < SPLITS; z++) s += g_partial[(size_t)z * NB * DD + idx];
    out1[idx] = s * g_cZinv[b];
}

// ======= new_mem GEMM (HMMA bf16) + fused erase, w from sharp ===============
// CTA 128(slot) x 256(d), K=512 in 16 chunks of 32. 512 threads.
__global__ void __launch_bounds__(512) k_newmem(const float* __restrict__ mem,
                                                float* __restrict__ out3) {
    __shared__ __align__(16) uint16_t sA[32*136], sB[32*264];
    __shared__ float s_red[32][128];
    __shared__ float s_sinv[NB];
    __shared__ float s_zinv[NB];
    __shared__ float s_erase[128];
    int tid = threadIdx.x, lane = tid & 31, w = tid >> 5;
    int wm = w >> 3, wn = w & 7;
    int bm = blockIdx.x * 128;
    if (tid < 128) {
        reinterpret_cast<float4*>(s_sinv)[tid] = reinterpret_cast<const float4*>(g_wsinv)[tid];
        reinterpret_cast<float4*>(s_zinv)[tid] = reinterpret_cast<const float4*>(g_wZinv)[tid];
    }
    float acc[4][4][4];
    #pragma unroll
    for (int i = 0; i < 4; i++)
        #pragma unroll
        for (int j = 0; j < 4; j++)
            #pragma unroll
            for (int u = 0; u < 4; u++) acc[i][j][u] = 0.f;
    float pr[8];
    #pragma unroll
    for (int j = 0; j < 8; j++) pr[j] = 1.f;
    uint32_t aA = smem_u32(sA), aB = smem_u32(sB);
    int r = lane & 7, gq = lane >> 3;
    int arw = tid >> 4, ac8 = (tid & 15) * 8;   // A fill: one uint4 per thread
    __syncthreads();

    for (int ch = 0; ch < 16; ch++) {
        int k0 = ch * 32;
        {   // A: w on the fly from sharp; 32 x 128 = 512 uint4
            uint4 u = *reinterpret_cast<const uint4*>(g_wwb + (size_t)(k0 + arw) * NS + bm + ac8);
            float sv = s_sinv[k0 + arw], zv = s_zinv[k0 + arw];
            float f[8];
            unpack2(u.x, f[0], f[1]); unpack2(u.y, f[2], f[3]);
            unpack2(u.z, f[4], f[5]); unpack2(u.w, f[6], f[7]);
            uint32_t st[4];
            #pragma unroll
            for (int j = 0; j < 8; j += 2) {
                float x0 = f[j] * sv, x1 = f[j+1] * sv;
                float w0 = (1.f + x0 + 0.5f*x0*x0) * zv;
                float w1 = (1.f + x1 + 0.5f*x1*x1) * zv;
                pr[j]   *= (1.f - 0.5f*w0);
                pr[j+1] *= (1.f - 0.5f*w1);
                st[j >> 1] = pack_bf16x2(w0, w1);
            }
            *reinterpret_cast<uint4*>(&sA[arw*136 + ac8]) =
                make_uint4(st[0], st[1], st[2], st[3]);
        }
        #pragma unroll
        for (int i = 0; i < 2; i++) {   // B: value bf16 32 x 256 = 1024 uint4
            int idx = tid + i * 512;
            int row = idx >> 5, q8 = (idx & 31) * 8;
            *reinterpret_cast<uint4*>(&sB[row*264 + q8]) =
                *reinterpret_cast<const uint4*>(g_valb + (size_t)(k0 + row) * DD + q8);
        }
        __syncthreads();
        #pragma unroll
        for (int ks = 0; ks < 2; ks++) {
            int kk = ks * 16;
            uint32_t af[4][4], bf[2][4];
            #pragma unroll
            for (int mt = 0; mt < 4; mt++) {
                int arow = kk + r + 8*(gq >> 1);
                int acol = wm*64 + mt*16 + 8*(gq & 1);
                ldsm4t(af[mt], aA + (uint32_t)(arow*272 + acol*2));
            }
            #pragma unroll
            for (int np = 0; np < 2; np++) {
                int brow = kk + r + 8*(gq & 1);
                int bcol = wn*32 + np*16 + 8*(gq >> 1);
                ldsm4t(bf[np], aB + (uint32_t)(brow*528 + bcol*2));
            }
            #pragma unroll
            for (int mt = 0; mt < 4; mt++)
                #pragma unroll
                for (int nt = 0; nt < 4; nt++) {
                    int np = nt >> 1, hb = (nt & 1) * 2;
                    mma_bf16(acc[mt][nt], af[mt], bf[np][hb], bf[np][hb+1]);
                }
        }
        __syncthreads();
    }
    #pragma unroll
    for (int j = 0; j < 8; j++) s_red[arw][ac8 + j] = pr[j];
    __syncthreads();
    if (tid < 128) {
        float p = 1.f;
        #pragma unroll
        for (int k = 0; k < 32; k++) p *= s_red[k][tid];
        s_erase[tid] = p;
    }
    __syncthreads();
    int g = lane >> 2, tq = lane & 3;
    #pragma unroll
    for (int mt = 0; mt < 4; mt++)
        #pragma unroll
        for (int rs = 0; rs < 2; rs++) {
            int mloc = wm*64 + mt*16 + g + rs*8;
            int slot = bm + mloc;
            float er = s_erase[mloc];
            const float* mrow = mem + (size_t)slot * DD;
            float* dst = out3 + (size_t)slot * DD;
            #pragma unroll
            for (int nt = 0; nt < 4; nt++) {
                int off = wn*32 + nt*8 + tq*2;
                float2 mv = *reinterpret_cast<const float2*>(mrow + off);
                *reinterpret_cast<float2*>(dst + off) =
                    make_float2(mv.x*er + acc[mt][nt][rs*2], mv.y*er + acc[mt][nt][rs*2+1]);
            }
        }
}

// ---------------- launch ----------------------------------------------------
extern "C" void kernel_launch(void* const* d_in, const int* in_sizes, int n_in,
                              void* d_out, int out_size) {
    const float* memory  = (const float*)d_in[0];
    const float* query   = (const float*)d_in[1];
    const float* value   = (const float*)d_in[2];
    const float* prev    = (const float*)d_in[3];
    const float* shiftw  = (const float*)d_in[4];

    float* out  = (float*)d_out;
    float* out1 = out;                     // read_content [512,256]
    float* out2 = out + NB * DD;           // read_topk    [512,256]
    float* out3 = out + 2 * NB * DD;       // new_mem      [65536,256]

    k_norms  <<<(NS + 2*NB) / 8, dim3(32, 8)>>>(memory, query, value);
    k_sim    <<<dim3(NS / 128, NB / 128), 256>>>();
    k_combine<<<NB, 256>>>(memory);
    k_sharp  <<<dim3(NB, WCH), 256>>>(prev, shiftw);
    k_wcomb  <<<1, NB>>>();
    k_topk   <<<NB, 256>>>(memory, out2);
    k_content<<<dim3(NB / 128, SPLITS), 512>>>();
    k_reduce <<<(NB * DD) / 256, 256>>>(out1);
    k_newmem <<<NS / 128, 512>>>(memory, out3);
}

// round 8
// speedup vs baseline: 3.7725x; 1.1017x over previous
#include <cuda_runtime.h>
#include <cuda_bf16.h>
#include <math.h>
#include <stdint.h>

#define NB 512
#define NS 65536
#define DD 256
#define SPLITS 64
#define NBLK 512
#define WCH 8          // k_sharp chunks per row

// ---------------- scratch (device globals; no allocations allowed) ----------
__device__ __nv_bfloat16 g_simb[(size_t)NB * NS];   // 64 MB : E = exp(sim), bf16
__device__ __nv_bfloat16 g_wwb [(size_t)NB * NS];   // 64 MB : sharp (pre-normalize), bf16
__device__ __nv_bfloat16 g_memb[(size_t)NS * DD];   // 32 MB : bf16 memory
__device__ __nv_bfloat16 g_qnb [NB * DD];
__device__ __nv_bfloat16 g_valb[NB * DD];
__device__ float g_qn [NB * DD];
__device__ float g_minv[NS];
__device__ float g_pmax[(size_t)NB * NBLK];
__device__ float g_psum[(size_t)NB * NBLK];
__device__ int   g_argmax[NB];
__device__ float g_cZinv[NB];
__device__ float g_ws1[NB * WCH];
__device__ float g_ws2[NB * WCH];
__device__ float g_wsinv[NB];
__device__ float g_wZinv[NB];
__device__ float g_partial[(size_t)SPLITS * NB * DD];  // 32 MB

// ======================= helpers ============================================
__device__ __forceinline__ uint32_t smem_u32(const void* p) {
    uint32_t a;
    asm("{ .reg .u64 t; cvta.to.shared.u64 t, %1; cvt.u32.u64 %0, t; }" : "=r"(a) : "l"(p));
    return a;
}
__device__ __forceinline__ uint32_t pack_bf16x2(float lo, float hi) {
    uint32_t r;
    asm("cvt.rn.bf16x2.f32 %0, %1, %2;" : "=r"(r) : "f"(hi), "f"(lo));
    return r;
}
__device__ __forceinline__ void unpack2(uint32_t u, float& a, float& b) {
    __nv_bfloat162 h = *reinterpret_cast<__nv_bfloat162*>(&u);
    a = __bfloat162float(h.x); b = __bfloat162float(h.y);
}
__device__ __forceinline__ void ldsm4(uint32_t* r, uint32_t addr) {
    asm volatile("ldmatrix.sync.aligned.m8n8.x4.shared.b16 {%0,%1,%2,%3}, [%4];"
        : "=r"(r[0]), "=r"(r[1]), "=r"(r[2]), "=r"(r[3]) : "r"(addr));
}
__device__ __forceinline__ void ldsm4t(uint32_t* r, uint32_t addr) {
    asm volatile("ldmatrix.sync.aligned.m8n8.x4.trans.shared.b16 {%0,%1,%2,%3}, [%4];"
        : "=r"(r[0]), "=r"(r[1]), "=r"(r[2]), "=r"(r[3]) : "r"(addr));
}
__device__ __forceinline__ void mma_bf16(float* c, const uint32_t* a, uint32_t b0, uint32_t b1) {
    asm volatile("mma.sync.aligned.m16n8k16.row.col.f32.bf16.bf16.f32 "
        "{%0,%1,%2,%3}, {%4,%5,%6,%7}, {%8,%9}, {%0,%1,%2,%3};"
        : "+f"(c[0]), "+f"(c[1]), "+f"(c[2]), "+f"(c[3])
        : "r"(a[0]), "r"(a[1]), "r"(a[2]), "r"(a[3]), "r"(b0), "r"(b1));
}

extern __shared__ __align__(16) char dsm[];

// ------- norms + bf16 pre-conversion of all GEMM operands -------------------
__global__ void k_norms(const float* __restrict__ mem, const float* __restrict__ q,
                        const float* __restrict__ val) {
    int lane = threadIdx.x;
    int row  = blockIdx.x * 8 + threadIdx.y;
    if (row < NS) {
        const float4* p = reinterpret_cast<const float4*>(mem + (size_t)row * DD);
        float4 v0 = p[lane];
        float4 v1 = p[lane + 32];
        float s = v0.x*v0.x + v0.y*v0.y + v0.z*v0.z + v0.w*v0.w
                + v1.x*v1.x + v1.y*v1.y + v1.z*v1.z + v1.w*v1.w;
        #pragma unroll
        for (int o = 16; o; o >>= 1) s += __shfl_xor_sync(0xffffffffu, s, o);
        if (lane == 0) g_minv[row] = 1.0f / fmaxf(sqrtf(s), 1e-12f);
        __nv_bfloat16* d = g_memb + (size_t)row * DD;
        *reinterpret_cast<uint2*>(d + lane*4) =
            make_uint2(pack_bf16x2(v0.x, v0.y), pack_bf16x2(v0.z, v0.w));
        *reinterpret_cast<uint2*>(d + 128 + lane*4) =
            make_uint2(pack_bf16x2(v1.x, v1.y), pack_bf16x2(v1.z, v1.w));
    } else if (row < NS + NB) {
        int qr = row - NS;
        const float4* p = reinterpret_cast<const float4*>(q + (size_t)qr * DD);
        float4 v0 = p[lane];
        float4 v1 = p[lane + 32];
        float s = v0.x*v0.x + v0.y*v0.y + v0.z*v0.z + v0.w*v0.w
                + v1.x*v1.x + v1.y*v1.y + v1.z*v1.z + v1.w*v1.w;
        #pragma unroll
        for (int o = 16; o; o >>= 1) s += __shfl_xor_sync(0xffffffffu, s, o);
        float inv = 1.0f / fmaxf(sqrtf(s), 1e-12f);
        v0.x *= inv; v0.y *= inv; v0.z *= inv; v0.w *= inv;
        v1.x *= inv; v1.y *= inv; v1.z *= inv; v1.w *= inv;
        float4* o4 = reinterpret_cast<float4*>(g_qn + (size_t)qr * DD);
        o4[lane] = v0; o4[lane + 32] = v1;
        __nv_bfloat16* d = g_qnb + (size_t)qr * DD;
        *reinterpret_cast<uint2*>(d + lane*4) =
            make_uint2(pack_bf16x2(v0.x, v0.y), pack_bf16x2(v0.z, v0.w));
        *reinterpret_cast<uint2*>(d + 128 + lane*4) =
            make_uint2(pack_bf16x2(v1.x, v1.y), pack_bf16x2(v1.z, v1.w));
    } else {
        int vr = row - NS - NB;
        const float4* p = reinterpret_cast<const float4*>(val + (size_t)vr * DD);
        float4 v0 = p[lane];
        float4 v1 = p[lane + 32];
        __nv_bfloat16* d = g_valb + (size_t)vr * DD;
        *reinterpret_cast<uint2*>(d + lane*4) =
            make_uint2(pack_bf16x2(v0.x, v0.y), pack_bf16x2(v0.z, v0.w));
        *reinterpret_cast<uint2*>(d + 128 + lane*4) =
            make_uint2(pack_bf16x2(v1.x, v1.y), pack_bf16x2(v1.z, v1.w));
    }
}

// ============ sim GEMM (HMMA bf16, double-buffered) + exp epilogue ==========
// dsm: A0@0 A1@10240 B0@20480 B1@30720 minv@40960  => 41472 bytes
#define SIM_DSM 41472
__global__ void __launch_bounds__(256) k_sim() {
    char* pA[2] = { dsm, dsm + 10240 };
    char* pB[2] = { dsm + 20480, dsm + 30720 };
    float* s_minv = reinterpret_cast<float*>(dsm + 40960);
    int tid = threadIdx.x, lane = tid & 31, w = tid >> 5;
    int wm = w >> 2, wn = w & 3;
    int bn = blockIdx.x * 128, bm = blockIdx.y * 128;
    if (tid < 32) reinterpret_cast<float4*>(s_minv)[tid] =
        reinterpret_cast<const float4*>(g_minv + bn)[tid];

    float acc[4][4][4];
    #pragma unroll
    for (int i = 0; i < 4; i++)
        #pragma unroll
        for (int j = 0; j < 4; j++)
            #pragma unroll
            for (int u = 0; u < 4; u++) acc[i][j][u] = 0.f;

    int r = lane & 7, gq = lane >> 3;

    // prologue: fill stage 0 (chunk 0)
    #pragma unroll
    for (int i = 0; i < 2; i++) {
        int idx = tid + i * 256;
        int row = idx >> 2, q8 = (idx & 3) * 8;
        *reinterpret_cast<uint4*>(pA[0] + row*80 + q8*2) =
            *reinterpret_cast<const uint4*>(g_qnb + (size_t)(bm + row) * DD + q8);
        *reinterpret_cast<uint4*>(pB[0] + row*80 + q8*2) =
            *reinterpret_cast<const uint4*>(g_memb + (size_t)(bn + row) * DD + q8);
    }
    __syncthreads();

    uint4 pfa[2], pfb[2];
    for (int ch = 0; ch < 8; ch++) {
        int st = ch & 1;
        if (ch < 7) {
            int k0 = (ch + 1) * 32;
            #pragma unroll
            for (int i = 0; i < 2; i++) {
                int idx = tid + i * 256;
                int row = idx >> 2, q8 = (idx & 3) * 8;
                pfa[i] = *reinterpret_cast<const uint4*>(g_qnb + (size_t)(bm + row) * DD + k0 + q8);
                pfb[i] = *reinterpret_cast<const uint4*>(g_memb + (size_t)(bn + row) * DD + k0 + q8);
            }
        }
        uint32_t aA = smem_u32(pA[st]), aB = smem_u32(pB[st]);
        #pragma unroll
        for (int ks = 0; ks < 2; ks++) {
            int kk = ks * 16;
            uint32_t ah[4][4], bh[2][4];
            #pragma unroll
            for (int mt = 0; mt < 4; mt++) {
                int arow = wm*64 + mt*16 + r + 8*(gq & 1);
                int acol = kk + 8*(gq >> 1);
                ldsm4(ah[mt], aA + (uint32_t)(arow*80 + acol*2));
            }
            #pragma unroll
            for (int np = 0; np < 2; np++) {
                int brow = wn*32 + np*16 + r + 8*(gq >> 1);
                int bcol = kk + 8*(gq & 1);
                ldsm4(bh[np], aB + (uint32_t)(brow*80 + bcol*2));
            }
            #pragma unroll
            for (int mt = 0; mt < 4; mt++)
                #pragma unroll
                for (int nt = 0; nt < 4; nt++) {
                    int np = nt >> 1, hb = (nt & 1) * 2;
                    mma_bf16(acc[mt][nt], ah[mt], bh[np][hb], bh[np][hb+1]);
                }
        }
        if (ch < 7) {
            int ns = st ^ 1;
            #pragma unroll
            for (int i = 0; i < 2; i++) {
                int idx = tid + i * 256;
                int row = idx >> 2, q8 = (idx & 3) * 8;
                *reinterpret_cast<uint4*>(pA[ns] + row*80 + q8*2) = pfa[i];
                *reinterpret_cast<uint4*>(pB[ns] + row*80 + q8*2) = pfb[i];
            }
            __syncthreads();
        }
    }
    __syncthreads();

    float* s_max = reinterpret_cast<float*>(pA[0]);
    float* s_sum = reinterpret_cast<float*>(pB[0]);
    int g = lane >> 2, t = lane & 3;
    #pragma unroll
    for (int mt = 0; mt < 4; mt++)
        #pragma unroll
        for (int rs = 0; rs < 2; rs++) {
            int mloc = wm*64 + mt*16 + g + rs*8;
            float lm = -1e30f; float ls = 0.f;
            #pragma unroll
            for (int nt = 0; nt < 4; nt++) {
                int ncl = wn*32 + nt*8 + t*2;
                float s0 = acc[mt][nt][rs*2]   * s_minv[ncl];
                float s1 = acc[mt][nt][rs*2+1] * s_minv[ncl+1];
                lm = fmaxf(lm, fmaxf(s0, s1));
                float e0 = __expf(s0), e1 = __expf(s1);
                ls += e0 + e1;
                *reinterpret_cast<uint32_t*>(g_simb + (size_t)(bm + mloc) * NS + bn + ncl) =
                    pack_bf16x2(e0, e1);
            }
            #pragma unroll
            for (int o = 1; o < 4; o <<= 1) {
                lm = fmaxf(lm, __shfl_xor_sync(0xffffffffu, lm, o));
                ls += __shfl_xor_sync(0xffffffffu, ls, o);
            }
            if (t == 0) {
                s_max[wn*128 + mloc] = lm;
                s_sum[wn*128 + mloc] = ls;
            }
        }
    __syncthreads();
    if (tid < 128) {
        float m = s_max[tid]; float s = s_sum[tid];
        #pragma unroll
        for (int wq = 1; wq < 4; wq++) {
            m = fmaxf(m, s_max[wq*128 + tid]);
            s += s_sum[wq*128 + tid];
        }
        size_t pidx = (size_t)(bm + tid) * NBLK + blockIdx.x;
        g_pmax[pidx] = m; g_psum[pidx] = s;
    }
}

// ------- combine partials + exact argmax via block candidates ----------------
__global__ void __launch_bounds__(256) k_combine(const float* __restrict__ mem) {
    int b = blockIdx.x, t = threadIdx.x, lane = t & 31, w = t >> 5;
    size_t base = (size_t)b * NBLK;
    float p1 = g_pmax[base + t], p2 = g_pmax[base + t + 256];
    float m = fmaxf(p1, p2);
    float s = g_psum[base + t] + g_psum[base + t + 256];
    __shared__ float sm[256]; __shared__ float ss[256];
    __shared__ float s_q[DD];
    __shared__ int s_cnt, s_cand[64];
    __shared__ float s_bv[8]; __shared__ int s_bi[8];
    if (t == 0) s_cnt = 0;
    if (t < 64) reinterpret_cast<float4*>(s_q)[t] =
        reinterpret_cast<const float4*>(g_qn + (size_t)b * DD)[t];
    sm[t] = m; ss[t] = s; __syncthreads();
    for (int o = 128; o; o >>= 1) {
        if (t < o) { ss[t] += ss[t+o]; sm[t] = fmaxf(sm[t], sm[t+o]); }
        __syncthreads();
    }
    float rm = sm[0];
    if (t == 0) g_cZinv[b] = 1.0f / ss[0];
    float thr = rm - 8e-3f;
    if (p1 >= thr) { int p = atomicAdd(&s_cnt, 1); if (p < 64) s_cand[p] = t; }
    if (p2 >= thr) { int p = atomicAdd(&s_cnt, 1); if (p < 64) s_cand[p] = t + 256; }
    __syncthreads();
    int nc = min(s_cnt, 64);
    float bv = -1e30f; int bi = 0x7fffffff;
    for (int si = w; si < nc * 128; si += 8) {
        int n = s_cand[si >> 7] * 128 + (si & 127);
        const float* mr = mem + (size_t)n * DD;
        float d = 0.f;
        #pragma unroll
        for (int j = 0; j < 8; j += 4) {
            float4 qv = *reinterpret_cast<const float4*>(s_q + lane*8 + j);
            float4 mv = *reinterpret_cast<const float4*>(mr + lane*8 + j);
            d += qv.x*mv.x + qv.y*mv.y + qv.z*mv.z + qv.w*mv.w;
        }
        #pragma unroll
        for (int o = 16; o; o >>= 1) d += __shfl_xor_sync(0xffffffffu, d, o);
        d *= g_minv[n];
        if (lane == 0) {
            if (d > bv || (d == bv && n < bi)) { bv = d; bi = n; }
        }
    }
    if (lane == 0) { s_bv[w] = bv; s_bi[w] = bi; }
    __syncthreads();
    if (t == 0) {
        float v = s_bv[0]; int ix = s_bi[0];
        #pragma unroll
        for (int k = 1; k < 8; k++)
            if (s_bv[k] > v || (s_bv[k] == v && s_bi[k] < ix)) { v = s_bv[k]; ix = s_bi[k]; }
        g_argmax[b] = ix;
    }
}

// ------- sharp: one streaming pass, store bf16, partial S1/S2 ----------------
__global__ void __launch_bounds__(256) k_sharp(const float* __restrict__ prev,
                                               const float* __restrict__ sw) {
    int b = blockIdx.x, ch = blockIdx.y, t = threadIdx.x, lane = t & 31;
    const float* row = prev + (size_t)b * NS;
    __nv_bfloat16* wr = g_wwb + (size_t)b * NS;
    float w0 = sw[0], w1 = sw[1], w2 = sw[2];
    int base = ch * (NS / WCH);
    float s1 = 0.f, s2 = 0.f;
    #pragma unroll
    for (int it = 0; it < NS / WCH / 1024; it++) {
        int i4 = base + (it * 256 + t) * 4;
        float4 v = *reinterpret_cast<const float4*>(row + i4);
        float pl = __shfl_up_sync(0xffffffffu, v.w, 1);
        float nx = __shfl_down_sync(0xffffffffu, v.x, 1);
        if (lane == 0)  pl = (i4 > 0) ? row[i4 - 1] : 0.f;
        if (lane == 31) nx = (i4 + 4 < NS) ? row[i4 + 4] : 0.f;
        float a0 = pl*w0 + v.x*w1 + v.y*w2;
        float a1 = v.x*w0 + v.y*w1 + v.z*w2;
        float a2 = v.y*w0 + v.z*w1 + v.w*w2;
        float a3 = v.z*w0 + v.w*w1 + nx*w2;
        float p0 = a0*sqrtf(a0), p1 = a1*sqrtf(a1);
        float p2 = a2*sqrtf(a2), p3 = a3*sqrtf(a3);
        s1 += p0 + p1 + p2 + p3;
        s2 += p0*p0 + p1*p1 + p2*p2 + p3*p3;
        *reinterpret_cast<uint2*>(wr + i4) =
            make_uint2(pack_bf16x2(p0, p1), pack_bf16x2(p2, p3));
    }
    __shared__ float r1[256], r2[256];
    r1[t] = s1; r2[t] = s2; __syncthreads();
    for (int o = 128; o; o >>= 1) {
        if (t < o) { r1[t] += r1[t+o]; r2[t] += r2[t+o]; }
        __syncthreads();
    }
    if (t == 0) { g_ws1[b * WCH + ch] = r1[0]; g_ws2[b * WCH + ch] = r2[0]; }
}

// ------- per-row write-softmax constants (Taylor closed form) ----------------
__global__ void k_wcomb() {
    int b = threadIdx.x;
    float s1 = 0.f, s2 = 0.f;
    #pragma unroll
    for (int c = 0; c < WCH; c++) { s1 += g_ws1[b*WCH + c]; s2 += g_ws2[b*WCH + c]; }
    float sinv = 1.0f / (s1 + 1e-8f);
    float z = (float)NS + s1 * sinv + 0.5f * s2 * sinv * sinv;
    g_wsinv[b] = sinv;
    g_wZinv[b] = 1.0f / z;
}

// ---------------- read_topk: one-hot gather of argmax row --------------------
__global__ void k_topk(const float* __restrict__ mem, float* __restrict__ out2) {
    int b = blockIdx.x;
    int t = threadIdx.x;
    out2[(size_t)b * DD + t] = mem[(size_t)g_argmax[b] * DD + t];
}

// ============ content GEMM (HMMA bf16, split-K, double-buffered) ============
// dsm: A0@0 A1@10240 B0@20480 B1@37376  => 54272 bytes
#define CONT_DSM 54272
__global__ void __launch_bounds__(512) k_content() {
    char* pA[2] = { dsm, dsm + 10240 };
    char* pB[2] = { dsm + 20480, dsm + 37376 };
    int tid = threadIdx.x, lane = tid & 31, w = tid >> 5;
    int wm = w >> 3, wn = w & 7;
    int bm = blockIdx.x * 128, z = blockIdx.y;
    float acc[4][4][4];
    #pragma unroll
    for (int i = 0; i < 4; i++)
        #pragma unroll
        for (int j = 0; j < 4; j++)
            #pragma unroll
            for (int u = 0; u < 4; u++) acc[i][j][u] = 0.f;
    int r = lane & 7, gq = lane >> 3;
    int kbase = z * 1024;
    int arow0 = tid >> 2, aq8 = (tid & 3) * 8;   // A fill: 1 uint4/thread

    // prologue: fill stage 0
    {
        *reinterpret_cast<uint4*>(pA[0] + arow0*80 + aq8*2) =
            *reinterpret_cast<const uint4*>(g_simb + (size_t)(bm + arow0) * NS + kbase + aq8);
        #pragma unroll
        for (int i = 0; i < 2; i++) {
            int idx = tid + i * 512;
            int row = idx >> 5, q8 = (idx & 31) * 8;
            *reinterpret_cast<uint4*>(pB[0] + row*528 + q8*2) =
                *reinterpret_cast<const uint4*>(g_memb + (size_t)(kbase + row) * DD + q8);
        }
    }
    __syncthreads();

    uint4 pfa, pfb[2];
    for (int it = 0; it < 32; it++) {
        int st = it & 1;
        if (it < 31) {
            int k0 = kbase + (it + 1) * 32;
            pfa = *reinterpret_cast<const uint4*>(g_simb + (size_t)(bm + arow0) * NS + k0 + aq8);
            #pragma unroll
            for (int i = 0; i < 2; i++) {
                int idx = tid + i * 512;
                int row = idx >> 5, q8 = (idx & 31) * 8;
                pfb[i] = *reinterpret_cast<const uint4*>(g_memb + (size_t)(k0 + row) * DD + q8);
            }
        }
        uint32_t aA = smem_u32(pA[st]), aB = smem_u32(pB[st]);
        #pragma unroll
        for (int ks = 0; ks < 2; ks++) {
            int kk = ks * 16;
            uint32_t af[4][4], bf[2][4];
            #pragma unroll
            for (int mt = 0; mt < 4; mt++) {
                int arow = wm*64 + mt*16 + r + 8*(gq & 1);
                int acol = kk + 8*(gq >> 1);
                ldsm4(af[mt], aA + (uint32_t)(arow*80 + acol*2));
            }
            #pragma unroll
            for (int np = 0; np < 2; np++) {
                int brow = kk + r + 8*(gq & 1);
                int bcol = wn*32 + np*16 + 8*(gq >> 1);
                ldsm4t(bf[np], aB + (uint32_t)(brow*528 + bcol*2));
            }
            #pragma unroll
            for (int mt = 0; mt < 4; mt++)
                #pragma unroll
                for (int nt = 0; nt < 4; nt++) {
                    int np = nt >> 1, hb = (nt & 1) * 2;
                    mma_bf16(acc[mt][nt], af[mt], bf[np][hb], bf[np][hb+1]);
                }
        }
        if (it < 31) {
            int ns = st ^ 1;
            *reinterpret_cast<uint4*>(pA[ns] + arow0*80 + aq8*2) = pfa;
            #pragma unroll
            for (int i = 0; i < 2; i++) {
                int idx = tid + i * 512;
                int row = idx >> 5, q8 = (idx & 31) * 8;
                *reinterpret_cast<uint4*>(pB[ns] + row*528 + q8*2) = pfb[i];
            }
            __syncthreads();
        }
    }
    int g = lane >> 2, tq = lane & 3;
    #pragma unroll
    for (int mt = 0; mt < 4; mt++)
        #pragma unroll
        for (int rs = 0; rs < 2; rs++) {
            int mloc = wm*64 + mt*16 + g + rs*8;
            float* dst = g_partial + ((size_t)z * NB + bm + mloc) * DD;
            #pragma unroll
            for (int nt = 0; nt < 4; nt++) {
                int off = wn*32 + nt*8 + tq*2;
                *reinterpret_cast<float2*>(dst + off) =
                    make_float2(acc[mt][nt][rs*2], acc[mt][nt][rs*2+1]);
            }
        }
}

// ---------------- reduce split-K partials, scale by 1/Z ----------------------
__global__ void __launch_bounds__(256) k_reduce(float* __restrict__ out1) {
    int idx = blockIdx.x * 256 + threadIdx.x;
    int b = idx >> 8;
    float s = 0.f;
    #pragma unroll 8
    for (int z = 0; z < SPLITS; z++) s += g_partial[(size_t)z * NB * DD + idx];
    out1[idx] = s * g_cZinv[b];
}

// ======= new_mem GEMM (HMMA bf16, double-buffered) + fused erase ============
// dsm: A0@0 A1@8704 B0@17408 B1@34304 red@51200 sinv@67584 zinv@69632 erase@71680
#define NEWM_DSM 72192
__global__ void __launch_bounds__(512) k_newmem(const float* __restrict__ mem,
                                                float* __restrict__ out3) {
    char* pA[2] = { dsm, dsm + 8704 };
    char* pB[2] = { dsm + 17408, dsm + 34304 };
    float* s_red   = reinterpret_cast<float*>(dsm + 51200);   // [32][128]
    float* s_sinv  = reinterpret_cast<float*>(dsm + 67584);
    float* s_zinv  = reinterpret_cast<float*>(dsm + 69632);
    float* s_erase = reinterpret_cast<float*>(dsm + 71680);
    int tid = threadIdx.x, lane = tid & 31, w = tid >> 5;
    int wm = w >> 3, wn = w & 7;
    int bm = blockIdx.x * 128;
    if (tid < 128) {
        reinterpret_cast<float4*>(s_sinv)[tid] = reinterpret_cast<const float4*>(g_wsinv)[tid];
        reinterpret_cast<float4*>(s_zinv)[tid] = reinterpret_cast<const float4*>(g_wZinv)[tid];
    }
    float acc[4][4][4];
    #pragma unroll
    for (int i = 0; i < 4; i++)
        #pragma unroll
        for (int j = 0; j < 4; j++)
            #pragma unroll
            for (int u = 0; u < 4; u++) acc[i][j][u] = 0.f;
    float pr[8];
    #pragma unroll
    for (int j = 0; j < 8; j++) pr[j] = 1.f;
    int r = lane & 7, gq = lane >> 3;
    int arw = tid >> 4, ac8 = (tid & 15) * 8;
    __syncthreads();   // s_sinv/zinv visible

    // A convert+store helper (chunk row = k0+arw)
    auto storeA = [&](int st, int krow, uint4 u) {
        float sv = s_sinv[krow], zv = s_zinv[krow];
        float f[8];
        unpack2(u.x, f[0], f[1]); unpack2(u.y, f[2], f[3]);
        unpack2(u.z, f[4], f[5]); unpack2(u.w, f[6], f[7]);
        uint32_t stv[4];
        #pragma unroll
        for (int j = 0; j < 8; j += 2) {
            float x0 = f[j] * sv, x1 = f[j+1] * sv;
            float w0 = (1.f + x0 + 0.5f*x0*x0) * zv;
            float w1 = (1.f + x1 + 0.5f*x1*x1) * zv;
            pr[j]   *= (1.f - 0.5f*w0);
            pr[j+1] *= (1.f - 0.5f*w1);
            stv[j >> 1] = pack_bf16x2(w0, w1);
        }
        *reinterpret_cast<uint4*>(pA[st] + arw*272 + ac8*2) =
            make_uint4(stv[0], stv[1], stv[2], stv[3]);
    };

    // prologue: chunk 0
    {
        uint4 u = *reinterpret_cast<const uint4*>(g_wwb + (size_t)arw * NS + bm + ac8);
        storeA(0, arw, u);
        #pragma unroll
        for (int i = 0; i < 2; i++) {
            int idx = tid + i * 512;
            int row = idx >> 5, q8 = (idx & 31) * 8;
            *reinterpret_cast<uint4*>(pB[0] + row*528 + q8*2) =
                *reinterpret_cast<const uint4*>(g_valb + (size_t)row * DD + q8);
        }
    }
    __syncthreads();

    uint4 pfa, pfb[2];
    for (int ch = 0; ch < 16; ch++) {
        int st = ch & 1;
        if (ch < 15) {
            int k0 = (ch + 1) * 32;
            pfa = *reinterpret_cast<const uint4*>(g_wwb + (size_t)(k0 + arw) * NS + bm + ac8);
            #pragma unroll
            for (int i = 0; i < 2; i++) {
                int idx = tid + i * 512;
                int row = idx >> 5, q8 = (idx & 31) * 8;
                pfb[i] = *reinterpret_cast<const uint4*>(g_valb + (size_t)(k0 + row) * DD + q8);
            }
        }
        uint32_t aA = smem_u32(pA[st]), aB = smem_u32(pB[st]);
        #pragma unroll
        for (int ks = 0; ks < 2; ks++) {
            int kk = ks * 16;
            uint32_t af[4][4], bf[2][4];
            #pragma unroll
            for (int mt = 0; mt < 4; mt++) {
                int arow = kk + r + 8*(gq >> 1);
                int acol = wm*64 + mt*16 + 8*(gq & 1);
                ldsm4t(af[mt], aA + (uint32_t)(arow*272 + acol*2));
            }
            #pragma unroll
            for (int np = 0; np < 2; np++) {
                int brow = kk + r + 8*(gq & 1);
                int bcol = wn*32 + np*16 + 8*(gq >> 1);
                ldsm4t(bf[np], aB + (uint32_t)(brow*528 + bcol*2));
            }
            #pragma unroll
            for (int mt = 0; mt < 4; mt++)
                #pragma unroll
                for (int nt = 0; nt < 4; nt++) {
                    int np = nt >> 1, hb = (nt & 1) * 2;
                    mma_bf16(acc[mt][nt], af[mt], bf[np][hb], bf[np][hb+1]);
                }
        }
        if (ch < 15) {
            int ns = st ^ 1;
            storeA(ns, (ch + 1) * 32 + arw, pfa);
            #pragma unroll
            for (int i = 0; i < 2; i++) {
                int idx = tid + i * 512;
                int row = idx >> 5, q8 = (idx & 31) * 8;
                *reinterpret_cast<uint4*>(pB[ns] + row*528 + q8*2) = pfb[i];
            }
            __syncthreads();
        }
    }
    __syncthreads();
    #pragma unroll
    for (int j = 0; j < 8; j++) s_red[arw*128 + ac8 + j] = pr[j];
    __syncthreads();
    if (tid < 128) {
        float p = 1.f;
        #pragma unroll
        for (int k = 0; k < 32; k++) p *= s_red[k*128 + tid];
        s_erase[tid] = p;
    }
    __syncthreads();
    int g = lane >> 2, tq = lane & 3;
    #pragma unroll
    for (int mt = 0; mt < 4; mt++)
        #pragma unroll
        for (int rs = 0; rs < 2; rs++) {
            int mloc = wm*64 + mt*16 + g + rs*8;
            int slot = bm + mloc;
            float er = s_erase[mloc];
            const float* mrow = mem + (size_t)slot * DD;
            float* dst = out3 + (size_t)slot * DD;
            #pragma unroll
            for (int nt = 0; nt < 4; nt++) {
                int off = wn*32 + nt*8 + tq*2;
                float2 mv = *reinterpret_cast<const float2*>(mrow + off);
                *reinterpret_cast<float2*>(dst + off) =
                    make_float2(mv.x*er + acc[mt][nt][rs*2], mv.y*er + acc[mt][nt][rs*2+1]);
            }
        }
}

// ---------------- launch ----------------------------------------------------
extern "C" void kernel_launch(void* const* d_in, const int* in_sizes, int n_in,
                              void* d_out, int out_size) {
    const float* memory  = (const float*)d_in[0];
    const float* query   = (const float*)d_in[1];
    const float* value   = (const float*)d_in[2];
    const float* prev    = (const float*)d_in[3];
    const float* shiftw  = (const float*)d_in[4];

    float* out  = (float*)d_out;
    float* out1 = out;                     // read_content [512,256]
    float* out2 = out + NB * DD;           // read_topk    [512,256]
    float* out3 = out + 2 * NB * DD;       // new_mem      [65536,256]

    cudaFuncSetAttribute(k_sim,     cudaFuncAttributeMaxDynamicSharedMemorySize, SIM_DSM);
    cudaFuncSetAttribute(k_content, cudaFuncAttributeMaxDynamicSharedMemorySize, CONT_DSM);
    cudaFuncSetAttribute(k_newmem,  cudaFuncAttributeMaxDynamicSharedMemorySize, NEWM_DSM);

    k_norms  <<<(NS + 2*NB) / 8, dim3(32, 8)>>>(memory, query, value);
    k_sim    <<<dim3(NS / 128, NB / 128), 256, SIM_DSM>>>();
    k_combine<<<NB, 256>>>(memory);
    k_sharp  <<<dim3(NB, WCH), 256>>>(prev, shiftw);
    k_wcomb  <<<1, NB>>>();
    k_topk   <<<NB, 256>>>(memory, out2);
    k_content<<<dim3(NB / 128, SPLITS), 512, CONT_DSM>>>();
    k_reduce <<<(NB * DD) / 256, 256>>>(out1);
    k_newmem <<<NS / 128, 512, NEWM_DSM>>>(memory, out3);
}

// round 9
// speedup vs baseline: 3.8507x; 1.0207x over previous
#include <cuda_runtime.h>
#include <cuda_bf16.h>
#include <math.h>
#include <stdint.h>

#define NB 512
#define NS 65536
#define DD 256
#define SPLITS 16
#define KCHUNK (NS / SPLITS)   // 4096
#define NBLK 512
#define WCH 8          // k_sharp chunks per row

// ---------------- scratch (device globals; no allocations allowed) ----------
__device__ __nv_bfloat16 g_simb[(size_t)NB * NS];   // 64 MB : E = exp(sim), bf16
__device__ __nv_bfloat16 g_wwb [(size_t)NB * NS];   // 64 MB : sharp (pre-normalize), bf16
__device__ __nv_bfloat16 g_memb[(size_t)NS * DD];   // 32 MB : bf16 memory
__device__ __nv_bfloat16 g_qnb [NB * DD];
__device__ __nv_bfloat16 g_valb[NB * DD];
__device__ float g_qn [NB * DD];
__device__ float g_minv[NS];
__device__ float g_pmax[(size_t)NB * NBLK];
__device__ float g_psum[(size_t)NB * NBLK];
__device__ int   g_argmax[NB];
__device__ float g_cZinv[NB];
__device__ float g_ws1[NB * WCH];
__device__ float g_ws2[NB * WCH];
__device__ float g_wsinv[NB];
__device__ float g_wZinv[NB];
__device__ float g_partial[(size_t)SPLITS * NB * DD];  // 8 MB

// ======================= helpers ============================================
__device__ __forceinline__ uint32_t smem_u32(const void* p) {
    uint32_t a;
    asm("{ .reg .u64 t; cvta.to.shared.u64 t, %1; cvt.u32.u64 %0, t; }" : "=r"(a) : "l"(p));
    return a;
}
__device__ __forceinline__ uint32_t pack_bf16x2(float lo, float hi) {
    uint32_t r;
    asm("cvt.rn.bf16x2.f32 %0, %1, %2;" : "=r"(r) : "f"(hi), "f"(lo));
    return r;
}
__device__ __forceinline__ void unpack2(uint32_t u, float& a, float& b) {
    __nv_bfloat162 h = *reinterpret_cast<__nv_bfloat162*>(&u);
    a = __bfloat162float(h.x); b = __bfloat162float(h.y);
}
__device__ __forceinline__ void ldsm4(uint32_t* r, uint32_t addr) {
    asm volatile("ldmatrix.sync.aligned.m8n8.x4.shared.b16 {%0,%1,%2,%3}, [%4];"
        : "=r"(r[0]), "=r"(r[1]), "=r"(r[2]), "=r"(r[3]) : "r"(addr));
}
__device__ __forceinline__ void ldsm4t(uint32_t* r, uint32_t addr) {
    asm volatile("ldmatrix.sync.aligned.m8n8.x4.trans.shared.b16 {%0,%1,%2,%3}, [%4];"
        : "=r"(r[0]), "=r"(r[1]), "=r"(r[2]), "=r"(r[3]) : "r"(addr));
}
__device__ __forceinline__ void mma_bf16(float* c, const uint32_t* a, uint32_t b0, uint32_t b1) {
    asm volatile("mma.sync.aligned.m16n8k16.row.col.f32.bf16.bf16.f32 "
        "{%0,%1,%2,%3}, {%4,%5,%6,%7}, {%8,%9}, {%0,%1,%2,%3};"
        : "+f"(c[0]), "+f"(c[1]), "+f"(c[2]), "+f"(c[3])
        : "r"(a[0]), "r"(a[1]), "r"(a[2]), "r"(a[3]), "r"(b0), "r"(b1));
}

extern __shared__ __align__(16) char dsm[];

// ------- norms + bf16 pre-conversion of all GEMM operands -------------------
__global__ void k_norms(const float* __restrict__ mem, const float* __restrict__ q,
                        const float* __restrict__ val) {
    int lane = threadIdx.x;
    int row  = blockIdx.x * 8 + threadIdx.y;
    if (row < NS) {
        const float4* p = reinterpret_cast<const float4*>(mem + (size_t)row * DD);
        float4 v0 = p[lane];
        float4 v1 = p[lane + 32];
        float s = v0.x*v0.x + v0.y*v0.y + v0.z*v0.z + v0.w*v0.w
                + v1.x*v1.x + v1.y*v1.y + v1.z*v1.z + v1.w*v1.w;
        #pragma unroll
        for (int o = 16; o; o >>= 1) s += __shfl_xor_sync(0xffffffffu, s, o);
        if (lane == 0) g_minv[row] = 1.0f / fmaxf(sqrtf(s), 1e-12f);
        __nv_bfloat16* d = g_memb + (size_t)row * DD;
        *reinterpret_cast<uint2*>(d + lane*4) =
            make_uint2(pack_bf16x2(v0.x, v0.y), pack_bf16x2(v0.z, v0.w));
        *reinterpret_cast<uint2*>(d + 128 + lane*4) =
            make_uint2(pack_bf16x2(v1.x, v1.y), pack_bf16x2(v1.z, v1.w));
    } else if (row < NS + NB) {
        int qr = row - NS;
        const float4* p = reinterpret_cast<const float4*>(q + (size_t)qr * DD);
        float4 v0 = p[lane];
        float4 v1 = p[lane + 32];
        float s = v0.x*v0.x + v0.y*v0.y + v0.z*v0.z + v0.w*v0.w
                + v1.x*v1.x + v1.y*v1.y + v1.z*v1.z + v1.w*v1.w;
        #pragma unroll
        for (int o = 16; o; o >>= 1) s += __shfl_xor_sync(0xffffffffu, s, o);
        float inv = 1.0f / fmaxf(sqrtf(s), 1e-12f);
        v0.x *= inv; v0.y *= inv; v0.z *= inv; v0.w *= inv;
        v1.x *= inv; v1.y *= inv; v1.z *= inv; v1.w *= inv;
        float4* o4 = reinterpret_cast<float4*>(g_qn + (size_t)qr * DD);
        o4[lane] = v0; o4[lane + 32] = v1;
        __nv_bfloat16* d = g_qnb + (size_t)qr * DD;
        *reinterpret_cast<uint2*>(d + lane*4) =
            make_uint2(pack_bf16x2(v0.x, v0.y), pack_bf16x2(v0.z, v0.w));
        *reinterpret_cast<uint2*>(d + 128 + lane*4) =
            make_uint2(pack_bf16x2(v1.x, v1.y), pack_bf16x2(v1.z, v1.w));
    } else {
        int vr = row - NS - NB;
        const float4* p = reinterpret_cast<const float4*>(val + (size_t)vr * DD);
        float4 v0 = p[lane];
        float4 v1 = p[lane + 32];
        __nv_bfloat16* d = g_valb + (size_t)vr * DD;
        *reinterpret_cast<uint2*>(d + lane*4) =
            make_uint2(pack_bf16x2(v0.x, v0.y), pack_bf16x2(v0.z, v0.w));
        *reinterpret_cast<uint2*>(d + 128 + lane*4) =
            make_uint2(pack_bf16x2(v1.x, v1.y), pack_bf16x2(v1.z, v1.w));
    }
}

// ============ sim GEMM (HMMA bf16, double-buffered) + exp epilogue ==========
// dsm: A0@0 A1@10240 B0@20480 B1@30720 minv@40960  => 41472 bytes
#define SIM_DSM 41472
__global__ void __launch_bounds__(256) k_sim() {
    char* pA[2] = { dsm, dsm + 10240 };
    char* pB[2] = { dsm + 20480, dsm + 30720 };
    float* s_minv = reinterpret_cast<float*>(dsm + 40960);
    int tid = threadIdx.x, lane = tid & 31, w = tid >> 5;
    int wm = w >> 2, wn = w & 3;
    int bn = blockIdx.x * 128, bm = blockIdx.y * 128;
    if (tid < 32) reinterpret_cast<float4*>(s_minv)[tid] =
        reinterpret_cast<const float4*>(g_minv + bn)[tid];

    float acc[4][4][4];
    #pragma unroll
    for (int i = 0; i < 4; i++)
        #pragma unroll
        for (int j = 0; j < 4; j++)
            #pragma unroll
            for (int u = 0; u < 4; u++) acc[i][j][u] = 0.f;

    int r = lane & 7, gq = lane >> 3;

    #pragma unroll
    for (int i = 0; i < 2; i++) {
        int idx = tid + i * 256;
        int row = idx >> 2, q8 = (idx & 3) * 8;
        *reinterpret_cast<uint4*>(pA[0] + row*80 + q8*2) =
            *reinterpret_cast<const uint4*>(g_qnb + (size_t)(bm + row) * DD + q8);
        *reinterpret_cast<uint4*>(pB[0] + row*80 + q8*2) =
            *reinterpret_cast<const uint4*>(g_memb + (size_t)(bn + row) * DD + q8);
    }
    __syncthreads();

    uint4 pfa[2], pfb[2];
    for (int ch = 0; ch < 8; ch++) {
        int st = ch & 1;
        if (ch < 7) {
            int k0 = (ch + 1) * 32;
            #pragma unroll
            for (int i = 0; i < 2; i++) {
                int idx = tid + i * 256;
                int row = idx >> 2, q8 = (idx & 3) * 8;
                pfa[i] = *reinterpret_cast<const uint4*>(g_qnb + (size_t)(bm + row) * DD + k0 + q8);
                pfb[i] = *reinterpret_cast<const uint4*>(g_memb + (size_t)(bn + row) * DD + k0 + q8);
            }
        }
        uint32_t aA = smem_u32(pA[st]), aB = smem_u32(pB[st]);
        #pragma unroll
        for (int ks = 0; ks < 2; ks++) {
            int kk = ks * 16;
            uint32_t ah[4][4], bh[2][4];
            #pragma unroll
            for (int mt = 0; mt < 4; mt++) {
                int arow = wm*64 + mt*16 + r + 8*(gq & 1);
                int acol = kk + 8*(gq >> 1);
                ldsm4(ah[mt], aA + (uint32_t)(arow*80 + acol*2));
            }
            #pragma unroll
            for (int np = 0; np < 2; np++) {
                int brow = wn*32 + np*16 + r + 8*(gq >> 1);
                int bcol = kk + 8*(gq & 1);
                ldsm4(bh[np], aB + (uint32_t)(brow*80 + bcol*2));
            }
            #pragma unroll
            for (int mt = 0; mt < 4; mt++)
                #pragma unroll
                for (int nt = 0; nt < 4; nt++) {
                    int np = nt >> 1, hb = (nt & 1) * 2;
                    mma_bf16(acc[mt][nt], ah[mt], bh[np][hb], bh[np][hb+1]);
                }
        }
        if (ch < 7) {
            int ns = st ^ 1;
            #pragma unroll
            for (int i = 0; i < 2; i++) {
                int idx = tid + i * 256;
                int row = idx >> 2, q8 = (idx & 3) * 8;
                *reinterpret_cast<uint4*>(pA[ns] + row*80 + q8*2) = pfa[i];
                *reinterpret_cast<uint4*>(pB[ns] + row*80 + q8*2) = pfb[i];
            }
            __syncthreads();
        }
    }
    __syncthreads();

    float* s_max = reinterpret_cast<float*>(pA[0]);
    float* s_sum = reinterpret_cast<float*>(pB[0]);
    int g = lane >> 2, t = lane & 3;
    #pragma unroll
    for (int mt = 0; mt < 4; mt++)
        #pragma unroll
        for (int rs = 0; rs < 2; rs++) {
            int mloc = wm*64 + mt*16 + g + rs*8;
            float lm = -1e30f; float ls = 0.f;
            #pragma unroll
            for (int nt = 0; nt < 4; nt++) {
                int ncl = wn*32 + nt*8 + t*2;
                float s0 = acc[mt][nt][rs*2]   * s_minv[ncl];
                float s1 = acc[mt][nt][rs*2+1] * s_minv[ncl+1];
                lm = fmaxf(lm, fmaxf(s0, s1));
                float e0 = __expf(s0), e1 = __expf(s1);
                ls += e0 + e1;
                *reinterpret_cast<uint32_t*>(g_simb + (size_t)(bm + mloc) * NS + bn + ncl) =
                    pack_bf16x2(e0, e1);
            }
            #pragma unroll
            for (int o = 1; o < 4; o <<= 1) {
                lm = fmaxf(lm, __shfl_xor_sync(0xffffffffu, lm, o));
                ls += __shfl_xor_sync(0xffffffffu, ls, o);
            }
            if (t == 0) {
                s_max[wn*128 + mloc] = lm;
                s_sum[wn*128 + mloc] = ls;
            }
        }
    __syncthreads();
    if (tid < 128) {
        float m = s_max[tid]; float s = s_sum[tid];
        #pragma unroll
        for (int wq = 1; wq < 4; wq++) {
            m = fmaxf(m, s_max[wq*128 + tid]);
            s += s_sum[wq*128 + tid];
        }
        size_t pidx = (size_t)(bm + tid) * NBLK + blockIdx.x;
        g_pmax[pidx] = m; g_psum[pidx] = s;
    }
}

// ------- sharp: one streaming pass, store bf16, partial S1/S2 ----------------
__global__ void __launch_bounds__(256) k_sharp(const float* __restrict__ prev,
                                               const float* __restrict__ sw) {
    int b = blockIdx.x, ch = blockIdx.y, t = threadIdx.x, lane = t & 31;
    const float* row = prev + (size_t)b * NS;
    __nv_bfloat16* wr = g_wwb + (size_t)b * NS;
    float w0 = sw[0], w1 = sw[1], w2 = sw[2];
    int base = ch * (NS / WCH);
    float s1 = 0.f, s2 = 0.f;
    #pragma unroll
    for (int it = 0; it < NS / WCH / 1024; it++) {
        int i4 = base + (it * 256 + t) * 4;
        float4 v = *reinterpret_cast<const float4*>(row + i4);
        float pl = __shfl_up_sync(0xffffffffu, v.w, 1);
        float nx = __shfl_down_sync(0xffffffffu, v.x, 1);
        if (lane == 0)  pl = (i4 > 0) ? row[i4 - 1] : 0.f;
        if (lane == 31) nx = (i4 + 4 < NS) ? row[i4 + 4] : 0.f;
        float a0 = pl*w0 + v.x*w1 + v.y*w2;
        float a1 = v.x*w0 + v.y*w1 + v.z*w2;
        float a2 = v.y*w0 + v.z*w1 + v.w*w2;
        float a3 = v.z*w0 + v.w*w1 + nx*w2;
        float p0 = a0*sqrtf(a0), p1 = a1*sqrtf(a1);
        float p2 = a2*sqrtf(a2), p3 = a3*sqrtf(a3);
        s1 += p0 + p1 + p2 + p3;
        s2 += p0*p0 + p1*p1 + p2*p2 + p3*p3;
        *reinterpret_cast<uint2*>(wr + i4) =
            make_uint2(pack_bf16x2(p0, p1), pack_bf16x2(p2, p3));
    }
    __shared__ float r1[256], r2[256];
    r1[t] = s1; r2[t] = s2; __syncthreads();
    for (int o = 128; o; o >>= 1) {
        if (t < o) { r1[t] += r1[t+o]; r2[t] += r2[t+o]; }
        __syncthreads();
    }
    if (t == 0) { g_ws1[b * WCH + ch] = r1[0]; g_ws2[b * WCH + ch] = r2[0]; }
}

// ------- combine: softmax Z + argmax rescore + wcomb + topk gather ----------
__global__ void __launch_bounds__(256) k_combine(const float* __restrict__ mem,
                                                 float* __restrict__ out2) {
    int b = blockIdx.x, t = threadIdx.x, lane = t & 31, w = t >> 5;
    size_t base = (size_t)b * NBLK;
    float p1 = g_pmax[base + t], p2 = g_pmax[base + t + 256];
    float m = fmaxf(p1, p2);
    float s = g_psum[base + t] + g_psum[base + t + 256];
    __shared__ float sm[256]; __shared__ float ss[256];
    __shared__ float s_q[DD];
    __shared__ int s_cnt, s_cand[64];
    __shared__ float s_bv[8]; __shared__ int s_bi[8];
    __shared__ int s_arg;
    if (t == 0) s_cnt = 0;
    if (t < 64) reinterpret_cast<float4*>(s_q)[t] =
        reinterpret_cast<const float4*>(g_qn + (size_t)b * DD)[t];
    sm[t] = m; ss[t] = s; __syncthreads();
    for (int o = 128; o; o >>= 1) {
        if (t < o) { ss[t] += ss[t+o]; sm[t] = fmaxf(sm[t], sm[t+o]); }
        __syncthreads();
    }
    float rm = sm[0];
    if (t == 0) {
        g_cZinv[b] = 1.0f / ss[0];
        // wcomb (Taylor closed form for write softmax)
        float s1 = 0.f, s2 = 0.f;
        #pragma unroll
        for (int c = 0; c < WCH; c++) { s1 += g_ws1[b*WCH + c]; s2 += g_ws2[b*WCH + c]; }
        float sinv = 1.0f / (s1 + 1e-8f);
        float z = (float)NS + s1 * sinv + 0.5f * s2 * sinv * sinv;
        g_wsinv[b] = sinv;
        g_wZinv[b] = 1.0f / z;
    }
    float thr = rm - 8e-3f;
    if (p1 >= thr) { int p = atomicAdd(&s_cnt, 1); if (p < 64) s_cand[p] = t; }
    if (p2 >= thr) { int p = atomicAdd(&s_cnt, 1); if (p < 64) s_cand[p] = t + 256; }
    __syncthreads();
    int nc = min(s_cnt, 64);
    float bv = -1e30f; int bi = 0x7fffffff;
    for (int si = w; si < nc * 128; si += 8) {
        int n = s_cand[si >> 7] * 128 + (si & 127);
        const float* mr = mem + (size_t)n * DD;
        float d = 0.f;
        #pragma unroll
        for (int j = 0; j < 8; j += 4) {
            float4 qv = *reinterpret_cast<const float4*>(s_q + lane*8 + j);
            float4 mv = *reinterpret_cast<const float4*>(mr + lane*8 + j);
            d += qv.x*mv.x + qv.y*mv.y + qv.z*mv.z + qv.w*mv.w;
        }
        #pragma unroll
        for (int o = 16; o; o >>= 1) d += __shfl_xor_sync(0xffffffffu, d, o);
        d *= g_minv[n];
        if (lane == 0) {
            if (d > bv || (d == bv && n < bi)) { bv = d; bi = n; }
        }
    }
    if (lane == 0) { s_bv[w] = bv; s_bi[w] = bi; }
    __syncthreads();
    if (t == 0) {
        float v = s_bv[0]; int ix = s_bi[0];
        #pragma unroll
        for (int k = 1; k < 8; k++)
            if (s_bv[k] > v || (s_bv[k] == v && s_bi[k] < ix)) { v = s_bv[k]; ix = s_bi[k]; }
        g_argmax[b] = ix;
        s_arg = ix;
    }
    __syncthreads();
    // topk gather (one-hot row copy)
    out2[(size_t)b * DD + t] = mem[(size_t)s_arg * DD + t];
}

// ======= merged GEMM kernel: content (blocks 0..63) + newmem (64..575) ======
// dsm (max of both layouts) = 72192 bytes
#define CNM_DSM 72192
#define CONT_BLKS (4 * SPLITS)   // 64

__device__ __forceinline__ void content_body(int bx) {
    char* pA[2] = { dsm, dsm + 10240 };
    char* pB[2] = { dsm + 20480, dsm + 37376 };
    int tid = threadIdx.x, lane = tid & 31, w = tid >> 5;
    int wm = w >> 3, wn = w & 7;
    int bm = (bx & 3) * 128, z = bx >> 2;
    float acc[4][4][4];
    #pragma unroll
    for (int i = 0; i < 4; i++)
        #pragma unroll
        for (int j = 0; j < 4; j++)
            #pragma unroll
            for (int u = 0; u < 4; u++) acc[i][j][u] = 0.f;
    int r = lane & 7, gq = lane >> 3;
    int kbase = z * KCHUNK;
    int arow0 = tid >> 2, aq8 = (tid & 3) * 8;

    {
        *reinterpret_cast<uint4*>(pA[0] + arow0*80 + aq8*2) =
            *reinterpret_cast<const uint4*>(g_simb + (size_t)(bm + arow0) * NS + kbase + aq8);
        #pragma unroll
        for (int i = 0; i < 2; i++) {
            int idx = tid + i * 512;
            int row = idx >> 5, q8 = (idx & 31) * 8;
            *reinterpret_cast<uint4*>(pB[0] + row*528 + q8*2) =
                *reinterpret_cast<const uint4*>(g_memb + (size_t)(kbase + row) * DD + q8);
        }
    }
    __syncthreads();

    uint4 pfa, pfb[2];
    for (int it = 0; it < KCHUNK / 32; it++) {
        int st = it & 1;
        if (it < KCHUNK / 32 - 1) {
            int k0 = kbase + (it + 1) * 32;
            pfa = *reinterpret_cast<const uint4*>(g_simb + (size_t)(bm + arow0) * NS + k0 + aq8);
            #pragma unroll
            for (int i = 0; i < 2; i++) {
                int idx = tid + i * 512;
                int row = idx >> 5, q8 = (idx & 31) * 8;
                pfb[i] = *reinterpret_cast<const uint4*>(g_memb + (size_t)(k0 + row) * DD + q8);
            }
        }
        uint32_t aA = smem_u32(pA[st]), aB = smem_u32(pB[st]);
        #pragma unroll
        for (int ks = 0; ks < 2; ks++) {
            int kk = ks * 16;
            uint32_t af[4][4], bf[2][4];
            #pragma unroll
            for (int mt = 0; mt < 4; mt++) {
                int arow = wm*64 + mt*16 + r + 8*(gq & 1);
                int acol = kk + 8*(gq >> 1);
                ldsm4(af[mt], aA + (uint32_t)(arow*80 + acol*2));
            }
            #pragma unroll
            for (int np = 0; np < 2; np++) {
                int brow = kk + r + 8*(gq & 1);
                int bcol = wn*32 + np*16 + 8*(gq >> 1);
                ldsm4t(bf[np], aB + (uint32_t)(brow*528 + bcol*2));
            }
            #pragma unroll
            for (int mt = 0; mt < 4; mt++)
                #pragma unroll
                for (int nt = 0; nt < 4; nt++) {
                    int np = nt >> 1, hb = (nt & 1) * 2;
                    mma_bf16(acc[mt][nt], af[mt], bf[np][hb], bf[np][hb+1]);
                }
        }
        if (it < KCHUNK / 32 - 1) {
            int ns = st ^ 1;
            *reinterpret_cast<uint4*>(pA[ns] + arow0*80 + aq8*2) = pfa;
            #pragma unroll
            for (int i = 0; i < 2; i++) {
                int idx = tid + i * 512;
                int row = idx >> 5, q8 = (idx & 31) * 8;
                *reinterpret_cast<uint4*>(pB[ns] + row*528 + q8*2) = pfb[i];
            }
            __syncthreads();
        }
    }
    int g = lane >> 2, tq = lane & 3;
    #pragma unroll
    for (int mt = 0; mt < 4; mt++)
        #pragma unroll
        for (int rs = 0; rs < 2; rs++) {
            int mloc = wm*64 + mt*16 + g + rs*8;
            float* dst = g_partial + ((size_t)z * NB + bm + mloc) * DD;
            #pragma unroll
            for (int nt = 0; nt < 4; nt++) {
                int off = wn*32 + nt*8 + tq*2;
                *reinterpret_cast<float2*>(dst + off) =
                    make_float2(acc[mt][nt][rs*2], acc[mt][nt][rs*2+1]);
            }
        }
}

__device__ __forceinline__ void newmem_body(int bx, const float* __restrict__ mem,
                                            float* __restrict__ out3) {
    char* pA[2] = { dsm, dsm + 8704 };
    char* pB[2] = { dsm + 17408, dsm + 34304 };
    float* s_red   = reinterpret_cast<float*>(dsm + 51200);   // [32][128]
    float* s_sinv  = reinterpret_cast<float*>(dsm + 67584);
    float* s_zinv  = reinterpret_cast<float*>(dsm + 69632);
    float* s_erase = reinterpret_cast<float*>(dsm + 71680);
    int tid = threadIdx.x, lane = tid & 31, w = tid >> 5;
    int wm = w >> 3, wn = w & 7;
    int bm = bx * 128;
    if (tid < 128) {
        reinterpret_cast<float4*>(s_sinv)[tid] = reinterpret_cast<const float4*>(g_wsinv)[tid];
        reinterpret_cast<float4*>(s_zinv)[tid] = reinterpret_cast<const float4*>(g_wZinv)[tid];
    }
    float acc[4][4][4];
    #pragma unroll
    for (int i = 0; i < 4; i++)
        #pragma unroll
        for (int j = 0; j < 4; j++)
            #pragma unroll
            for (int u = 0; u < 4; u++) acc[i][j][u] = 0.f;
    float pr[8];
    #pragma unroll
    for (int j = 0; j < 8; j++) pr[j] = 1.f;
    int r = lane & 7, gq = lane >> 3;
    int arw = tid >> 4, ac8 = (tid & 15) * 8;
    __syncthreads();

    auto storeA = [&](int st, int krow, uint4 u) {
        float sv = s_sinv[krow], zv = s_zinv[krow];
        float f[8];
        unpack2(u.x, f[0], f[1]); unpack2(u.y, f[2], f[3]);
        unpack2(u.z, f[4], f[5]); unpack2(u.w, f[6], f[7]);
        uint32_t stv[4];
        #pragma unroll
        for (int j = 0; j < 8; j += 2) {
            float x0 = f[j] * sv, x1 = f[j+1] * sv;
            float w0 = (1.f + x0 + 0.5f*x0*x0) * zv;
            float w1 = (1.f + x1 + 0.5f*x1*x1) * zv;
            pr[j]   *= (1.f - 0.5f*w0);
            pr[j+1] *= (1.f - 0.5f*w1);
            stv[j >> 1] = pack_bf16x2(w0, w1);
        }
        *reinterpret_cast<uint4*>(pA[st] + arw*272 + ac8*2) =
            make_uint4(stv[0], stv[1], stv[2], stv[3]);
    };

    {
        uint4 u = *reinterpret_cast<const uint4*>(g_wwb + (size_t)arw * NS + bm + ac8);
        storeA(0, arw, u);
        #pragma unroll
        for (int i = 0; i < 2; i++) {
            int idx = tid + i * 512;
            int row = idx >> 5, q8 = (idx & 31) * 8;
            *reinterpret_cast<uint4*>(pB[0] + row*528 + q8*2) =
                *reinterpret_cast<const uint4*>(g_valb + (size_t)row * DD + q8);
        }
    }
    __syncthreads();

    uint4 pfa, pfb[2];
    for (int ch = 0; ch < 16; ch++) {
        int st = ch & 1;
        if (ch < 15) {
            int k0 = (ch + 1) * 32;
            pfa = *reinterpret_cast<const uint4*>(g_wwb + (size_t)(k0 + arw) * NS + bm + ac8);
            #pragma unroll
            for (int i = 0; i < 2; i++) {
                int idx = tid + i * 512;
                int row = idx >> 5, q8 = (idx & 31) * 8;
                pfb[i] = *reinterpret_cast<const uint4*>(g_valb + (size_t)(k0 + row) * DD + q8);
            }
        }
        uint32_t aA = smem_u32(pA[st]), aB = smem_u32(pB[st]);
        #pragma unroll
        for (int ks = 0; ks < 2; ks++) {
            int kk = ks * 16;
            uint32_t af[4][4], bf[2][4];
            #pragma unroll
            for (int mt = 0; mt < 4; mt++) {
                int arow = kk + r + 8*(gq >> 1);
                int acol = wm*64 + mt*16 + 8*(gq & 1);
                ldsm4t(af[mt], aA + (uint32_t)(arow*272 + acol*2));
            }
            #pragma unroll
            for (int np = 0; np < 2; np++) {
                int brow = kk + r + 8*(gq & 1);
                int bcol = wn*32 + np*16 + 8*(gq >> 1);
                ldsm4t(bf[np], aB + (uint32_t)(brow*528 + bcol*2));
            }
            #pragma unroll
            for (int mt = 0; mt < 4; mt++)
                #pragma unroll
                for (int nt = 0; nt < 4; nt++) {
                    int np = nt >> 1, hb = (nt & 1) * 2;
                    mma_bf16(acc[mt][nt], af[mt], bf[np][hb], bf[np][hb+1]);
                }
        }
        if (ch < 15) {
            int ns = st ^ 1;
            storeA(ns, (ch + 1) * 32 + arw, pfa);
            #pragma unroll
            for (int i = 0; i < 2; i++) {
                int idx = tid + i * 512;
                int row = idx >> 5, q8 = (idx & 31) * 8;
                *reinterpret_cast<uint4*>(pB[ns] + row*528 + q8*2) = pfb[i];
            }
            __syncthreads();
        }
    }
    __syncthreads();
    #pragma unroll
    for (int j = 0; j < 8; j++) s_red[arw*128 + ac8 + j] = pr[j];
    __syncthreads();
    if (tid < 128) {
        float p = 1.f;
        #pragma unroll
        for (int k = 0; k < 32; k++) p *= s_red[k*128 + tid];
        s_erase[tid] = p;
    }
    __syncthreads();
    int g = lane >> 2, tq = lane & 3;
    #pragma unroll
    for (int mt = 0; mt < 4; mt++)
        #pragma unroll
        for (int rs = 0; rs < 2; rs++) {
            int mloc = wm*64 + mt*16 + g + rs*8;
            int slot = bm + mloc;
            float er = s_erase[mloc];
            const float* mrow = mem + (size_t)slot * DD;
            float* dst = out3 + (size_t)slot * DD;
            #pragma unroll
            for (int nt = 0; nt < 4; nt++) {
                int off = wn*32 + nt*8 + tq*2;
                float2 mv = *reinterpret_cast<const float2*>(mrow + off);
                *reinterpret_cast<float2*>(dst + off) =
                    make_float2(mv.x*er + acc[mt][nt][rs*2], mv.y*er + acc[mt][nt][rs*2+1]);
            }
        }
}

__global__ void __launch_bounds__(512) k_cnm(const float* __restrict__ mem,
                                             float* __restrict__ out3) {
    if (blockIdx.x < CONT_BLKS) content_body(blockIdx.x);
    else                        newmem_body(blockIdx.x - CONT_BLKS, mem, out3);
}

// ---------------- reduce split-K partials, scale by 1/Z ----------------------
__global__ void __launch_bounds__(256) k_reduce(float* __restrict__ out1) {
    int idx = blockIdx.x * 256 + threadIdx.x;
    int b = idx >> 8;
    float s = 0.f;
    #pragma unroll
    for (int z = 0; z < SPLITS; z++) s += g_partial[(size_t)z * NB * DD + idx];
    out1[idx] = s * g_cZinv[b];
}

// ---------------- launch ----------------------------------------------------
extern "C" void kernel_launch(void* const* d_in, const int* in_sizes, int n_in,
                              void* d_out, int out_size) {
    const float* memory  = (const float*)d_in[0];
    const float* query   = (const float*)d_in[1];
    const float* value   = (const float*)d_in[2];
    const float* prev    = (const float*)d_in[3];
    const float* shiftw  = (const float*)d_in[4];

    float* out  = (float*)d_out;
    float* out1 = out;                     // read_content [512,256]
    float* out2 = out + NB * DD;           // read_topk    [512,256]
    float* out3 = out + 2 * NB * DD;       // new_mem      [65536,256]

    cudaFuncSetAttribute(k_sim, cudaFuncAttributeMaxDynamicSharedMemorySize, SIM_DSM);
    cudaFuncSetAttribute(k_cnm, cudaFuncAttributeMaxDynamicSharedMemorySize, CNM_DSM);

    k_norms  <<<(NS + 2*NB) / 8, dim3(32, 8)>>>(memory, query, value);
    k_sim    <<<dim3(NS / 128, NB / 128), 256, SIM_DSM>>>();
    k_sharp  <<<dim3(NB, WCH), 256>>>(prev, shiftw);
    k_combine<<<NB, 256>>>(memory, out2);
    k_cnm    <<<CONT_BLKS + NS / 128, 512, CNM_DSM>>>(memory, out3);
    k_reduce <<<(NB * DD) / 256, 256>>>(out1);
}

// round 10
// speedup vs baseline: 4.6442x; 1.2061x over previous
#include <cuda_runtime.h>
#include <cuda_bf16.h>
#include <math.h>
#include <stdint.h>

#define NB 512
#define NS 65536
#define DD 256
#define SPLITS 16
#define KCHUNK (NS / SPLITS)   // 4096
#define NBLK 512
#define WCH 8          // k_sharp chunks per row

// ---------------- scratch (device globals; no allocations allowed) ----------
__device__ __nv_bfloat16 g_simb[(size_t)NB * NS];   // 64 MB : E = exp(sim), bf16
__device__ __nv_bfloat16 g_wwb [(size_t)NB * NS];   // 64 MB : sharp (pre-normalize), bf16
__device__ __nv_bfloat16 g_memb[(size_t)NS * DD];   // 32 MB : bf16 memory
__device__ __nv_bfloat16 g_qnb [NB * DD];
__device__ __nv_bfloat16 g_valb[NB * DD];
__device__ float g_qn [NB * DD];
__device__ float g_minv[NS];
__device__ float g_pmax[(size_t)NB * NBLK];
__device__ float g_psum[(size_t)NB * NBLK];
__device__ int   g_argmax[NB];
__device__ float g_cZinv[NB];
__device__ float g_ws1[NB * WCH];
__device__ float g_ws2[NB * WCH];
__device__ float g_wsinv[NB];
__device__ float g_wZinv[NB];
__device__ float g_partial[(size_t)SPLITS * NB * DD];  // 8 MB

// ======================= helpers ============================================
__device__ __forceinline__ uint32_t smem_u32(const void* p) {
    uint32_t a;
    asm("{ .reg .u64 t; cvta.to.shared.u64 t, %1; cvt.u32.u64 %0, t; }" : "=r"(a) : "l"(p));
    return a;
}
__device__ __forceinline__ uint32_t pack_bf16x2(float lo, float hi) {
    uint32_t r;
    asm("cvt.rn.bf16x2.f32 %0, %1, %2;" : "=r"(r) : "f"(hi), "f"(lo));
    return r;
}
__device__ __forceinline__ void unpack2(uint32_t u, float& a, float& b) {
    __nv_bfloat162 h = *reinterpret_cast<__nv_bfloat162*>(&u);
    a = __bfloat162float(h.x); b = __bfloat162float(h.y);
}
__device__ __forceinline__ void ldsm4(uint32_t* r, uint32_t addr) {
    asm volatile("ldmatrix.sync.aligned.m8n8.x4.shared.b16 {%0,%1,%2,%3}, [%4];"
        : "=r"(r[0]), "=r"(r[1]), "=r"(r[2]), "=r"(r[3]) : "r"(addr));
}
__device__ __forceinline__ void ldsm4t(uint32_t* r, uint32_t addr) {
    asm volatile("ldmatrix.sync.aligned.m8n8.x4.trans.shared.b16 {%0,%1,%2,%3}, [%4];"
        : "=r"(r[0]), "=r"(r[1]), "=r"(r[2]), "=r"(r[3]) : "r"(addr));
}
__device__ __forceinline__ void mma_bf16(float* c, const uint32_t* a, uint32_t b0, uint32_t b1) {
    asm volatile("mma.sync.aligned.m16n8k16.row.col.f32.bf16.bf16.f32 "
        "{%0,%1,%2,%3}, {%4,%5,%6,%7}, {%8,%9}, {%0,%1,%2,%3};"
        : "+f"(c[0]), "+f"(c[1]), "+f"(c[2]), "+f"(c[3])
        : "r"(a[0]), "r"(a[1]), "r"(a[2]), "r"(a[3]), "r"(b0), "r"(b1));
}

extern __shared__ __align__(16) char dsm[];

// ------- norms + bf16 pre-conversion of all GEMM operands -------------------
__global__ void k_norms(const float* __restrict__ mem, const float* __restrict__ q,
                        const float* __restrict__ val) {
    int lane = threadIdx.x;
    int row  = blockIdx.x * 8 + threadIdx.y;
    if (row < NS) {
        const float4* p = reinterpret_cast<const float4*>(mem + (size_t)row * DD);
        float4 v0 = p[lane];
        float4 v1 = p[lane + 32];
        float s = v0.x*v0.x + v0.y*v0.y + v0.z*v0.z + v0.w*v0.w
                + v1.x*v1.x + v1.y*v1.y + v1.z*v1.z + v1.w*v1.w;
        #pragma unroll
        for (int o = 16; o; o >>= 1) s += __shfl_xor_sync(0xffffffffu, s, o);
        if (lane == 0) g_minv[row] = 1.0f / fmaxf(sqrtf(s), 1e-12f);
        __nv_bfloat16* d = g_memb + (size_t)row * DD;
        *reinterpret_cast<uint2*>(d + lane*4) =
            make_uint2(pack_bf16x2(v0.x, v0.y), pack_bf16x2(v0.z, v0.w));
        *reinterpret_cast<uint2*>(d + 128 + lane*4) =
            make_uint2(pack_bf16x2(v1.x, v1.y), pack_bf16x2(v1.z, v1.w));
    } else if (row < NS + NB) {
        int qr = row - NS;
        const float4* p = reinterpret_cast<const float4*>(q + (size_t)qr * DD);
        float4 v0 = p[lane];
        float4 v1 = p[lane + 32];
        float s = v0.x*v0.x + v0.y*v0.y + v0.z*v0.z + v0.w*v0.w
                + v1.x*v1.x + v1.y*v1.y + v1.z*v1.z + v1.w*v1.w;
        #pragma unroll
        for (int o = 16; o; o >>= 1) s += __shfl_xor_sync(0xffffffffu, s, o);
        float inv = 1.0f / fmaxf(sqrtf(s), 1e-12f);
        v0.x *= inv; v0.y *= inv; v0.z *= inv; v0.w *= inv;
        v1.x *= inv; v1.y *= inv; v1.z *= inv; v1.w *= inv;
        float4* o4 = reinterpret_cast<float4*>(g_qn + (size_t)qr * DD);
        o4[lane] = v0; o4[lane + 32] = v1;
        __nv_bfloat16* d = g_qnb + (size_t)qr * DD;
        *reinterpret_cast<uint2*>(d + lane*4) =
            make_uint2(pack_bf16x2(v0.x, v0.y), pack_bf16x2(v0.z, v0.w));
        *reinterpret_cast<uint2*>(d + 128 + lane*4) =
            make_uint2(pack_bf16x2(v1.x, v1.y), pack_bf16x2(v1.z, v1.w));
    } else {
        int vr = row - NS - NB;
        const float4* p = reinterpret_cast<const float4*>(val + (size_t)vr * DD);
        float4 v0 = p[lane];
        float4 v1 = p[lane + 32];
        __nv_bfloat16* d = g_valb + (size_t)vr * DD;
        *reinterpret_cast<uint2*>(d + lane*4) =
            make_uint2(pack_bf16x2(v0.x, v0.y), pack_bf16x2(v0.z, v0.w));
        *reinterpret_cast<uint2*>(d + 128 + lane*4) =
            make_uint2(pack_bf16x2(v1.x, v1.y), pack_bf16x2(v1.z, v1.w));
    }
}

// ============ sim GEMM (HMMA bf16, double-buffered) + exp epilogue ==========
// dsm: A0@0 A1@10240 B0@20480 B1@30720 minv@40960  => 41472 bytes
#define SIM_DSM 41472
__global__ void __launch_bounds__(256) k_sim() {
    char* pA[2] = { dsm, dsm + 10240 };
    char* pB[2] = { dsm + 20480, dsm + 30720 };
    float* s_minv = reinterpret_cast<float*>(dsm + 40960);
    int tid = threadIdx.x, lane = tid & 31, w = tid >> 5;
    int wm = w >> 2, wn = w & 3;
    int bn = blockIdx.x * 128, bm = blockIdx.y * 128;
    if (tid < 32) reinterpret_cast<float4*>(s_minv)[tid] =
        reinterpret_cast<const float4*>(g_minv + bn)[tid];

    float acc[4][4][4];
    #pragma unroll
    for (int i = 0; i < 4; i++)
        #pragma unroll
        for (int j = 0; j < 4; j++)
            #pragma unroll
            for (int u = 0; u < 4; u++) acc[i][j][u] = 0.f;

    int r = lane & 7, gq = lane >> 3;

    #pragma unroll
    for (int i = 0; i < 2; i++) {
        int idx = tid + i * 256;
        int row = idx >> 2, q8 = (idx & 3) * 8;
        *reinterpret_cast<uint4*>(pA[0] + row*80 + q8*2) =
            *reinterpret_cast<const uint4*>(g_qnb + (size_t)(bm + row) * DD + q8);
        *reinterpret_cast<uint4*>(pB[0] + row*80 + q8*2) =
            *reinterpret_cast<const uint4*>(g_memb + (size_t)(bn + row) * DD + q8);
    }
    __syncthreads();

    uint4 pfa[2], pfb[2];
    for (int ch = 0; ch < 8; ch++) {
        int st = ch & 1;
        if (ch < 7) {
            int k0 = (ch + 1) * 32;
            #pragma unroll
            for (int i = 0; i < 2; i++) {
                int idx = tid + i * 256;
                int row = idx >> 2, q8 = (idx & 3) * 8;
                pfa[i] = *reinterpret_cast<const uint4*>(g_qnb + (size_t)(bm + row) * DD + k0 + q8);
                pfb[i] = *reinterpret_cast<const uint4*>(g_memb + (size_t)(bn + row) * DD + k0 + q8);
            }
        }
        uint32_t aA = smem_u32(pA[st]), aB = smem_u32(pB[st]);
        #pragma unroll
        for (int ks = 0; ks < 2; ks++) {
            int kk = ks * 16;
            uint32_t ah[4][4], bh[2][4];
            #pragma unroll
            for (int mt = 0; mt < 4; mt++) {
                int arow = wm*64 + mt*16 + r + 8*(gq & 1);
                int acol = kk + 8*(gq >> 1);
                ldsm4(ah[mt], aA + (uint32_t)(arow*80 + acol*2));
            }
            #pragma unroll
            for (int np = 0; np < 2; np++) {
                int brow = wn*32 + np*16 + r + 8*(gq >> 1);
                int bcol = kk + 8*(gq & 1);
                ldsm4(bh[np], aB + (uint32_t)(brow*80 + bcol*2));
            }
            #pragma unroll
            for (int mt = 0; mt < 4; mt++)
                #pragma unroll
                for (int nt = 0; nt < 4; nt++) {
                    int np = nt >> 1, hb = (nt & 1) * 2;
                    mma_bf16(acc[mt][nt], ah[mt], bh[np][hb], bh[np][hb+1]);
                }
        }
        if (ch < 7) {
            int ns = st ^ 1;
            #pragma unroll
            for (int i = 0; i < 2; i++) {
                int idx = tid + i * 256;
                int row = idx >> 2, q8 = (idx & 3) * 8;
                *reinterpret_cast<uint4*>(pA[ns] + row*80 + q8*2) = pfa[i];
                *reinterpret_cast<uint4*>(pB[ns] + row*80 + q8*2) = pfb[i];
            }
            __syncthreads();
        }
    }
    __syncthreads();

    float* s_max = reinterpret_cast<float*>(pA[0]);
    float* s_sum = reinterpret_cast<float*>(pB[0]);
    int g = lane >> 2, t = lane & 3;
    #pragma unroll
    for (int mt = 0; mt < 4; mt++)
        #pragma unroll
        for (int rs = 0; rs < 2; rs++) {
            int mloc = wm*64 + mt*16 + g + rs*8;
            float lm = -1e30f; float ls = 0.f;
            #pragma unroll
            for (int nt = 0; nt < 4; nt++) {
                int ncl = wn*32 + nt*8 + t*2;
                float s0 = acc[mt][nt][rs*2]   * s_minv[ncl];
                float s1 = acc[mt][nt][rs*2+1] * s_minv[ncl+1];
                lm = fmaxf(lm, fmaxf(s0, s1));
                float e0 = __expf(s0), e1 = __expf(s1);
                ls += e0 + e1;
                *reinterpret_cast<uint32_t*>(g_simb + (size_t)(bm + mloc) * NS + bn + ncl) =
                    pack_bf16x2(e0, e1);
            }
            #pragma unroll
            for (int o = 1; o < 4; o <<= 1) {
                lm = fmaxf(lm, __shfl_xor_sync(0xffffffffu, lm, o));
                ls += __shfl_xor_sync(0xffffffffu, ls, o);
            }
            if (t == 0) {
                s_max[wn*128 + mloc] = lm;
                s_sum[wn*128 + mloc] = ls;
            }
        }
    __syncthreads();
    if (tid < 128) {
        float m = s_max[tid]; float s = s_sum[tid];
        #pragma unroll
        for (int wq = 1; wq < 4; wq++) {
            m = fmaxf(m, s_max[wq*128 + tid]);
            s += s_sum[wq*128 + tid];
        }
        size_t pidx = (size_t)(bm + tid) * NBLK + blockIdx.x;
        g_pmax[pidx] = m; g_psum[pidx] = s;
    }
}

// ------- sharp: one streaming pass, store bf16, partial S1/S2 ----------------
__global__ void __launch_bounds__(256) k_sharp(const float* __restrict__ prev,
                                               const float* __restrict__ sw) {
    int b = blockIdx.x, ch = blockIdx.y, t = threadIdx.x, lane = t & 31;
    const float* row = prev + (size_t)b * NS;
    __nv_bfloat16* wr = g_wwb + (size_t)b * NS;
    float w0 = sw[0], w1 = sw[1], w2 = sw[2];
    int base = ch * (NS / WCH);
    float s1 = 0.f, s2 = 0.f;
    #pragma unroll
    for (int it = 0; it < NS / WCH / 1024; it++) {
        int i4 = base + (it * 256 + t) * 4;
        float4 v = *reinterpret_cast<const float4*>(row + i4);
        float pl = __shfl_up_sync(0xffffffffu, v.w, 1);
        float nx = __shfl_down_sync(0xffffffffu, v.x, 1);
        if (lane == 0)  pl = (i4 > 0) ? row[i4 - 1] : 0.f;
        if (lane == 31) nx = (i4 + 4 < NS) ? row[i4 + 4] : 0.f;
        float a0 = pl*w0 + v.x*w1 + v.y*w2;
        float a1 = v.x*w0 + v.y*w1 + v.z*w2;
        float a2 = v.y*w0 + v.z*w1 + v.w*w2;
        float a3 = v.z*w0 + v.w*w1 + nx*w2;
        float p0 = a0*sqrtf(a0), p1 = a1*sqrtf(a1);
        float p2 = a2*sqrtf(a2), p3 = a3*sqrtf(a3);
        s1 += p0 + p1 + p2 + p3;
        s2 += p0*p0 + p1*p1 + p2*p2 + p3*p3;
        *reinterpret_cast<uint2*>(wr + i4) =
            make_uint2(pack_bf16x2(p0, p1), pack_bf16x2(p2, p3));
    }
    __shared__ float r1[256], r2[256];
    r1[t] = s1; r2[t] = s2; __syncthreads();
    for (int o = 128; o; o >>= 1) {
        if (t < o) { r1[t] += r1[t+o]; r2[t] += r2[t+o]; }
        __syncthreads();
    }
    if (t == 0) { g_ws1[b * WCH + ch] = r1[0]; g_ws2[b * WCH + ch] = r2[0]; }
}

// ------- combine: Z + two-stage argmax (block -> slot via E) + wcomb + topk --
__global__ void __launch_bounds__(256) k_combine(const float* __restrict__ mem,
                                                 float* __restrict__ out2) {
    int b = blockIdx.x, t = threadIdx.x, lane = t & 31, w = t >> 5;
    size_t base = (size_t)b * NBLK;
    float p1 = g_pmax[base + t], p2 = g_pmax[base + t + 256];
    float m = fmaxf(p1, p2);
    float s = g_psum[base + t] + g_psum[base + t + 256];
    __shared__ float sm[256]; __shared__ float ss[256];
    __shared__ float s_q[DD];
    __shared__ int s_cnt, s_cand[64];
    __shared__ int s_scnt, s_slot[64];
    __shared__ float s_bv[8]; __shared__ int s_bi[8];
    __shared__ int s_arg;
    if (t == 0) { s_cnt = 0; s_scnt = 0; }
    if (t < 64) reinterpret_cast<float4*>(s_q)[t] =
        reinterpret_cast<const float4*>(g_qn + (size_t)b * DD)[t];
    sm[t] = m; ss[t] = s; __syncthreads();
    for (int o = 128; o; o >>= 1) {
        if (t < o) { ss[t] += ss[t+o]; sm[t] = fmaxf(sm[t], sm[t+o]); }
        __syncthreads();
    }
    float rm = sm[0];
    if (t == 0) {
        g_cZinv[b] = 1.0f / ss[0];
        // wcomb (Taylor closed form for write softmax)
        float s1 = 0.f, s2 = 0.f;
        #pragma unroll
        for (int c = 0; c < WCH; c++) { s1 += g_ws1[b*WCH + c]; s2 += g_ws2[b*WCH + c]; }
        float sinv = 1.0f / (s1 + 1e-8f);
        float z = (float)NS + s1 * sinv + 0.5f * s2 * sinv * sinv;
        g_wsinv[b] = sinv;
        g_wZinv[b] = 1.0f / z;
    }
    // stage 1: candidate 128-blocks (fp32 pre-store blockmax; err <= 1e-3)
    float thr = rm - 8e-3f;
    if (p1 >= thr) { int p = atomicAdd(&s_cnt, 1); if (p < 64) s_cand[p] = t; }
    if (p2 >= thr) { int p = atomicAdd(&s_cnt, 1); if (p < 64) s_cand[p] = t + 256; }
    __syncthreads();
    int nc = min(s_cnt, 64);
    // stage 2: slot candidates via stored E (bf16; margin covers MMA 1e-3 + store 4e-3)
    float Eth = __expf(rm - 8e-3f) * 0.992f;
    const __nv_bfloat16* Erow = g_simb + (size_t)b * NS;
    for (int i = t; i < nc * 128; i += 256) {
        int n = s_cand[i >> 7] * 128 + (i & 127);
        if (__bfloat162float(Erow[n]) >= Eth) {
            int p = atomicAdd(&s_scnt, 1);
            if (p < 64) s_slot[p] = n;
        }
    }
    __syncthreads();
    int nsl = min(s_scnt, 64);
    // stage 3: exact fp32 rescore of the ~2 surviving slots
    float bv = -1e30f; int bi = 0x7fffffff;
    for (int c = w; c < nsl; c += 8) {
        int n = s_slot[c];
        const float* mr = mem + (size_t)n * DD;
        float d = 0.f;
        #pragma unroll
        for (int j = 0; j < 8; j += 4) {
            float4 qv = *reinterpret_cast<const float4*>(s_q + lane*8 + j);
            float4 mv = *reinterpret_cast<const float4*>(mr + lane*8 + j);
            d += qv.x*mv.x + qv.y*mv.y + qv.z*mv.z + qv.w*mv.w;
        }
        #pragma unroll
        for (int o = 16; o; o >>= 1) d += __shfl_xor_sync(0xffffffffu, d, o);
        d *= g_minv[n];
        if (lane == 0) {
            if (d > bv || (d == bv && n < bi)) { bv = d; bi = n; }
        }
    }
    if (lane == 0) { s_bv[w] = bv; s_bi[w] = bi; }
    __syncthreads();
    if (t == 0) {
        float v = s_bv[0]; int ix = s_bi[0];
        #pragma unroll
        for (int k = 1; k < 8; k++)
            if (s_bv[k] > v || (s_bv[k] == v && s_bi[k] < ix)) { v = s_bv[k]; ix = s_bi[k]; }
        g_argmax[b] = ix;
        s_arg = ix;
    }
    __syncthreads();
    // topk gather (one-hot row copy)
    out2[(size_t)b * DD + t] = mem[(size_t)s_arg * DD + t];
}

// ======= merged GEMM kernel: content (blocks 0..63) + newmem (64..575) ======
// dsm (max of both layouts) = 72192 bytes
#define CNM_DSM 72192
#define CONT_BLKS (4 * SPLITS)   // 64

__device__ __forceinline__ void content_body(int bx) {
    char* pA[2] = { dsm, dsm + 10240 };
    char* pB[2] = { dsm + 20480, dsm + 37376 };
    int tid = threadIdx.x, lane = tid & 31, w = tid >> 5;
    int wm = w >> 3, wn = w & 7;
    int bm = (bx & 3) * 128, z = bx >> 2;
    float acc[4][4][4];
    #pragma unroll
    for (int i = 0; i < 4; i++)
        #pragma unroll
        for (int j = 0; j < 4; j++)
            #pragma unroll
            for (int u = 0; u < 4; u++) acc[i][j][u] = 0.f;
    int r = lane & 7, gq = lane >> 3;
    int kbase = z * KCHUNK;
    int arow0 = tid >> 2, aq8 = (tid & 3) * 8;

    {
        *reinterpret_cast<uint4*>(pA[0] + arow0*80 + aq8*2) =
            *reinterpret_cast<const uint4*>(g_simb + (size_t)(bm + arow0) * NS + kbase + aq8);
        #pragma unroll
        for (int i = 0; i < 2; i++) {
            int idx = tid + i * 512;
            int row = idx >> 5, q8 = (idx & 31) * 8;
            *reinterpret_cast<uint4*>(pB[0] + row*528 + q8*2) =
                *reinterpret_cast<const uint4*>(g_memb + (size_t)(kbase + row) * DD + q8);
        }
    }
    __syncthreads();

    uint4 pfa, pfb[2];
    for (int it = 0; it < KCHUNK / 32; it++) {
        int st = it & 1;
        if (it < KCHUNK / 32 - 1) {
            int k0 = kbase + (it + 1) * 32;
            pfa = *reinterpret_cast<const uint4*>(g_simb + (size_t)(bm + arow0) * NS + k0 + aq8);
            #pragma unroll
            for (int i = 0; i < 2; i++) {
                int idx = tid + i * 512;
                int row = idx >> 5, q8 = (idx & 31) * 8;
                pfb[i] = *reinterpret_cast<const uint4*>(g_memb + (size_t)(k0 + row) * DD + q8);
            }
        }
        uint32_t aA = smem_u32(pA[st]), aB = smem_u32(pB[st]);
        #pragma unroll
        for (int ks = 0; ks < 2; ks++) {
            int kk = ks * 16;
            uint32_t af[4][4], bf[2][4];
            #pragma unroll
            for (int mt = 0; mt < 4; mt++) {
                int arow = wm*64 + mt*16 + r + 8*(gq & 1);
                int acol = kk + 8*(gq >> 1);
                ldsm4(af[mt], aA + (uint32_t)(arow*80 + acol*2));
            }
            #pragma unroll
            for (int np = 0; np < 2; np++) {
                int brow = kk + r + 8*(gq & 1);
                int bcol = wn*32 + np*16 + 8*(gq >> 1);
                ldsm4t(bf[np], aB + (uint32_t)(brow*528 + bcol*2));
            }
            #pragma unroll
            for (int mt = 0; mt < 4; mt++)
                #pragma unroll
                for (int nt = 0; nt < 4; nt++) {
                    int np = nt >> 1, hb = (nt & 1) * 2;
                    mma_bf16(acc[mt][nt], af[mt], bf[np][hb], bf[np][hb+1]);
                }
        }
        if (it < KCHUNK / 32 - 1) {
            int ns = st ^ 1;
            *reinterpret_cast<uint4*>(pA[ns] + arow0*80 + aq8*2) = pfa;
            #pragma unroll
            for (int i = 0; i < 2; i++) {
                int idx = tid + i * 512;
                int row = idx >> 5, q8 = (idx & 31) * 8;
                *reinterpret_cast<uint4*>(pB[ns] + row*528 + q8*2) = pfb[i];
            }
            __syncthreads();
        }
    }
    int g = lane >> 2, tq = lane & 3;
    #pragma unroll
    for (int mt = 0; mt < 4; mt++)
        #pragma unroll
        for (int rs = 0; rs < 2; rs++) {
            int mloc = wm*64 + mt*16 + g + rs*8;
            float* dst = g_partial + ((size_t)z * NB + bm + mloc) * DD;
            #pragma unroll
            for (int nt = 0; nt < 4; nt++) {
                int off = wn*32 + nt*8 + tq*2;
                *reinterpret_cast<float2*>(dst + off) =
                    make_float2(acc[mt][nt][rs*2], acc[mt][nt][rs*2+1]);
            }
        }
}

__device__ __forceinline__ void newmem_body(int bx, const float* __restrict__ mem,
                                            float* __restrict__ out3) {
    char* pA[2] = { dsm, dsm + 8704 };
    char* pB[2] = { dsm + 17408, dsm + 34304 };
    float* s_red   = reinterpret_cast<float*>(dsm + 51200);   // [32][128]
    float* s_sinv  = reinterpret_cast<float*>(dsm + 67584);
    float* s_zinv  = reinterpret_cast<float*>(dsm + 69632);
    float* s_erase = reinterpret_cast<float*>(dsm + 71680);
    int tid = threadIdx.x, lane = tid & 31, w = tid >> 5;
    int wm = w >> 3, wn = w & 7;
    int bm = bx * 128;
    if (tid < 128) {
        reinterpret_cast<float4*>(s_sinv)[tid] = reinterpret_cast<const float4*>(g_wsinv)[tid];
        reinterpret_cast<float4*>(s_zinv)[tid] = reinterpret_cast<const float4*>(g_wZinv)[tid];
    }
    float acc[4][4][4];
    #pragma unroll
    for (int i = 0; i < 4; i++)
        #pragma unroll
        for (int j = 0; j < 4; j++)
            #pragma unroll
            for (int u = 0; u < 4; u++) acc[i][j][u] = 0.f;
    float pr[8];
    #pragma unroll
    for (int j = 0; j < 8; j++) pr[j] = 1.f;
    int r = lane & 7, gq = lane >> 3;
    int arw = tid >> 4, ac8 = (tid & 15) * 8;
    __syncthreads();

    auto storeA = [&](int st, int krow, uint4 u) {
        float sv = s_sinv[krow], zv = s_zinv[krow];
        float f[8];
        unpack2(u.x, f[0], f[1]); unpack2(u.y, f[2], f[3]);
        unpack2(u.z, f[4], f[5]); unpack2(u.w, f[6], f[7]);
        uint32_t stv[4];
        #pragma unroll
        for (int j = 0; j < 8; j += 2) {
            float x0 = f[j] * sv, x1 = f[j+1] * sv;
            float w0 = (1.f + x0 + 0.5f*x0*x0) * zv;
            float w1 = (1.f + x1 + 0.5f*x1*x1) * zv;
            pr[j]   *= (1.f - 0.5f*w0);
            pr[j+1] *= (1.f - 0.5f*w1);
            stv[j >> 1] = pack_bf16x2(w0, w1);
        }
        *reinterpret_cast<uint4*>(pA[st] + arw*272 + ac8*2) =
            make_uint4(stv[0], stv[1], stv[2], stv[3]);
    };

    {
        uint4 u = *reinterpret_cast<const uint4*>(g_wwb + (size_t)arw * NS + bm + ac8);
        storeA(0, arw, u);
        #pragma unroll
        for (int i = 0; i < 2; i++) {
            int idx = tid + i * 512;
            int row = idx >> 5, q8 = (idx & 31) * 8;
            *reinterpret_cast<uint4*>(pB[0] + row*528 + q8*2) =
                *reinterpret_cast<const uint4*>(g_valb + (size_t)row * DD + q8);
        }
    }
    __syncthreads();

    uint4 pfa, pfb[2];
    for (int ch = 0; ch < 16; ch++) {
        int st = ch & 1;
        if (ch < 15) {
            int k0 = (ch + 1) * 32;
            pfa = *reinterpret_cast<const uint4*>(g_wwb + (size_t)(k0 + arw) * NS + bm + ac8);
            #pragma unroll
            for (int i = 0; i < 2; i++) {
                int idx = tid + i * 512;
                int row = idx >> 5, q8 = (idx & 31) * 8;
                pfb[i] = *reinterpret_cast<const uint4*>(g_valb + (size_t)(k0 + row) * DD + q8);
            }
        }
        uint32_t aA = smem_u32(pA[st]), aB = smem_u32(pB[st]);
        #pragma unroll
        for (int ks = 0; ks < 2; ks++) {
            int kk = ks * 16;
            uint32_t af[4][4], bf[2][4];
            #pragma unroll
            for (int mt = 0; mt < 4; mt++) {
                int arow = kk + r + 8*(gq >> 1);
                int acol = wm*64 + mt*16 + 8*(gq & 1);
                ldsm4t(af[mt], aA + (uint32_t)(arow*272 + acol*2));
            }
            #pragma unroll
            for (int np = 0; np < 2; np++) {
                int brow = kk + r + 8*(gq & 1);
                int bcol = wn*32 + np*16 + 8*(gq >> 1);
                ldsm4t(bf[np], aB + (uint32_t)(brow*528 + bcol*2));
            }
            #pragma unroll
            for (int mt = 0; mt < 4; mt++)
                #pragma unroll
                for (int nt = 0; nt < 4; nt++) {
                    int np = nt >> 1, hb = (nt & 1) * 2;
                    mma_bf16(acc[mt][nt], af[mt], bf[np][hb], bf[np][hb+1]);
                }
        }
        if (ch < 15) {
            int ns = st ^ 1;
            storeA(ns, (ch + 1) * 32 + arw, pfa);
            #pragma unroll
            for (int i = 0; i < 2; i++) {
                int idx = tid + i * 512;
                int row = idx >> 5, q8 = (idx & 31) * 8;
                *reinterpret_cast<uint4*>(pB[ns] + row*528 + q8*2) = pfb[i];
            }
            __syncthreads();
        }
    }
    __syncthreads();
    #pragma unroll
    for (int j = 0; j < 8; j++) s_red[arw*128 + ac8 + j] = pr[j];
    __syncthreads();
    if (tid < 128) {
        float p = 1.f;
        #pragma unroll
        for (int k = 0; k < 32; k++) p *= s_red[k*128 + tid];
        s_erase[tid] = p;
    }
    __syncthreads();
    int g = lane >> 2, tq = lane & 3;
    #pragma unroll
    for (int mt = 0; mt < 4; mt++)
        #pragma unroll
        for (int rs = 0; rs < 2; rs++) {
            int mloc = wm*64 + mt*16 + g + rs*8;
            int slot = bm + mloc;
            float er = s_erase[mloc];
            const float* mrow = mem + (size_t)slot * DD;
            float* dst = out3 + (size_t)slot * DD;
            #pragma unroll
            for (int nt = 0; nt < 4; nt++) {
                int off = wn*32 + nt*8 + tq*2;
                float2 mv = *reinterpret_cast<const float2*>(mrow + off);
                *reinterpret_cast<float2*>(dst + off) =
                    make_float2(mv.x*er + acc[mt][nt][rs*2], mv.y*er + acc[mt][nt][rs*2+1]);
            }
        }
}

__global__ void __launch_bounds__(512) k_cnm(const float* __restrict__ mem,
                                             float* __restrict__ out3) {
    if (blockIdx.x < CONT_BLKS) content_body(blockIdx.x);
    else                        newmem_body(blockIdx.x - CONT_BLKS, mem, out3);
}

// ---------------- reduce split-K partials, scale by 1/Z ----------------------
__global__ void __launch_bounds__(256) k_reduce(float* __restrict__ out1) {
    int idx = blockIdx.x * 256 + threadIdx.x;
    int b = idx >> 8;
    float s = 0.f;
    #pragma unroll
    for (int z = 0; z < SPLITS; z++) s += g_partial[(size_t)z * NB * DD + idx];
    out1[idx] = s * g_cZinv[b];
}

// ---------------- launch ----------------------------------------------------
extern "C" void kernel_launch(void* const* d_in, const int* in_sizes, int n_in,
                              void* d_out, int out_size) {
    const float* memory  = (const float*)d_in[0];
    const float* query   = (const float*)d_in[1];
    const float* value   = (const float*)d_in[2];
    const float* prev    = (const float*)d_in[3];
    const float* shiftw  = (const float*)d_in[4];

    float* out  = (float*)d_out;
    float* out1 = out;                     // read_content [512,256]
    float* out2 = out + NB * DD;           // read_topk    [512,256]
    float* out3 = out + 2 * NB * DD;       // new_mem      [65536,256]

    cudaFuncSetAttribute(k_sim, cudaFuncAttributeMaxDynamicSharedMemorySize, SIM_DSM);
    cudaFuncSetAttribute(k_cnm, cudaFuncAttributeMaxDynamicSharedMemorySize, CNM_DSM);

    k_norms  <<<(NS + 2*NB) / 8, dim3(32, 8)>>>(memory, query, value);
    k_sim    <<<dim3(NS / 128, NB / 128), 256, SIM_DSM>>>();
    k_sharp  <<<dim3(NB, WCH), 256>>>(prev, shiftw);
    k_combine<<<NB, 256>>>(memory, out2);
    k_cnm    <<<CONT_BLKS + NS / 128, 512, CNM_DSM>>>(memory, out3);
    k_reduce <<<(NB * DD) / 256, 256>>>(out1);
}

// round 11
// speedup vs baseline: 5.1174x; 1.1019x over previous
#include <cuda_runtime.h>
#include <cuda_bf16.h>
#include <math.h>
#include <stdint.h>

#define NB 512
#define NS 65536
#define DD 256
#define SPLITS 16
#define KCHUNK (NS / SPLITS)   // 4096
#define NBLK 512
#define WCH 8          // sharp chunks per row

// ---------------- scratch (device globals; no allocations allowed) ----------
__device__ __nv_bfloat16 g_simb[(size_t)NB * NS];   // 64 MB : E = exp(sim), bf16
__device__ __nv_bfloat16 g_wwb [(size_t)NB * NS];   // 64 MB : sharp (pre-normalize), bf16
__device__ __nv_bfloat16 g_memb[(size_t)NS * DD];   // 32 MB : bf16 memory
__device__ __nv_bfloat16 g_qnb [NB * DD];
__device__ __nv_bfloat16 g_valb[NB * DD];
__device__ float g_qn [NB * DD];
__device__ float g_minv[NS];
__device__ float g_pmax[(size_t)NB * NBLK];
__device__ float g_psum[(size_t)NB * NBLK];
__device__ int   g_argmax[NB];
__device__ float g_cZinv[NB];
__device__ float g_ws1[NB * WCH];
__device__ float g_ws2[NB * WCH];
__device__ float g_wsinv[NB];
__device__ float g_wZinv[NB];
__device__ float g_partial[(size_t)SPLITS * NB * DD];  // 8 MB

// ======================= helpers ============================================
__device__ __forceinline__ uint32_t smem_u32(const void* p) {
    uint32_t a;
    asm("{ .reg .u64 t; cvta.to.shared.u64 t, %1; cvt.u32.u64 %0, t; }" : "=r"(a) : "l"(p));
    return a;
}
__device__ __forceinline__ uint32_t pack_bf16x2(float lo, float hi) {
    uint32_t r;
    asm("cvt.rn.bf16x2.f32 %0, %1, %2;" : "=r"(r) : "f"(hi), "f"(lo));
    return r;
}
__device__ __forceinline__ void unpack2(uint32_t u, float& a, float& b) {
    __nv_bfloat162 h = *reinterpret_cast<__nv_bfloat162*>(&u);
    a = __bfloat162float(h.x); b = __bfloat162float(h.y);
}
__device__ __forceinline__ void ldsm4(uint32_t* r, uint32_t addr) {
    asm volatile("ldmatrix.sync.aligned.m8n8.x4.shared.b16 {%0,%1,%2,%3}, [%4];"
        : "=r"(r[0]), "=r"(r[1]), "=r"(r[2]), "=r"(r[3]) : "r"(addr));
}
__device__ __forceinline__ void ldsm4t(uint32_t* r, uint32_t addr) {
    asm volatile("ldmatrix.sync.aligned.m8n8.x4.trans.shared.b16 {%0,%1,%2,%3}, [%4];"
        : "=r"(r[0]), "=r"(r[1]), "=r"(r[2]), "=r"(r[3]) : "r"(addr));
}
__device__ __forceinline__ void mma_bf16(float* c, const uint32_t* a, uint32_t b0, uint32_t b1) {
    asm volatile("mma.sync.aligned.m16n8k16.row.col.f32.bf16.bf16.f32 "
        "{%0,%1,%2,%3}, {%4,%5,%6,%7}, {%8,%9}, {%0,%1,%2,%3};"
        : "+f"(c[0]), "+f"(c[1]), "+f"(c[2]), "+f"(c[3])
        : "r"(a[0]), "r"(a[1]), "r"(a[2]), "r"(a[3]), "r"(b0), "r"(b1));
}

extern __shared__ __align__(16) char dsm[];

// ===== merged pre-pass: sharp (blocks 0..4095) + norms/bf16-convert =========
__global__ void __launch_bounds__(256) k_pre(const float* __restrict__ mem,
                                             const float* __restrict__ q,
                                             const float* __restrict__ val,
                                             const float* __restrict__ prev,
                                             const float* __restrict__ sw) {
    __shared__ float r1[256], r2[256];
    int bx = blockIdx.x, t = threadIdx.x;
    if (bx < NB * WCH) {
        // ---- sharp: one streaming pass, store bf16, partial S1/S2 ----
        int b = bx >> 3, ch = bx & 7, lane = t & 31;
        const float* row = prev + (size_t)b * NS;
        __nv_bfloat16* wr = g_wwb + (size_t)b * NS;
        float w0 = sw[0], w1 = sw[1], w2 = sw[2];
        int base = ch * (NS / WCH);
        float s1 = 0.f, s2 = 0.f;
        #pragma unroll
        for (int it = 0; it < NS / WCH / 1024; it++) {
            int i4 = base + (it * 256 + t) * 4;
            float4 v = *reinterpret_cast<const float4*>(row + i4);
            float pl = __shfl_up_sync(0xffffffffu, v.w, 1);
            float nx = __shfl_down_sync(0xffffffffu, v.x, 1);
            if (lane == 0)  pl = (i4 > 0) ? row[i4 - 1] : 0.f;
            if (lane == 31) nx = (i4 + 4 < NS) ? row[i4 + 4] : 0.f;
            float a0 = pl*w0 + v.x*w1 + v.y*w2;
            float a1 = v.x*w0 + v.y*w1 + v.z*w2;
            float a2 = v.y*w0 + v.z*w1 + v.w*w2;
            float a3 = v.z*w0 + v.w*w1 + nx*w2;
            float p0 = a0*a0*rsqrtf(fmaxf(a0, 1e-35f));
            float p1 = a1*a1*rsqrtf(fmaxf(a1, 1e-35f));
            float p2 = a2*a2*rsqrtf(fmaxf(a2, 1e-35f));
            float p3 = a3*a3*rsqrtf(fmaxf(a3, 1e-35f));
            s1 += p0 + p1 + p2 + p3;
            s2 += p0*p0 + p1*p1 + p2*p2 + p3*p3;
            *reinterpret_cast<uint2*>(wr + i4) =
                make_uint2(pack_bf16x2(p0, p1), pack_bf16x2(p2, p3));
        }
        r1[t] = s1; r2[t] = s2; __syncthreads();
        for (int o = 128; o; o >>= 1) {
            if (t < o) { r1[t] += r1[t+o]; r2[t] += r2[t+o]; }
            __syncthreads();
        }
        if (t == 0) { g_ws1[b * WCH + ch] = r1[0]; g_ws2[b * WCH + ch] = r2[0]; }
        return;
    }
    // ---- norms + bf16 pre-conversion ----
    int lane = t & 31;
    int row = (bx - NB * WCH) * 8 + (t >> 5);
    if (row < NS) {
        const float4* p = reinterpret_cast<const float4*>(mem + (size_t)row * DD);
        float4 v0 = p[lane];
        float4 v1 = p[lane + 32];
        float s = v0.x*v0.x + v0.y*v0.y + v0.z*v0.z + v0.w*v0.w
                + v1.x*v1.x + v1.y*v1.y + v1.z*v1.z + v1.w*v1.w;
        #pragma unroll
        for (int o = 16; o; o >>= 1) s += __shfl_xor_sync(0xffffffffu, s, o);
        if (lane == 0) g_minv[row] = 1.0f / fmaxf(sqrtf(s), 1e-12f);
        __nv_bfloat16* d = g_memb + (size_t)row * DD;
        *reinterpret_cast<uint2*>(d + lane*4) =
            make_uint2(pack_bf16x2(v0.x, v0.y), pack_bf16x2(v0.z, v0.w));
        *reinterpret_cast<uint2*>(d + 128 + lane*4) =
            make_uint2(pack_bf16x2(v1.x, v1.y), pack_bf16x2(v1.z, v1.w));
    } else if (row < NS + NB) {
        int qr = row - NS;
        const float4* p = reinterpret_cast<const float4*>(q + (size_t)qr * DD);
        float4 v0 = p[lane];
        float4 v1 = p[lane + 32];
        float s = v0.x*v0.x + v0.y*v0.y + v0.z*v0.z + v0.w*v0.w
                + v1.x*v1.x + v1.y*v1.y + v1.z*v1.z + v1.w*v1.w;
        #pragma unroll
        for (int o = 16; o; o >>= 1) s += __shfl_xor_sync(0xffffffffu, s, o);
        float inv = 1.0f / fmaxf(sqrtf(s), 1e-12f);
        v0.x *= inv; v0.y *= inv; v0.z *= inv; v0.w *= inv;
        v1.x *= inv; v1.y *= inv; v1.z *= inv; v1.w *= inv;
        float4* o4 = reinterpret_cast<float4*>(g_qn + (size_t)qr * DD);
        o4[lane] = v0; o4[lane + 32] = v1;
        __nv_bfloat16* d = g_qnb + (size_t)qr * DD;
        *reinterpret_cast<uint2*>(d + lane*4) =
            make_uint2(pack_bf16x2(v0.x, v0.y), pack_bf16x2(v0.z, v0.w));
        *reinterpret_cast<uint2*>(d + 128 + lane*4) =
            make_uint2(pack_bf16x2(v1.x, v1.y), pack_bf16x2(v1.z, v1.w));
    } else {
        int vr = row - NS - NB;
        const float4* p = reinterpret_cast<const float4*>(val + (size_t)vr * DD);
        float4 v0 = p[lane];
        float4 v1 = p[lane + 32];
        __nv_bfloat16* d = g_valb + (size_t)vr * DD;
        *reinterpret_cast<uint2*>(d + lane*4) =
            make_uint2(pack_bf16x2(v0.x, v0.y), pack_bf16x2(v0.z, v0.w));
        *reinterpret_cast<uint2*>(d + 128 + lane*4) =
            make_uint2(pack_bf16x2(v1.x, v1.y), pack_bf16x2(v1.z, v1.w));
    }
}

// ============ sim GEMM (HMMA bf16, double-buffered) + exp epilogue ==========
// dsm: A0@0 A1@10240 B0@20480 B1@30720 minv@40960  => 41472 bytes
#define SIM_DSM 41472
__global__ void __launch_bounds__(256, 2) k_sim() {
    char* pA[2] = { dsm, dsm + 10240 };
    char* pB[2] = { dsm + 20480, dsm + 30720 };
    float* s_minv = reinterpret_cast<float*>(dsm + 40960);
    int tid = threadIdx.x, lane = tid & 31, w = tid >> 5;
    int wm = w >> 2, wn = w & 3;
    int bn = blockIdx.x * 128, bm = blockIdx.y * 128;
    if (tid < 32) reinterpret_cast<float4*>(s_minv)[tid] =
        reinterpret_cast<const float4*>(g_minv + bn)[tid];

    float acc[4][4][4];
    #pragma unroll
    for (int i = 0; i < 4; i++)
        #pragma unroll
        for (int j = 0; j < 4; j++)
            #pragma unroll
            for (int u = 0; u < 4; u++) acc[i][j][u] = 0.f;

    int r = lane & 7, gq = lane >> 3;

    #pragma unroll
    for (int i = 0; i < 2; i++) {
        int idx = tid + i * 256;
        int row = idx >> 2, q8 = (idx & 3) * 8;
        *reinterpret_cast<uint4*>(pA[0] + row*80 + q8*2) =
            *reinterpret_cast<const uint4*>(g_qnb + (size_t)(bm + row) * DD + q8);
        *reinterpret_cast<uint4*>(pB[0] + row*80 + q8*2) =
            *reinterpret_cast<const uint4*>(g_memb + (size_t)(bn + row) * DD + q8);
    }
    __syncthreads();

    uint4 pfa[2], pfb[2];
    for (int ch = 0; ch < 8; ch++) {
        int st = ch & 1;
        if (ch < 7) {
            int k0 = (ch + 1) * 32;
            #pragma unroll
            for (int i = 0; i < 2; i++) {
                int idx = tid + i * 256;
                int row = idx >> 2, q8 = (idx & 3) * 8;
                pfa[i] = *reinterpret_cast<const uint4*>(g_qnb + (size_t)(bm + row) * DD + k0 + q8);
                pfb[i] = *reinterpret_cast<const uint4*>(g_memb + (size_t)(bn + row) * DD + k0 + q8);
            }
        }
        uint32_t aA = smem_u32(pA[st]), aB = smem_u32(pB[st]);
        #pragma unroll
        for (int ks = 0; ks < 2; ks++) {
            int kk = ks * 16;
            uint32_t ah[4][4], bh[2][4];
            #pragma unroll
            for (int mt = 0; mt < 4; mt++) {
                int arow = wm*64 + mt*16 + r + 8*(gq & 1);
                int acol = kk + 8*(gq >> 1);
                ldsm4(ah[mt], aA + (uint32_t)(arow*80 + acol*2));
            }
            #pragma unroll
            for (int np = 0; np < 2; np++) {
                int brow = wn*32 + np*16 + r + 8*(gq >> 1);
                int bcol = kk + 8*(gq & 1);
                ldsm4(bh[np], aB + (uint32_t)(brow*80 + bcol*2));
            }
            #pragma unroll
            for (int mt = 0; mt < 4; mt++)
                #pragma unroll
                for (int nt = 0; nt < 4; nt++) {
                    int np = nt >> 1, hb = (nt & 1) * 2;
                    mma_bf16(acc[mt][nt], ah[mt], bh[np][hb], bh[np][hb+1]);
                }
        }
        if (ch < 7) {
            int ns = st ^ 1;
            #pragma unroll
            for (int i = 0; i < 2; i++) {
                int idx = tid + i * 256;
                int row = idx >> 2, q8 = (idx & 3) * 8;
                *reinterpret_cast<uint4*>(pA[ns] + row*80 + q8*2) = pfa[i];
                *reinterpret_cast<uint4*>(pB[ns] + row*80 + q8*2) = pfb[i];
            }
            __syncthreads();
        }
    }
    __syncthreads();

    float* s_max = reinterpret_cast<float*>(pA[0]);
    float* s_sum = reinterpret_cast<float*>(pB[0]);
    int g = lane >> 2, t = lane & 3;
    #pragma unroll
    for (int mt = 0; mt < 4; mt++)
        #pragma unroll
        for (int rs = 0; rs < 2; rs++) {
            int mloc = wm*64 + mt*16 + g + rs*8;
            float lm = -1e30f; float ls = 0.f;
            #pragma unroll
            for (int nt = 0; nt < 4; nt++) {
                int ncl = wn*32 + nt*8 + t*2;
                float s0 = acc[mt][nt][rs*2]   * s_minv[ncl];
                float s1 = acc[mt][nt][rs*2+1] * s_minv[ncl+1];
                lm = fmaxf(lm, fmaxf(s0, s1));
                float e0 = __expf(s0), e1 = __expf(s1);
                ls += e0 + e1;
                *reinterpret_cast<uint32_t*>(g_simb + (size_t)(bm + mloc) * NS + bn + ncl) =
                    pack_bf16x2(e0, e1);
            }
            #pragma unroll
            for (int o = 1; o < 4; o <<= 1) {
                lm = fmaxf(lm, __shfl_xor_sync(0xffffffffu, lm, o));
                ls += __shfl_xor_sync(0xffffffffu, ls, o);
            }
            if (t == 0) {
                s_max[wn*128 + mloc] = lm;
                s_sum[wn*128 + mloc] = ls;
            }
        }
    __syncthreads();
    if (tid < 128) {
        float m = s_max[tid]; float s = s_sum[tid];
        #pragma unroll
        for (int wq = 1; wq < 4; wq++) {
            m = fmaxf(m, s_max[wq*128 + tid]);
            s += s_sum[wq*128 + tid];
        }
        size_t pidx = (size_t)(bm + tid) * NBLK + blockIdx.x;
        g_pmax[pidx] = m; g_psum[pidx] = s;
    }
}

// ------- combine: Z + two-stage argmax (block -> slot via E) + wcomb + topk --
__global__ void __launch_bounds__(256) k_combine(const float* __restrict__ mem,
                                                 float* __restrict__ out2) {
    int b = blockIdx.x, t = threadIdx.x, lane = t & 31, w = t >> 5;
    size_t base = (size_t)b * NBLK;
    float p1 = g_pmax[base + t], p2 = g_pmax[base + t + 256];
    float m = fmaxf(p1, p2);
    float s = g_psum[base + t] + g_psum[base + t + 256];
    __shared__ float sm[256]; __shared__ float ss[256];
    __shared__ float s_q[DD];
    __shared__ int s_cnt, s_cand[64];
    __shared__ int s_scnt, s_slot[64];
    __shared__ float s_bv[8]; __shared__ int s_bi[8];
    __shared__ int s_arg;
    if (t == 0) { s_cnt = 0; s_scnt = 0; }
    if (t < 64) reinterpret_cast<float4*>(s_q)[t] =
        reinterpret_cast<const float4*>(g_qn + (size_t)b * DD)[t];
    sm[t] = m; ss[t] = s; __syncthreads();
    for (int o = 128; o; o >>= 1) {
        if (t < o) { ss[t] += ss[t+o]; sm[t] = fmaxf(sm[t], sm[t+o]); }
        __syncthreads();
    }
    float rm = sm[0];
    if (t == 0) {
        g_cZinv[b] = 1.0f / ss[0];
        float s1 = 0.f, s2 = 0.f;
        #pragma unroll
        for (int c = 0; c < WCH; c++) { s1 += g_ws1[b*WCH + c]; s2 += g_ws2[b*WCH + c]; }
        float sinv = 1.0f / (s1 + 1e-8f);
        float z = (float)NS + s1 * sinv + 0.5f * s2 * sinv * sinv;
        g_wsinv[b] = sinv;
        g_wZinv[b] = 1.0f / z;
    }
    float thr = rm - 8e-3f;
    if (p1 >= thr) { int p = atomicAdd(&s_cnt, 1); if (p < 64) s_cand[p] = t; }
    if (p2 >= thr) { int p = atomicAdd(&s_cnt, 1); if (p < 64) s_cand[p] = t + 256; }
    __syncthreads();
    int nc = min(s_cnt, 64);
    float Eth = __expf(rm - 8e-3f) * 0.992f;
    const __nv_bfloat16* Erow = g_simb + (size_t)b * NS;
    for (int i = t; i < nc * 128; i += 256) {
        int n = s_cand[i >> 7] * 128 + (i & 127);
        if (__bfloat162float(Erow[n]) >= Eth) {
            int p = atomicAdd(&s_scnt, 1);
            if (p < 64) s_slot[p] = n;
        }
    }
    __syncthreads();
    int nsl = min(s_scnt, 64);
    float bv = -1e30f; int bi = 0x7fffffff;
    for (int c = w; c < nsl; c += 8) {
        int n = s_slot[c];
        const float* mr = mem + (size_t)n * DD;
        float d = 0.f;
        #pragma unroll
        for (int j = 0; j < 8; j += 4) {
            float4 qv = *reinterpret_cast<const float4*>(s_q + lane*8 + j);
            float4 mv = *reinterpret_cast<const float4*>(mr + lane*8 + j);
            d += qv.x*mv.x + qv.y*mv.y + qv.z*mv.z + qv.w*mv.w;
        }
        #pragma unroll
        for (int o = 16; o; o >>= 1) d += __shfl_xor_sync(0xffffffffu, d, o);
        d *= g_minv[n];
        if (lane == 0) {
            if (d > bv || (d == bv && n < bi)) { bv = d; bi = n; }
        }
    }
    if (lane == 0) { s_bv[w] = bv; s_bi[w] = bi; }
    __syncthreads();
    if (t == 0) {
        float v = s_bv[0]; int ix = s_bi[0];
        #pragma unroll
        for (int k = 1; k < 8; k++)
            if (s_bv[k] > v || (s_bv[k] == v && s_bi[k] < ix)) { v = s_bv[k]; ix = s_bi[k]; }
        g_argmax[b] = ix;
        s_arg = ix;
    }
    __syncthreads();
    out2[(size_t)b * DD + t] = mem[(size_t)s_arg * DD + t];
}

// ======= merged GEMM kernel, 256 threads, 128x128 tiles, 2 CTA/SM ===========
// content blocks 0..127: (z=bx>>3, bm=((bx>>1)&3)*128, bd=(bx&1)*128)
// newmem blocks 128..1151: (bm=(bx>>1)*128, bd=(bx&1)*128)
#define CNM_DSM 47616
#define CONT_BLKS 128

__device__ __forceinline__ void content_body(int bx) {
    char* pA[2] = { dsm, dsm + 10240 };           // 128 x 32 bf16, stride 80
    char* pB[2] = { dsm + 20480, dsm + 29184 };   // 32 x 128 bf16, stride 272
    int tid = threadIdx.x, lane = tid & 31, w = tid >> 5;
    int wm = w >> 2, wn = w & 3;
    int z = bx >> 3, bm = ((bx >> 1) & 3) * 128, bd = (bx & 1) * 128;
    float acc[4][4][4];
    #pragma unroll
    for (int i = 0; i < 4; i++)
        #pragma unroll
        for (int j = 0; j < 4; j++)
            #pragma unroll
            for (int u = 0; u < 4; u++) acc[i][j][u] = 0.f;
    int r = lane & 7, gq = lane >> 3;
    int kbase = z * KCHUNK;

    #pragma unroll
    for (int i = 0; i < 2; i++) {
        int idx = tid + i * 256;
        int ar = idx >> 2, aq8 = (idx & 3) * 8;
        *reinterpret_cast<uint4*>(pA[0] + ar*80 + aq8*2) =
            *reinterpret_cast<const uint4*>(g_simb + (size_t)(bm + ar) * NS + kbase + aq8);
        int br = idx >> 4, bq8 = (idx & 15) * 8;
        *reinterpret_cast<uint4*>(pB[0] + br*272 + bq8*2) =
            *reinterpret_cast<const uint4*>(g_memb + (size_t)(kbase + br) * DD + bd + bq8);
    }
    __syncthreads();

    uint4 pfa[2], pfb[2];
    for (int it = 0; it < KCHUNK / 32; it++) {
        int st = it & 1;
        if (it < KCHUNK / 32 - 1) {
            int k0 = kbase + (it + 1) * 32;
            #pragma unroll
            for (int i = 0; i < 2; i++) {
                int idx = tid + i * 256;
                int ar = idx >> 2, aq8 = (idx & 3) * 8;
                pfa[i] = *reinterpret_cast<const uint4*>(g_simb + (size_t)(bm + ar) * NS + k0 + aq8);
                int br = idx >> 4, bq8 = (idx & 15) * 8;
                pfb[i] = *reinterpret_cast<const uint4*>(g_memb + (size_t)(k0 + br) * DD + bd + bq8);
            }
        }
        uint32_t aA = smem_u32(pA[st]), aB = smem_u32(pB[st]);
        #pragma unroll
        for (int ks = 0; ks < 2; ks++) {
            int kk = ks * 16;
            uint32_t af[4][4], bf[2][4];
            #pragma unroll
            for (int mt = 0; mt < 4; mt++) {
                int arow = wm*64 + mt*16 + r + 8*(gq & 1);
                int acol = kk + 8*(gq >> 1);
                ldsm4(af[mt], aA + (uint32_t)(arow*80 + acol*2));
            }
            #pragma unroll
            for (int np = 0; np < 2; np++) {
                int brow = kk + r + 8*(gq & 1);
                int bcol = wn*32 + np*16 + 8*(gq >> 1);
                ldsm4t(bf[np], aB + (uint32_t)(brow*272 + bcol*2));
            }
            #pragma unroll
            for (int mt = 0; mt < 4; mt++)
                #pragma unroll
                for (int nt = 0; nt < 4; nt++) {
                    int np = nt >> 1, hb = (nt & 1) * 2;
                    mma_bf16(acc[mt][nt], af[mt], bf[np][hb], bf[np][hb+1]);
                }
        }
        if (it < KCHUNK / 32 - 1) {
            int ns = st ^ 1;
            #pragma unroll
            for (int i = 0; i < 2; i++) {
                int idx = tid + i * 256;
                int ar = idx >> 2, aq8 = (idx & 3) * 8;
                *reinterpret_cast<uint4*>(pA[ns] + ar*80 + aq8*2) = pfa[i];
                int br = idx >> 4, bq8 = (idx & 15) * 8;
                *reinterpret_cast<uint4*>(pB[ns] + br*272 + bq8*2) = pfb[i];
            }
            __syncthreads();
        }
    }
    int g = lane >> 2, tq = lane & 3;
    #pragma unroll
    for (int mt = 0; mt < 4; mt++)
        #pragma unroll
        for (int rs = 0; rs < 2; rs++) {
            int mloc = wm*64 + mt*16 + g + rs*8;
            float* dst = g_partial + ((size_t)z * NB + bm + mloc) * DD + bd;
            #pragma unroll
            for (int nt = 0; nt < 4; nt++) {
                int off = wn*32 + nt*8 + tq*2;
                *reinterpret_cast<float2*>(dst + off) =
                    make_float2(acc[mt][nt][rs*2], acc[mt][nt][rs*2+1]);
            }
        }
}

__device__ __forceinline__ void newmem_body(int bx, const float* __restrict__ mem,
                                            float* __restrict__ out3) {
    char* pA[2] = { dsm, dsm + 8704 };            // 32 x 128 bf16 (w), stride 272
    char* pB[2] = { dsm + 17408, dsm + 26112 };   // 32 x 128 bf16 (valb), stride 272
    float* s_red   = reinterpret_cast<float*>(dsm + 34816);   // [16][128]
    float* s_sinv  = reinterpret_cast<float*>(dsm + 43008);
    float* s_zinv  = reinterpret_cast<float*>(dsm + 45056);
    float* s_erase = reinterpret_cast<float*>(dsm + 47104);
    int tid = threadIdx.x, lane = tid & 31, w = tid >> 5;
    int wm = w >> 2, wn = w & 3;
    int bm = (bx >> 1) * 128, bd = (bx & 1) * 128;
    if (tid < 128) {
        reinterpret_cast<float4*>(s_sinv)[tid] = reinterpret_cast<const float4*>(g_wsinv)[tid];
        reinterpret_cast<float4*>(s_zinv)[tid] = reinterpret_cast<const float4*>(g_wZinv)[tid];
    }
    float acc[4][4][4];
    #pragma unroll
    for (int i = 0; i < 4; i++)
        #pragma unroll
        for (int j = 0; j < 4; j++)
            #pragma unroll
            for (int u = 0; u < 4; u++) acc[i][j][u] = 0.f;
    float pr[8];
    #pragma unroll
    for (int j = 0; j < 8; j++) pr[j] = 1.f;
    int r = lane & 7, gq = lane >> 3;
    int ac8 = (tid & 15) * 8;
    __syncthreads();

    auto storeA = [&](int st, int rowoff, int krow, uint4 u) {
        float sv = s_sinv[krow], zv = s_zinv[krow];
        float f[8];
        unpack2(u.x, f[0], f[1]); unpack2(u.y, f[2], f[3]);
        unpack2(u.z, f[4], f[5]); unpack2(u.w, f[6], f[7]);
        uint32_t stv[4];
        #pragma unroll
        for (int j = 0; j < 8; j += 2) {
            float x0 = f[j] * sv, x1 = f[j+1] * sv;
            float w0 = (1.f + x0 + 0.5f*x0*x0) * zv;
            float w1 = (1.f + x1 + 0.5f*x1*x1) * zv;
            pr[j]   *= (1.f - 0.5f*w0);
            pr[j+1] *= (1.f - 0.5f*w1);
            stv[j >> 1] = pack_bf16x2(w0, w1);
        }
        *reinterpret_cast<uint4*>(pA[st] + rowoff*272 + ac8*2) =
            make_uint4(stv[0], stv[1], stv[2], stv[3]);
    };

    {
        #pragma unroll
        for (int i = 0; i < 2; i++) {
            int idx = tid + i * 256;
            int ar = idx >> 4;
            uint4 u = *reinterpret_cast<const uint4*>(g_wwb + (size_t)ar * NS + bm + ac8);
            storeA(0, ar, ar, u);
            *reinterpret_cast<uint4*>(pB[0] + ar*272 + ac8*2) =
                *reinterpret_cast<const uint4*>(g_valb + (size_t)ar * DD + bd + ac8);
        }
    }
    __syncthreads();

    uint4 pfa[2], pfb[2];
    for (int ch = 0; ch < 16; ch++) {
        int st = ch & 1;
        if (ch < 15) {
            int k0 = (ch + 1) * 32;
            #pragma unroll
            for (int i = 0; i < 2; i++) {
                int idx = tid + i * 256;
                int ar = idx >> 4;
                pfa[i] = *reinterpret_cast<const uint4*>(g_wwb + (size_t)(k0 + ar) * NS + bm + ac8);
                pfb[i] = *reinterpret_cast<const uint4*>(g_valb + (size_t)(k0 + ar) * DD + bd + ac8);
            }
        }
        uint32_t aA = smem_u32(pA[st]), aB = smem_u32(pB[st]);
        #pragma unroll
        for (int ks = 0; ks < 2; ks++) {
            int kk = ks * 16;
            uint32_t af[4][4], bf[2][4];
            #pragma unroll
            for (int mt = 0; mt < 4; mt++) {
                int arow = kk + r + 8*(gq >> 1);
                int acol = wm*64 + mt*16 + 8*(gq & 1);
                ldsm4t(af[mt], aA + (uint32_t)(arow*272 + acol*2));
            }
            #pragma unroll
            for (int np = 0; np < 2; np++) {
                int brow = kk + r + 8*(gq & 1);
                int bcol = wn*32 + np*16 + 8*(gq >> 1);
                ldsm4t(bf[np], aB + (uint32_t)(brow*272 + bcol*2));
            }
            #pragma unroll
            for (int mt = 0; mt < 4; mt++)
                #pragma unroll
                for (int nt = 0; nt < 4; nt++) {
                    int np = nt >> 1, hb = (nt & 1) * 2;
                    mma_bf16(acc[mt][nt], af[mt], bf[np][hb], bf[np][hb+1]);
                }
        }
        if (ch < 15) {
            int ns = st ^ 1;
            int k0 = (ch + 1) * 32;
            #pragma unroll
            for (int i = 0; i < 2; i++) {
                int idx = tid + i * 256;
                int ar = idx >> 4;
                storeA(ns, ar, k0 + ar, pfa[i]);
                *reinterpret_cast<uint4*>(pB[ns] + ar*272 + ac8*2) = pfb[i];
            }
            __syncthreads();
        }
    }
    __syncthreads();
    #pragma unroll
    for (int j = 0; j < 8; j++) s_red[(tid >> 4)*128 + ac8 + j] = pr[j];
    __syncthreads();
    if (tid < 128) {
        float p = 1.f;
        #pragma unroll
        for (int k = 0; k < 16; k++) p *= s_red[k*128 + tid];
        s_erase[tid] = p;
    }
    __syncthreads();
    int g = lane >> 2, tq = lane & 3;
    #pragma unroll
    for (int mt = 0; mt < 4; mt++)
        #pragma unroll
        for (int rs = 0; rs < 2; rs++) {
            int mloc = wm*64 + mt*16 + g + rs*8;
            int slot = bm + mloc;
            float er = s_erase[mloc];
            const float* mrow = mem + (size_t)slot * DD + bd;
            float* dst = out3 + (size_t)slot * DD + bd;
            #pragma unroll
            for (int nt = 0; nt < 4; nt++) {
                int off = wn*32 + nt*8 + tq*2;
                float2 mv = *reinterpret_cast<const float2*>(mrow + off);
                *reinterpret_cast<float2*>(dst + off) =
                    make_float2(mv.x*er + acc[mt][nt][rs*2], mv.y*er + acc[mt][nt][rs*2+1]);
            }
        }
}

__global__ void __launch_bounds__(256, 2) k_cnm(const float* __restrict__ mem,
                                                float* __restrict__ out3) {
    if (blockIdx.x < CONT_BLKS) content_body(blockIdx.x);
    else                        newmem_body(blockIdx.x - CONT_BLKS, mem, out3);
}

// ---------------- reduce split-K partials, scale by 1/Z ----------------------
__global__ void __launch_bounds__(256) k_reduce(float* __restrict__ out1) {
    int idx = blockIdx.x * 256 + threadIdx.x;
    int b = idx >> 8;
    float s = 0.f;
    #pragma unroll
    for (int z = 0; z < SPLITS; z++) s += g_partial[(size_t)z * NB * DD + idx];
    out1[idx] = s * g_cZinv[b];
}

// ---------------- launch ----------------------------------------------------
extern "C" void kernel_launch(void* const* d_in, const int* in_sizes, int n_in,
                              void* d_out, int out_size) {
    const float* memory  = (const float*)d_in[0];
    const float* query   = (const float*)d_in[1];
    const float* value   = (const float*)d_in[2];
    const float* prev    = (const float*)d_in[3];
    const float* shiftw  = (const float*)d_in[4];

    float* out  = (float*)d_out;
    float* out1 = out;                     // read_content [512,256]
    float* out2 = out + NB * DD;           // read_topk    [512,256]
    float* out3 = out + 2 * NB * DD;       // new_mem      [65536,256]

    cudaFuncSetAttribute(k_sim, cudaFuncAttributeMaxDynamicSharedMemorySize, SIM_DSM);
    cudaFuncSetAttribute(k_cnm, cudaFuncAttributeMaxDynamicSharedMemorySize, CNM_DSM);

    k_pre    <<<NB * WCH + (NS + 2*NB) / 8, 256>>>(memory, query, value, prev, shiftw);
    k_sim    <<<dim3(NS / 128, NB / 128), 256, SIM_DSM>>>();
    k_combine<<<NB, 256>>>(memory, out2);
    k_cnm    <<<CONT_BLKS + 2 * (NS / 128), 256, CNM_DSM>>>(memory, out3);
    k_reduce <<<(NB * DD) / 256, 256>>>(out1);
}

// round 12
// speedup vs baseline: 5.4498x; 1.0650x over previous
#include <cuda_runtime.h>
#include <cuda_bf16.h>
#include <math.h>
#include <stdint.h>

#define NB 512
#define NS 65536
#define DD 256
#define SPLITS 32
#define KCHUNK (NS / SPLITS)   // 2048
#define NBLK 512
#define WCH 8          // sharp chunks per row

// ---------------- scratch (device globals; no allocations allowed) ----------
__device__ __nv_bfloat16 g_simb[(size_t)NB * NS];   // 64 MB : E = exp(sim), bf16
__device__ __nv_bfloat16 g_wwb [(size_t)NB * NS];   // 64 MB : sharp (pre-normalize), bf16
__device__ __nv_bfloat16 g_memb[(size_t)NS * DD];   // 32 MB : bf16 memory
__device__ __nv_bfloat16 g_qnb [NB * DD];
__device__ __nv_bfloat16 g_valb[NB * DD];
__device__ float g_qn [NB * DD];
__device__ float g_minv[NS];
__device__ float g_pmax[(size_t)NB * NBLK];
__device__ float g_psum[(size_t)NB * NBLK];
__device__ int   g_argmax[NB];
__device__ float g_cZinv[NB];
__device__ float g_ws1[NB * WCH];
__device__ float g_ws2[NB * WCH];
__device__ float g_wsinv[NB];
__device__ float g_wZinv[NB];
__device__ float g_partial[(size_t)SPLITS * NB * DD];  // 16 MB

// ======================= helpers ============================================
__device__ __forceinline__ uint32_t smem_u32(const void* p) {
    uint32_t a;
    asm("{ .reg .u64 t; cvta.to.shared.u64 t, %1; cvt.u32.u64 %0, t; }" : "=r"(a) : "l"(p));
    return a;
}
__device__ __forceinline__ uint32_t pack_bf16x2(float lo, float hi) {
    uint32_t r;
    asm("cvt.rn.bf16x2.f32 %0, %1, %2;" : "=r"(r) : "f"(hi), "f"(lo));
    return r;
}
__device__ __forceinline__ void unpack2(uint32_t u, float& a, float& b) {
    __nv_bfloat162 h = *reinterpret_cast<__nv_bfloat162*>(&u);
    a = __bfloat162float(h.x); b = __bfloat162float(h.y);
}
__device__ __forceinline__ void ldsm4(uint32_t* r, uint32_t addr) {
    asm volatile("ldmatrix.sync.aligned.m8n8.x4.shared.b16 {%0,%1,%2,%3}, [%4];"
        : "=r"(r[0]), "=r"(r[1]), "=r"(r[2]), "=r"(r[3]) : "r"(addr));
}
__device__ __forceinline__ void ldsm4t(uint32_t* r, uint32_t addr) {
    asm volatile("ldmatrix.sync.aligned.m8n8.x4.trans.shared.b16 {%0,%1,%2,%3}, [%4];"
        : "=r"(r[0]), "=r"(r[1]), "=r"(r[2]), "=r"(r[3]) : "r"(addr));
}
__device__ __forceinline__ void mma_bf16(float* c, const uint32_t* a, uint32_t b0, uint32_t b1) {
    asm volatile("mma.sync.aligned.m16n8k16.row.col.f32.bf16.bf16.f32 "
        "{%0,%1,%2,%3}, {%4,%5,%6,%7}, {%8,%9}, {%0,%1,%2,%3};"
        : "+f"(c[0]), "+f"(c[1]), "+f"(c[2]), "+f"(c[3])
        : "r"(a[0]), "r"(a[1]), "r"(a[2]), "r"(a[3]), "r"(b0), "r"(b1));
}
__device__ __forceinline__ void cp16(uint32_t d, const void* s) {
    asm volatile("cp.async.cg.shared.global [%0], [%1], 16;" :: "r"(d), "l"(s) : "memory");
}
#define CP_COMMIT() asm volatile("cp.async.commit_group;" ::: "memory")
#define CP_WAIT2()  asm volatile("cp.async.wait_group 2;" ::: "memory")

extern __shared__ __align__(16) char dsm[];

// ===== merged pre-pass: sharp (blocks 0..4095) + norms/bf16-convert =========
__global__ void __launch_bounds__(256) k_pre(const float* __restrict__ mem,
                                             const float* __restrict__ q,
                                             const float* __restrict__ val,
                                             const float* __restrict__ prev,
                                             const float* __restrict__ sw) {
    __shared__ float r1[256], r2[256];
    int bx = blockIdx.x, t = threadIdx.x;
    if (bx < NB * WCH) {
        int b = bx >> 3, ch = bx & 7, lane = t & 31;
        const float* row = prev + (size_t)b * NS;
        __nv_bfloat16* wr = g_wwb + (size_t)b * NS;
        float w0 = sw[0], w1 = sw[1], w2 = sw[2];
        int base = ch * (NS / WCH);
        float s1 = 0.f, s2 = 0.f;
        #pragma unroll
        for (int it = 0; it < NS / WCH / 1024; it++) {
            int i4 = base + (it * 256 + t) * 4;
            float4 v = *reinterpret_cast<const float4*>(row + i4);
            float pl = __shfl_up_sync(0xffffffffu, v.w, 1);
            float nx = __shfl_down_sync(0xffffffffu, v.x, 1);
            if (lane == 0)  pl = (i4 > 0) ? row[i4 - 1] : 0.f;
            if (lane == 31) nx = (i4 + 4 < NS) ? row[i4 + 4] : 0.f;
            float a0 = pl*w0 + v.x*w1 + v.y*w2;
            float a1 = v.x*w0 + v.y*w1 + v.z*w2;
            float a2 = v.y*w0 + v.z*w1 + v.w*w2;
            float a3 = v.z*w0 + v.w*w1 + nx*w2;
            float p0 = a0*a0*rsqrtf(fmaxf(a0, 1e-35f));
            float p1 = a1*a1*rsqrtf(fmaxf(a1, 1e-35f));
            float p2 = a2*a2*rsqrtf(fmaxf(a2, 1e-35f));
            float p3 = a3*a3*rsqrtf(fmaxf(a3, 1e-35f));
            s1 += p0 + p1 + p2 + p3;
            s2 += p0*p0 + p1*p1 + p2*p2 + p3*p3;
            *reinterpret_cast<uint2*>(wr + i4) =
                make_uint2(pack_bf16x2(p0, p1), pack_bf16x2(p2, p3));
        }
        r1[t] = s1; r2[t] = s2; __syncthreads();
        for (int o = 128; o; o >>= 1) {
            if (t < o) { r1[t] += r1[t+o]; r2[t] += r2[t+o]; }
            __syncthreads();
        }
        if (t == 0) { g_ws1[b * WCH + ch] = r1[0]; g_ws2[b * WCH + ch] = r2[0]; }
        return;
    }
    int lane = t & 31;
    int row = (bx - NB * WCH) * 8 + (t >> 5);
    if (row < NS) {
        const float4* p = reinterpret_cast<const float4*>(mem + (size_t)row * DD);
        float4 v0 = p[lane];
        float4 v1 = p[lane + 32];
        float s = v0.x*v0.x + v0.y*v0.y + v0.z*v0.z + v0.w*v0.w
                + v1.x*v1.x + v1.y*v1.y + v1.z*v1.z + v1.w*v1.w;
        #pragma unroll
        for (int o = 16; o; o >>= 1) s += __shfl_xor_sync(0xffffffffu, s, o);
        if (lane == 0) g_minv[row] = 1.0f / fmaxf(sqrtf(s), 1e-12f);
        __nv_bfloat16* d = g_memb + (size_t)row * DD;
        *reinterpret_cast<uint2*>(d + lane*4) =
            make_uint2(pack_bf16x2(v0.x, v0.y), pack_bf16x2(v0.z, v0.w));
        *reinterpret_cast<uint2*>(d + 128 + lane*4) =
            make_uint2(pack_bf16x2(v1.x, v1.y), pack_bf16x2(v1.z, v1.w));
    } else if (row < NS + NB) {
        int qr = row - NS;
        const float4* p = reinterpret_cast<const float4*>(q + (size_t)qr * DD);
        float4 v0 = p[lane];
        float4 v1 = p[lane + 32];
        float s = v0.x*v0.x + v0.y*v0.y + v0.z*v0.z + v0.w*v0.w
                + v1.x*v1.x + v1.y*v1.y + v1.z*v1.z + v1.w*v1.w;
        #pragma unroll
        for (int o = 16; o; o >>= 1) s += __shfl_xor_sync(0xffffffffu, s, o);
        float inv = 1.0f / fmaxf(sqrtf(s), 1e-12f);
        v0.x *= inv; v0.y *= inv; v0.z *= inv; v0.w *= inv;
        v1.x *= inv; v1.y *= inv; v1.z *= inv; v1.w *= inv;
        float4* o4 = reinterpret_cast<float4*>(g_qn + (size_t)qr * DD);
        o4[lane] = v0; o4[lane + 32] = v1;
        __nv_bfloat16* d = g_qnb + (size_t)qr * DD;
        *reinterpret_cast<uint2*>(d + lane*4) =
            make_uint2(pack_bf16x2(v0.x, v0.y), pack_bf16x2(v0.z, v0.w));
        *reinterpret_cast<uint2*>(d + 128 + lane*4) =
            make_uint2(pack_bf16x2(v1.x, v1.y), pack_bf16x2(v1.z, v1.w));
    } else {
        int vr = row - NS - NB;
        const float4* p = reinterpret_cast<const float4*>(val + (size_t)vr * DD);
        float4 v0 = p[lane];
        float4 v1 = p[lane + 32];
        __nv_bfloat16* d = g_valb + (size_t)vr * DD;
        *reinterpret_cast<uint2*>(d + lane*4) =
            make_uint2(pack_bf16x2(v0.x, v0.y), pack_bf16x2(v0.z, v0.w));
        *reinterpret_cast<uint2*>(d + 128 + lane*4) =
            make_uint2(pack_bf16x2(v1.x, v1.y), pack_bf16x2(v1.z, v1.w));
    }
}

// ============ sim GEMM (HMMA bf16, cp.async 4-stage) + exp epilogue =========
// dsm: A stages s*10240 (4), B stages 40960+s*10240 (4), minv @ 81920
#define SIM_DSM 82432
__global__ void __launch_bounds__(256, 2) k_sim() {
    float* s_minv = reinterpret_cast<float*>(dsm + 81920);
    int tid = threadIdx.x, lane = tid & 31, w = tid >> 5;
    int wm = w >> 2, wn = w & 3;
    int bn = blockIdx.x * 128, bm = blockIdx.y * 128;
    uint32_t sb = smem_u32(dsm);
    if (tid < 32) reinterpret_cast<float4*>(s_minv)[tid] =
        reinterpret_cast<const float4*>(g_minv + bn)[tid];

    float acc[4][4][4];
    #pragma unroll
    for (int i = 0; i < 4; i++)
        #pragma unroll
        for (int j = 0; j < 4; j++)
            #pragma unroll
            for (int u = 0; u < 4; u++) acc[i][j][u] = 0.f;

    int r = lane & 7, gq = lane >> 3;

    auto issue = [&](int it) {
        if (it < 8) {
            int k0 = it * 32;
            uint32_t sa = sb + (it & 3) * 10240;
            uint32_t sbb = sb + 40960 + (it & 3) * 10240;
            #pragma unroll
            for (int i = 0; i < 2; i++) {
                int idx = tid + i * 256;
                int row = idx >> 2, q8 = (idx & 3) * 8;
                cp16(sa  + (uint32_t)(row*80 + q8*2), g_qnb  + (size_t)(bm + row) * DD + k0 + q8);
                cp16(sbb + (uint32_t)(row*80 + q8*2), g_memb + (size_t)(bn + row) * DD + k0 + q8);
            }
        }
        CP_COMMIT();
    };
    issue(0); issue(1); issue(2);

    for (int ch = 0; ch < 8; ch++) {
        CP_WAIT2();
        __syncthreads();
        issue(ch + 3);
        uint32_t aA = sb + (ch & 3) * 10240;
        uint32_t aB = sb + 40960 + (ch & 3) * 10240;
        #pragma unroll
        for (int ks = 0; ks < 2; ks++) {
            int kk = ks * 16;
            uint32_t ah[4][4], bh[2][4];
            #pragma unroll
            for (int mt = 0; mt < 4; mt++) {
                int arow = wm*64 + mt*16 + r + 8*(gq & 1);
                int acol = kk + 8*(gq >> 1);
                ldsm4(ah[mt], aA + (uint32_t)(arow*80 + acol*2));
            }
            #pragma unroll
            for (int np = 0; np < 2; np++) {
                int brow = wn*32 + np*16 + r + 8*(gq >> 1);
                int bcol = kk + 8*(gq & 1);
                ldsm4(bh[np], aB + (uint32_t)(brow*80 + bcol*2));
            }
            #pragma unroll
            for (int mt = 0; mt < 4; mt++)
                #pragma unroll
                for (int nt = 0; nt < 4; nt++) {
                    int np = nt >> 1, hb = (nt & 1) * 2;
                    mma_bf16(acc[mt][nt], ah[mt], bh[np][hb], bh[np][hb+1]);
                }
        }
    }
    __syncthreads();

    float* s_max = reinterpret_cast<float*>(dsm);
    float* s_sum = reinterpret_cast<float*>(dsm + 40960);
    int g = lane >> 2, t = lane & 3;
    #pragma unroll
    for (int mt = 0; mt < 4; mt++)
        #pragma unroll
        for (int rs = 0; rs < 2; rs++) {
            int mloc = wm*64 + mt*16 + g + rs*8;
            float lm = -1e30f; float ls = 0.f;
            #pragma unroll
            for (int nt = 0; nt < 4; nt++) {
                int ncl = wn*32 + nt*8 + t*2;
                float s0 = acc[mt][nt][rs*2]   * s_minv[ncl];
                float s1 = acc[mt][nt][rs*2+1] * s_minv[ncl+1];
                lm = fmaxf(lm, fmaxf(s0, s1));
                float e0 = __expf(s0), e1 = __expf(s1);
                ls += e0 + e1;
                *reinterpret_cast<uint32_t*>(g_simb + (size_t)(bm + mloc) * NS + bn + ncl) =
                    pack_bf16x2(e0, e1);
            }
            #pragma unroll
            for (int o = 1; o < 4; o <<= 1) {
                lm = fmaxf(lm, __shfl_xor_sync(0xffffffffu, lm, o));
                ls += __shfl_xor_sync(0xffffffffu, ls, o);
            }
            if (t == 0) {
                s_max[wn*128 + mloc] = lm;
                s_sum[wn*128 + mloc] = ls;
            }
        }
    __syncthreads();
    if (tid < 128) {
        float m = s_max[tid]; float s = s_sum[tid];
        #pragma unroll
        for (int wq = 1; wq < 4; wq++) {
            m = fmaxf(m, s_max[wq*128 + tid]);
            s += s_sum[wq*128 + tid];
        }
        size_t pidx = (size_t)(bm + tid) * NBLK + blockIdx.x;
        g_pmax[pidx] = m; g_psum[pidx] = s;
    }
}

// ------- combine: Z + two-stage argmax (block -> slot via E) + wcomb + topk --
__global__ void __launch_bounds__(256) k_combine(const float* __restrict__ mem,
                                                 float* __restrict__ out2) {
    int b = blockIdx.x, t = threadIdx.x, lane = t & 31, w = t >> 5;
    size_t base = (size_t)b * NBLK;
    float p1 = g_pmax[base + t], p2 = g_pmax[base + t + 256];
    float m = fmaxf(p1, p2);
    float s = g_psum[base + t] + g_psum[base + t + 256];
    __shared__ float sm[256]; __shared__ float ss[256];
    __shared__ float s_q[DD];
    __shared__ int s_cnt, s_cand[64];
    __shared__ int s_scnt, s_slot[64];
    __shared__ float s_bv[8]; __shared__ int s_bi[8];
    __shared__ int s_arg;
    if (t == 0) { s_cnt = 0; s_scnt = 0; }
    if (t < 64) reinterpret_cast<float4*>(s_q)[t] =
        reinterpret_cast<const float4*>(g_qn + (size_t)b * DD)[t];
    sm[t] = m; ss[t] = s; __syncthreads();
    for (int o = 128; o; o >>= 1) {
        if (t < o) { ss[t] += ss[t+o]; sm[t] = fmaxf(sm[t], sm[t+o]); }
        __syncthreads();
    }
    float rm = sm[0];
    if (t == 0) {
        g_cZinv[b] = 1.0f / ss[0];
        float s1 = 0.f, s2 = 0.f;
        #pragma unroll
        for (int c = 0; c < WCH; c++) { s1 += g_ws1[b*WCH + c]; s2 += g_ws2[b*WCH + c]; }
        float sinv = 1.0f / (s1 + 1e-8f);
        float z = (float)NS + s1 * sinv + 0.5f * s2 * sinv * sinv;
        g_wsinv[b] = sinv;
        g_wZinv[b] = 1.0f / z;
    }
    float thr = rm - 8e-3f;
    if (p1 >= thr) { int p = atomicAdd(&s_cnt, 1); if (p < 64) s_cand[p] = t; }
    if (p2 >= thr) { int p = atomicAdd(&s_cnt, 1); if (p < 64) s_cand[p] = t + 256; }
    __syncthreads();
    int nc = min(s_cnt, 64);
    float Eth = __expf(rm - 8e-3f) * 0.992f;
    const __nv_bfloat16* Erow = g_simb + (size_t)b * NS;
    for (int i = t; i < nc * 128; i += 256) {
        int n = s_cand[i >> 7] * 128 + (i & 127);
        if (__bfloat162float(Erow[n]) >= Eth) {
            int p = atomicAdd(&s_scnt, 1);
            if (p < 64) s_slot[p] = n;
        }
    }
    __syncthreads();
    int nsl = min(s_scnt, 64);
    float bv = -1e30f; int bi = 0x7fffffff;
    for (int c = w; c < nsl; c += 8) {
        int n = s_slot[c];
        const float* mr = mem + (size_t)n * DD;
        float d = 0.f;
        #pragma unroll
        for (int j = 0; j < 8; j += 4) {
            float4 qv = *reinterpret_cast<const float4*>(s_q + lane*8 + j);
            float4 mv = *reinterpret_cast<const float4*>(mr + lane*8 + j);
            d += qv.x*mv.x + qv.y*mv.y + qv.z*mv.z + qv.w*mv.w;
        }
        #pragma unroll
        for (int o = 16; o; o >>= 1) d += __shfl_xor_sync(0xffffffffu, d, o);
        d *= g_minv[n];
        if (lane == 0) {
            if (d > bv || (d == bv && n < bi)) { bv = d; bi = n; }
        }
    }
    if (lane == 0) { s_bv[w] = bv; s_bi[w] = bi; }
    __syncthreads();
    if (t == 0) {
        float v = s_bv[0]; int ix = s_bi[0];
        #pragma unroll
        for (int k = 1; k < 8; k++)
            if (s_bv[k] > v || (s_bv[k] == v && s_bi[k] < ix)) { v = s_bv[k]; ix = s_bi[k]; }
        g_argmax[b] = ix;
        s_arg = ix;
    }
    __syncthreads();
    out2[(size_t)b * DD + t] = mem[(size_t)s_arg * DD + t];
}

// ======= merged GEMM kernel, 256 threads, 128x128 tiles, 2 CTA/SM ===========
// content blocks 0..255 (cp.async 4-stage): z=bx>>3, bm=((bx>>1)&3)*128, bd=(bx&1)*128
// newmem blocks 256..1279: bm=(bx>>1)*128, bd=(bx&1)*128
#define CNM_DSM 75776
#define CONT_BLKS (SPLITS * 8)   // 256

__device__ __forceinline__ void content_body(int bx) {
    int tid = threadIdx.x, lane = tid & 31, w = tid >> 5;
    int wm = w >> 2, wn = w & 3;
    int z = bx >> 3, bm = ((bx >> 1) & 3) * 128, bd = (bx & 1) * 128;
    uint32_t sb = smem_u32(dsm);
    float acc[4][4][4];
    #pragma unroll
    for (int i = 0; i < 4; i++)
        #pragma unroll
        for (int j = 0; j < 4; j++)
            #pragma unroll
            for (int u = 0; u < 4; u++) acc[i][j][u] = 0.f;
    int r = lane & 7, gq = lane >> 3;
    int kbase = z * KCHUNK;
    const int NIT = KCHUNK / 32;   // 64

    auto issue = [&](int it) {
        if (it < NIT) {
            int k0 = kbase + it * 32;
            uint32_t sa = sb + (it & 3) * 10240;
            uint32_t sbb = sb + 40960 + (it & 3) * 8704;
            #pragma unroll
            for (int i = 0; i < 2; i++) {
                int idx = tid + i * 256;
                int ar = idx >> 2, aq8 = (idx & 3) * 8;
                cp16(sa + (uint32_t)(ar*80 + aq8*2),
                     g_simb + (size_t)(bm + ar) * NS + k0 + aq8);
                int br = idx >> 4, bq8 = (idx & 15) * 8;
                cp16(sbb + (uint32_t)(br*272 + bq8*2),
                     g_memb + (size_t)(k0 + br) * DD + bd + bq8);
            }
        }
        CP_COMMIT();
    };
    issue(0); issue(1); issue(2);

    for (int it = 0; it < NIT; it++) {
        CP_WAIT2();
        __syncthreads();
        issue(it + 3);
        uint32_t aA = sb + (it & 3) * 10240;
        uint32_t aB = sb + 40960 + (it & 3) * 8704;
        #pragma unroll
        for (int ks = 0; ks < 2; ks++) {
            int kk = ks * 16;
            uint32_t af[4][4], bf[2][4];
            #pragma unroll
            for (int mt = 0; mt < 4; mt++) {
                int arow = wm*64 + mt*16 + r + 8*(gq & 1);
                int acol = kk + 8*(gq >> 1);
                ldsm4(af[mt], aA + (uint32_t)(arow*80 + acol*2));
            }
            #pragma unroll
            for (int np = 0; np < 2; np++) {
                int brow = kk + r + 8*(gq & 1);
                int bcol = wn*32 + np*16 + 8*(gq >> 1);
                ldsm4t(bf[np], aB + (uint32_t)(brow*272 + bcol*2));
            }
            #pragma unroll
            for (int mt = 0; mt < 4; mt++)
                #pragma unroll
                for (int nt = 0; nt < 4; nt++) {
                    int np = nt >> 1, hb = (nt & 1) * 2;
                    mma_bf16(acc[mt][nt], af[mt], bf[np][hb], bf[np][hb+1]);
                }
        }
    }
    int g = lane >> 2, tq = lane & 3;
    #pragma unroll
    for (int mt = 0; mt < 4; mt++)
        #pragma unroll
        for (int rs = 0; rs < 2; rs++) {
            int mloc = wm*64 + mt*16 + g + rs*8;
            float* dst = g_partial + ((size_t)z * NB + bm + mloc) * DD + bd;
            #pragma unroll
            for (int nt = 0; nt < 4; nt++) {
                int off = wn*32 + nt*8 + tq*2;
                *reinterpret_cast<float2*>(dst + off) =
                    make_float2(acc[mt][nt][rs*2], acc[mt][nt][rs*2+1]);
            }
        }
}

__device__ __forceinline__ void newmem_body(int bx, const float* __restrict__ mem,
                                            float* __restrict__ out3) {
    char* pA[2] = { dsm, dsm + 8704 };            // 32 x 128 bf16 (w), stride 272
    char* pB[2] = { dsm + 17408, dsm + 26112 };   // 32 x 128 bf16 (valb), stride 272
    float* s_red   = reinterpret_cast<float*>(dsm + 34816);   // [16][128]
    float* s_sinv  = reinterpret_cast<float*>(dsm + 43008);
    float* s_zinv  = reinterpret_cast<float*>(dsm + 45056);
    float* s_erase = reinterpret_cast<float*>(dsm + 47104);
    int tid = threadIdx.x, lane = tid & 31, w = tid >> 5;
    int wm = w >> 2, wn = w & 3;
    int bm = (bx >> 1) * 128, bd = (bx & 1) * 128;
    if (tid < 128) {
        reinterpret_cast<float4*>(s_sinv)[tid] = reinterpret_cast<const float4*>(g_wsinv)[tid];
        reinterpret_cast<float4*>(s_zinv)[tid] = reinterpret_cast<const float4*>(g_wZinv)[tid];
    }
    float acc[4][4][4];
    #pragma unroll
    for (int i = 0; i < 4; i++)
        #pragma unroll
        for (int j = 0; j < 4; j++)
            #pragma unroll
            for (int u = 0; u < 4; u++) acc[i][j][u] = 0.f;
    float pr[8];
    #pragma unroll
    for (int j = 0; j < 8; j++) pr[j] = 1.f;
    int r = lane & 7, gq = lane >> 3;
    int ac8 = (tid & 15) * 8;
    __syncthreads();

    auto storeA = [&](int st, int rowoff, int krow, uint4 u) {
        float sv = s_sinv[krow], zv = s_zinv[krow];
        float f[8];
        unpack2(u.x, f[0], f[1]); unpack2(u.y, f[2], f[3]);
        unpack2(u.z, f[4], f[5]); unpack2(u.w, f[6], f[7]);
        uint32_t stv[4];
        #pragma unroll
        for (int j = 0; j < 8; j += 2) {
            float x0 = f[j] * sv, x1 = f[j+1] * sv;
            float w0 = (1.f + x0 + 0.5f*x0*x0) * zv;
            float w1 = (1.f + x1 + 0.5f*x1*x1) * zv;
            pr[j]   *= (1.f - 0.5f*w0);
            pr[j+1] *= (1.f - 0.5f*w1);
            stv[j >> 1] = pack_bf16x2(w0, w1);
        }
        *reinterpret_cast<uint4*>(pA[st] + rowoff*272 + ac8*2) =
            make_uint4(stv[0], stv[1], stv[2], stv[3]);
    };

    {
        #pragma unroll
        for (int i = 0; i < 2; i++) {
            int idx = tid + i * 256;
            int ar = idx >> 4;
            uint4 u = *reinterpret_cast<const uint4*>(g_wwb + (size_t)ar * NS + bm + ac8);
            storeA(0, ar, ar, u);
            *reinterpret_cast<uint4*>(pB[0] + ar*272 + ac8*2) =
                *reinterpret_cast<const uint4*>(g_valb + (size_t)ar * DD + bd + ac8);
        }
    }
    __syncthreads();

    uint4 pfa[2], pfb[2];
    for (int ch = 0; ch < 16; ch++) {
        int st = ch & 1;
        if (ch < 15) {
            int k0 = (ch + 1) * 32;
            #pragma unroll
            for (int i = 0; i < 2; i++) {
                int idx = tid + i * 256;
                int ar = idx >> 4;
                pfa[i] = *reinterpret_cast<const uint4*>(g_wwb + (size_t)(k0 + ar) * NS + bm + ac8);
                pfb[i] = *reinterpret_cast<const uint4*>(g_valb + (size_t)(k0 + ar) * DD + bd + ac8);
            }
        }
        uint32_t aA = smem_u32(pA[st]), aB = smem_u32(pB[st]);
        #pragma unroll
        for (int ks = 0; ks < 2; ks++) {
            int kk = ks * 16;
            uint32_t af[4][4], bf[2][4];
            #pragma unroll
            for (int mt = 0; mt < 4; mt++) {
                int arow = kk + r + 8*(gq >> 1);
                int acol = wm*64 + mt*16 + 8*(gq & 1);
                ldsm4t(af[mt], aA + (uint32_t)(arow*272 + acol*2));
            }
            #pragma unroll
            for (int np = 0; np < 2; np++) {
                int brow = kk + r + 8*(gq & 1);
                int bcol = wn*32 + np*16 + 8*(gq >> 1);
                ldsm4t(bf[np], aB + (uint32_t)(brow*272 + bcol*2));
            }
            #pragma unroll
            for (int mt = 0; mt < 4; mt++)
                #pragma unroll
                for (int nt = 0; nt < 4; nt++) {
                    int np = nt >> 1, hb = (nt & 1) * 2;
                    mma_bf16(acc[mt][nt], af[mt], bf[np][hb], bf[np][hb+1]);
                }
        }
        if (ch < 15) {
            int ns = st ^ 1;
            int k0 = (ch + 1) * 32;
            #pragma unroll
            for (int i = 0; i < 2; i++) {
                int idx = tid + i * 256;
                int ar = idx >> 4;
                storeA(ns, ar, k0 + ar, pfa[i]);
                *reinterpret_cast<uint4*>(pB[ns] + ar*272 + ac8*2) = pfb[i];
            }
            __syncthreads();
        }
    }
    __syncthreads();
    #pragma unroll
    for (int j = 0; j < 8; j++) s_red[(tid >> 4)*128 + ac8 + j] = pr[j];
    __syncthreads();
    if (tid < 128) {
        float p = 1.f;
        #pragma unroll
        for (int k = 0; k < 16; k++) p *= s_red[k*128 + tid];
        s_erase[tid] = p;
    }
    __syncthreads();
    int g = lane >> 2, tq = lane & 3;
    #pragma unroll
    for (int mt = 0; mt < 4; mt++)
        #pragma unroll
        for (int rs = 0; rs < 2; rs++) {
            int mloc = wm*64 + mt*16 + g + rs*8;
            int slot = bm + mloc;
            float er = s_erase[mloc];
            const float* mrow = mem + (size_t)slot * DD + bd;
            float* dst = out3 + (size_t)slot * DD + bd;
            #pragma unroll
            for (int nt = 0; nt < 4; nt++) {
                int off = wn*32 + nt*8 + tq*2;
                float2 mv = *reinterpret_cast<const float2*>(mrow + off);
                *reinterpret_cast<float2*>(dst + off) =
                    make_float2(mv.x*er + acc[mt][nt][rs*2], mv.y*er + acc[mt][nt][rs*2+1]);
            }
        }
}

__global__ void __launch_bounds__(256, 2) k_cnm(const float* __restrict__ mem,
                                                float* __restrict__ out3) {
    if (blockIdx.x < CONT_BLKS) content_body(blockIdx.x);
    else                        newmem_body(blockIdx.x - CONT_BLKS, mem, out3);
}

// ---------------- reduce split-K partials, scale by 1/Z ----------------------
__global__ void __launch_bounds__(256) k_reduce(float* __restrict__ out1) {
    int idx = blockIdx.x * 256 + threadIdx.x;
    int b = idx >> 8;
    float s = 0.f;
    #pragma unroll
    for (int z = 0; z < SPLITS; z++) s += g_partial[(size_t)z * NB * DD + idx];
    out1[idx] = s * g_cZinv[b];
}

// ---------------- launch ----------------------------------------------------
extern "C" void kernel_launch(void* const* d_in, const int* in_sizes, int n_in,
                              void* d_out, int out_size) {
    const float* memory  = (const float*)d_in[0];
    const float* query   = (const float*)d_in[1];
    const float* value   = (const float*)d_in[2];
    const float* prev    = (const float*)d_in[3];
    const float* shiftw  = (const float*)d_in[4];

    float* out  = (float*)d_out;
    float* out1 = out;                     // read_content [512,256]
    float* out2 = out + NB * DD;           // read_topk    [512,256]
    float* out3 = out + 2 * NB * DD;       // new_mem      [65536,256]

    cudaFuncSetAttribute(k_sim, cudaFuncAttributeMaxDynamicSharedMemorySize, SIM_DSM);
    cudaFuncSetAttribute(k_cnm, cudaFuncAttributeMaxDynamicSharedMemorySize, CNM_DSM);

    k_pre    <<<NB * WCH + (NS + 2*NB) / 8, 256>>>(memory, query, value, prev, shiftw);
    k_sim    <<<dim3(NS / 128, NB / 128), 256, SIM_DSM>>>();
    k_combine<<<NB, 256>>>(memory, out2);
    k_cnm    <<<CONT_BLKS + 2 * (NS / 128), 256, CNM_DSM>>>(memory, out3);
    k_reduce <<<(NB * DD) / 256, 256>>>(out1);
}